// round 6
// baseline (speedup 1.0000x reference)
#include <cuda_runtime.h>
#include <cuda_fp16.h>
#include <math.h>
#include <stdint.h>

// ---------------- problem constants ----------------
#define S 4096
#define HID 128
#define NHEADS 4
#define HD 32
#define NCOE 50
#define NSCALES 4
#define NKC 4              // split-K chunks for attention
#define CHUNK (S / NKC)    // 1024 keys per chunk
#define QT 128             // queries per block (8 warps x 16)
#define KT 64              // key tile

// KV tile image geometry (halves). Padded rows for conflict-free LDS.
#define KROW 72                      // per-key: 32 hi + 32 lo + 8 pad
#define KIMG (KT * KROW)             // 4608 halves
#define VROW 136                     // per-dim: 64 hi + 64 lo + 8 pad
#define VIMG (HD * VROW)             // 4352 halves
#define TILE_H (KIMG + VIMG)         // 8960 halves = 17920 B
#define TILE_U4 (TILE_H / 8)         // 1120 uint4

// ---------------- scratch (__device__ globals; no allocs allowed) ----------------
__device__ float  g_eig [S * HID];
__device__ float  g_qkv [S * 3 * HID];
__device__ float  g_att [S * HID];
__device__ float  g_h1  [S * HID];
__device__ float  g_eigf[S * HID];
__device__ __align__(16) __half g_kv[NHEADS * (S / KT) * TILE_H];  // pre-swizzled K/V tiles
__device__ float  g_pm  [NHEADS * NKC * S];        // partial max
__device__ float  g_pl  [NHEADS * NKC * S];        // partial sum
__device__ float  g_po  [NHEADS * NKC * S * HD];   // partial (unnormalized) out
__device__ double g_xsum[HID];
__device__ float  g_coef[128];   // [0:50) scaling, [50:100) wavelet, [100:104) scales

// ---------------- mma helpers ----------------
__device__ __forceinline__ void mma16816(float& c0, float& c1, float& c2, float& c3,
                                         uint32_t a0, uint32_t a1, uint32_t a2, uint32_t a3,
                                         uint32_t b0, uint32_t b1) {
    asm volatile("mma.sync.aligned.m16n8k16.row.col.f32.f16.f16.f32 "
                 "{%0,%1,%2,%3}, {%4,%5,%6,%7}, {%8,%9}, {%0,%1,%2,%3};\n"
                 : "+f"(c0), "+f"(c1), "+f"(c2), "+f"(c3)
                 : "r"(a0), "r"(a1), "r"(a2), "r"(a3), "r"(b0), "r"(b1));
}

__device__ __forceinline__ uint32_t packh2(__half a, __half b) {
    __half2 t = __halves2half2(a, b);     // a -> low half
    return *reinterpret_cast<uint32_t*>(&t);
}

// split x into hi (fp16) and lo (fp16 of remainder)
__device__ __forceinline__ void hsplit(float x, __half& h, __half& l) {
    h = __float2half_rn(x);
    l = __float2half_rn(x - __half2float(h));
}

__device__ __forceinline__ void packsplit2h(float x, float y, uint32_t& hi, uint32_t& lo) {
    __half xh, xl, yh, yl;
    hsplit(x, xh, xl);
    hsplit(y, yh, yl);
    hi = packh2(xh, yh);
    lo = packh2(xl, yl);
}

__device__ __forceinline__ uint32_t pack2f(float x, float y) {
    __half2 t = __floats2half2_rn(x, y);  // x -> low
    return *reinterpret_cast<uint32_t*>(&t);
}

// ============================================================================
// K1: sine encoding + GEMM  ->  g_eig = eeig[S,129] @ W[129,128] + b
// 8 rows per block, 128 threads
// ============================================================================
__global__ void __launch_bounds__(128) k_sine_enc(const float* __restrict__ eve,
                                                  const float* __restrict__ W,
                                                  const float* __restrict__ b) {
    __shared__ float ee[8][132];   // 129 used
    const int m0  = blockIdx.x * 8;
    const int tid = threadIdx.x;
    const float kLog = -9.210340371976184f / 128.0f;   // -ln(1e4)/128

    for (int idx = tid; idx < 8 * 129; idx += 128) {
        int r = idx / 129, j = idx - r * 129;
        float e = eve[m0 + r];
        float val;
        if (j == 0) {
            val = e;
        } else if (j <= 64) {
            int i = j - 1;
            float div = __expf((2.0f * i) * kLog);
            val = sinf(e * 100.0f * div);
        } else {
            int i = j - 65;
            float div = __expf((2.0f * i) * kLog);
            val = cosf(e * 100.0f * div);
        }
        ee[r][j] = val;
    }
    __syncthreads();

    float acc[8];
#pragma unroll
    for (int r = 0; r < 8; r++) acc[r] = 0.0f;

    for (int k = 0; k < 129; k++) {
        float wv = W[k * HID + tid];
#pragma unroll
        for (int r = 0; r < 8; r++) acc[r] = fmaf(ee[r][k], wv, acc[r]);
    }
    float bb = b[tid];
#pragma unroll
    for (int r = 0; r < 8; r++) g_eig[(m0 + r) * HID + tid] = acc[r] + bb;
}

// ============================================================================
// GEMM  C[M,N] = act( LN?(A)[M,128] @ W[128,N] + bias ) (+ R)
// 8 rows per block, 128 threads. NC = N/128 columns per thread.
// ============================================================================
template <int NC, int ACT, int RESID, int LNORM>
__global__ void __launch_bounds__(128) k_gemm(const float* __restrict__ A,
                                              const float* __restrict__ W,
                                              const float* __restrict__ bias,
                                              const float* __restrict__ R,
                                              float* __restrict__ C,
                                              const float* __restrict__ lng,
                                              const float* __restrict__ lnb) {
    constexpr int N = NC * 128;
    __shared__ float As[8][HID];
    __shared__ float rowMean[8], rowRstd[8];
    const int m0  = blockIdx.x * 8;
    const int tid = threadIdx.x;

    for (int idx = tid; idx < 8 * HID; idx += 128)
        As[idx >> 7][idx & 127] = A[m0 * HID + idx];
    __syncthreads();

    if (LNORM) {
        // 16 threads per row, 8 rows
        const int r = tid >> 4, l16 = tid & 15;
        float s = 0.0f, s2 = 0.0f;
        for (int j = l16; j < HID; j += 16) {
            float v = As[r][j];
            s += v; s2 += v * v;
        }
#pragma unroll
        for (int o = 8; o; o >>= 1) {
            s  += __shfl_xor_sync(0xffffffffu, s,  o);
            s2 += __shfl_xor_sync(0xffffffffu, s2, o);
        }
        if (l16 == 0) {
            float mean = s * (1.0f / HID);
            float var  = s2 * (1.0f / HID) - mean * mean;
            rowMean[r] = mean;
            rowRstd[r] = rsqrtf(var + 1e-5f);
        }
        __syncthreads();
        float gg = lng[tid], bb2 = lnb[tid];
#pragma unroll
        for (int r2 = 0; r2 < 8; r2++)
            As[r2][tid] = (As[r2][tid] - rowMean[r2]) * rowRstd[r2] * gg + bb2;
        __syncthreads();
    }

    float acc[NC][8];
#pragma unroll
    for (int c = 0; c < NC; c++)
#pragma unroll
        for (int r = 0; r < 8; r++) acc[c][r] = 0.0f;

    for (int k = 0; k < HID; k += 4) {
        float wv[4][NC];
#pragma unroll
        for (int i = 0; i < 4; i++)
#pragma unroll
            for (int c = 0; c < NC; c++)
                wv[i][c] = W[(k + i) * N + c * 128 + tid];
#pragma unroll
        for (int r = 0; r < 8; r++) {
            float4 a4 = *reinterpret_cast<const float4*>(&As[r][k]);
#pragma unroll
            for (int c = 0; c < NC; c++) {
                acc[c][r] = fmaf(a4.x, wv[0][c], acc[c][r]);
                acc[c][r] = fmaf(a4.y, wv[1][c], acc[c][r]);
                acc[c][r] = fmaf(a4.z, wv[2][c], acc[c][r]);
                acc[c][r] = fmaf(a4.w, wv[3][c], acc[c][r]);
            }
        }
    }

#pragma unroll
    for (int c = 0; c < NC; c++) {
        int col = c * 128 + tid;
        float bb = bias[col];
#pragma unroll
        for (int r = 0; r < 8; r++) {
            float v = acc[c][r] + bb;
            if (ACT == 1) v = 0.5f * v * (1.0f + erff(v * 0.70710678118654752f));
            if (RESID)    v += R[(m0 + r) * HID + tid];
            C[(m0 + r) * N + col] = v;
        }
    }
}

// ============================================================================
// K-prep: build per-(head, 64-key tile) smem-image of K (hi/lo) and V^T (hi/lo)
// in fp16 with the exact padded layout the attention kernel uses.
// grid = (S/KT, NHEADS), 256 threads.
// ============================================================================
__global__ void __launch_bounds__(256) k_prep(const float* __restrict__ qkv) {
    __shared__ __align__(16) __half img[TILE_H];
    const int tid = threadIdx.x;
    const int kb  = blockIdx.x * KT;
    const int h   = blockIdx.y;

    for (int i = tid; i < KT * HD; i += 256) {
        int key = i >> 5, d = i & 31;
        const float* base = qkv + (size_t)(kb + key) * 384 + h * HD + d;
        float kx = base[128];
        float vx = base[256];
        __half kh, kl, vh, vl;
        hsplit(kx, kh, kl);
        hsplit(vx, vh, vl);
        img[key * KROW + d]        = kh;
        img[key * KROW + 32 + d]   = kl;
        img[KIMG + d * VROW + key]      = vh;
        img[KIMG + d * VROW + 64 + key] = vl;
    }
    __syncthreads();

    uint4* dst = reinterpret_cast<uint4*>(g_kv + (size_t)(h * (S / KT) + blockIdx.x) * TILE_H);
    const uint4* src = reinterpret_cast<const uint4*>(img);
    for (int i = tid; i < TILE_U4; i += 256) dst[i] = src[i];
}

// ============================================================================
// K4a: MMA flash attention partial (fp16; QK 3-term, PV 2-term).
// grid = (S/QT, NHEADS, NKC), block = 256 (8 warps x 16 queries).
// ============================================================================
__global__ void __launch_bounds__(256) k_attn_mma(const float* __restrict__ qkv,
                                                  const int* __restrict__ snp) {
    __shared__ __align__(16) __half tile[TILE_H];

    const int tid  = threadIdx.x;
    const int warp = tid >> 5;
    const int lane = tid & 31;
    const int g    = lane >> 2;    // group (row within fragment)
    const int t4   = lane & 3;     // thread-in-group
    const int h    = blockIdx.y;
    const int kc   = blockIdx.z;
    const int sn   = *snp;
    const float scale = 0.17677669529663687f;   // 1/sqrt(32)

    const int qbase = blockIdx.x * QT + warp * 16;
    const int r0 = qbase + g;        // query rows owned by this thread
    const int r1 = r0 + 8;

    // ---- load Q fragments (2 k-steps), split hi/lo fp16 ----
    uint32_t Qhi[2][4], Qlo[2][4];
#pragma unroll
    for (int ks = 0; ks < 2; ks++) {
#pragma unroll
        for (int hh = 0; hh < 2; hh++) {     // k-half (+0 / +8)
#pragma unroll
            for (int rr = 0; rr < 2; rr++) { // row g / g+8
                int row = rr ? r1 : r0;
                int d0  = ks * 16 + hh * 8 + 2 * t4;
                float x0 = qkv[row * 384 + h * HD + d0]     * scale;
                float x1 = qkv[row * 384 + h * HD + d0 + 1] * scale;
                int ri = hh * 2 + rr;
                packsplit2h(x0, x1, Qhi[ks][ri], Qlo[ks][ri]);
            }
        }
    }

    float O[4][4];                    // [d-tile][frag] fp32 accumulators
#pragma unroll
    for (int nt = 0; nt < 4; nt++)
#pragma unroll
        for (int i = 0; i < 4; i++) O[nt][i] = 0.0f;
    float m0v = -INFINITY, m1v = -INFINITY, l0v = 0.0f, l1v = 0.0f;

    const int kbeg = kc * CHUNK;
    for (int kb = kbeg; kb < kbeg + CHUNK; kb += KT) {
        __syncthreads();
        // ---- stage pre-swizzled tile image (pure vector copy) ----
        {
            const uint4* src = reinterpret_cast<const uint4*>(
                g_kv + (size_t)(h * (S / KT) + (kb >> 6)) * TILE_H);
            uint4* dst = reinterpret_cast<uint4*>(tile);
            for (int i = tid; i < TILE_U4; i += 256) dst[i] = src[i];
        }
        __syncthreads();

        // ---- QK^T: 8 n-tiles of 8 keys, 3-term fp16 ----
        float Sf[8][4];
#pragma unroll
        for (int nt = 0; nt < 8; nt++) {
#pragma unroll
            for (int i = 0; i < 4; i++) Sf[nt][i] = 0.0f;
            int key = nt * 8 + g;
            const __half* krow = &tile[key * KROW];
#pragma unroll
            for (int ks = 0; ks < 2; ks++) {
                uint32_t bh0 = *reinterpret_cast<const uint32_t*>(&krow[ks * 16 + 2 * t4]);
                uint32_t bh1 = *reinterpret_cast<const uint32_t*>(&krow[ks * 16 + 8 + 2 * t4]);
                uint32_t bl0 = *reinterpret_cast<const uint32_t*>(&krow[32 + ks * 16 + 2 * t4]);
                uint32_t bl1 = *reinterpret_cast<const uint32_t*>(&krow[32 + ks * 16 + 8 + 2 * t4]);
                mma16816(Sf[nt][0], Sf[nt][1], Sf[nt][2], Sf[nt][3],
                         Qhi[ks][0], Qhi[ks][1], Qhi[ks][2], Qhi[ks][3], bh0, bh1);
                mma16816(Sf[nt][0], Sf[nt][1], Sf[nt][2], Sf[nt][3],
                         Qlo[ks][0], Qlo[ks][1], Qlo[ks][2], Qlo[ks][3], bh0, bh1);
                mma16816(Sf[nt][0], Sf[nt][1], Sf[nt][2], Sf[nt][3],
                         Qhi[ks][0], Qhi[ks][1], Qhi[ks][2], Qhi[ks][3], bl0, bl1);
            }
        }

        // ---- mask ----
        if (kb + KT > sn) {
#pragma unroll
            for (int nt = 0; nt < 8; nt++) {
                int k0 = kb + nt * 8 + 2 * t4;
                if (k0     >= sn) { Sf[nt][0] = -INFINITY; Sf[nt][2] = -INFINITY; }
                if (k0 + 1 >= sn) { Sf[nt][1] = -INFINITY; Sf[nt][3] = -INFINITY; }
            }
        }

        // ---- online softmax ----
        float mx0 = -INFINITY, mx1 = -INFINITY;
#pragma unroll
        for (int nt = 0; nt < 8; nt++) {
            mx0 = fmaxf(mx0, fmaxf(Sf[nt][0], Sf[nt][1]));
            mx1 = fmaxf(mx1, fmaxf(Sf[nt][2], Sf[nt][3]));
        }
#pragma unroll
        for (int o = 1; o <= 2; o <<= 1) {
            mx0 = fmaxf(mx0, __shfl_xor_sync(0xffffffffu, mx0, o));
            mx1 = fmaxf(mx1, __shfl_xor_sync(0xffffffffu, mx1, o));
        }
        float mn0 = fmaxf(m0v, mx0);
        float mn1 = fmaxf(m1v, mx1);
        if (mn0 == -INFINITY) mn0 = 0.0f;   // fully-masked guard
        if (mn1 == -INFINITY) mn1 = 0.0f;
        float c0 = __expf(m0v - mn0);
        float c1 = __expf(m1v - mn1);
        l0v *= c0;  l1v *= c1;
#pragma unroll
        for (int nt = 0; nt < 4; nt++) {
            O[nt][0] *= c0; O[nt][1] *= c0;
            O[nt][2] *= c1; O[nt][3] *= c1;
        }
        m0v = mn0; m1v = mn1;

        float rs0 = 0.0f, rs1 = 0.0f;
        uint32_t Ph[4][4];               // single fp16 P fragments
#pragma unroll
        for (int j = 0; j < 4; j++) {    // key-step j covers tiles 2j, 2j+1
#pragma unroll
            for (int tt = 0; tt < 2; tt++) {
                int nt = 2 * j + tt;
                float p0 = __expf(Sf[nt][0] - mn0);
                float p1 = __expf(Sf[nt][1] - mn0);
                float p2 = __expf(Sf[nt][2] - mn1);
                float p3 = __expf(Sf[nt][3] - mn1);
                rs0 += p0 + p1;
                rs1 += p2 + p3;
                Ph[j][tt * 2]     = pack2f(p0, p1);
                Ph[j][tt * 2 + 1] = pack2f(p2, p3);
            }
        }
#pragma unroll
        for (int o = 1; o <= 2; o <<= 1) {
            rs0 += __shfl_xor_sync(0xffffffffu, rs0, o);
            rs1 += __shfl_xor_sync(0xffffffffu, rs1, o);
        }
        l0v += rs0;  l1v += rs1;

        // ---- PV: 4 d-tiles x 4 key-steps, 2-term (P fp16, V hi/lo) ----
#pragma unroll
        for (int nt = 0; nt < 4; nt++) {
            int d = nt * 8 + g;
            const __half* vrow = &tile[KIMG + d * VROW];
#pragma unroll
            for (int ks = 0; ks < 4; ks++) {
                uint32_t bh0 = *reinterpret_cast<const uint32_t*>(&vrow[ks * 16 + 2 * t4]);
                uint32_t bh1 = *reinterpret_cast<const uint32_t*>(&vrow[ks * 16 + 8 + 2 * t4]);
                uint32_t bl0 = *reinterpret_cast<const uint32_t*>(&vrow[64 + ks * 16 + 2 * t4]);
                uint32_t bl1 = *reinterpret_cast<const uint32_t*>(&vrow[64 + ks * 16 + 8 + 2 * t4]);
                mma16816(O[nt][0], O[nt][1], O[nt][2], O[nt][3],
                         Ph[ks][0], Ph[ks][1], Ph[ks][2], Ph[ks][3], bh0, bh1);
                mma16816(O[nt][0], O[nt][1], O[nt][2], O[nt][3],
                         Ph[ks][0], Ph[ks][1], Ph[ks][2], Ph[ks][3], bl0, bl1);
            }
        }
    }

    // ---- write partials (unnormalized) ----
    const int p0 = (h * NKC + kc) * S + r0;
    const int p1 = (h * NKC + kc) * S + r1;
    if (t4 == 0) {
        g_pm[p0] = m0v;  g_pl[p0] = l0v;
        g_pm[p1] = m1v;  g_pl[p1] = l1v;
    }
#pragma unroll
    for (int nt = 0; nt < 4; nt++) {
        int d = nt * 8 + 2 * t4;
        g_po[(size_t)p0 * HD + d]     = O[nt][0];
        g_po[(size_t)p0 * HD + d + 1] = O[nt][1];
        g_po[(size_t)p1 * HD + d]     = O[nt][2];
        g_po[(size_t)p1 * HD + d + 1] = O[nt][3];
    }
}

// ============================================================================
// K4b: split-K combine. grid = (S/128, NHEADS, 4 d-quarters), 128 threads.
// ============================================================================
__global__ void __launch_bounds__(128) k_attn_comb(void) {
    const int h  = blockIdx.y;
    const int q  = blockIdx.x * 128 + threadIdx.x;
    const int dq = blockIdx.z * 8;

    float M = -INFINITY;
#pragma unroll
    for (int kc = 0; kc < NKC; kc++)
        M = fmaxf(M, g_pm[(h * NKC + kc) * S + q]);

    float L = 0.0f;
    float o[8];
#pragma unroll
    for (int d = 0; d < 8; d++) o[d] = 0.0f;

#pragma unroll
    for (int kc = 0; kc < NKC; kc++) {
        const int p = (h * NKC + kc) * S + q;
        float li = g_pl[p];
        if (li > 0.0f) {
            float w = __expf(g_pm[p] - M);
            L += li * w;
            const float4* po = reinterpret_cast<const float4*>(&g_po[(size_t)p * HD + dq]);
            float4 v0 = po[0], v1 = po[1];
            o[0] = fmaf(w, v0.x, o[0]);  o[1] = fmaf(w, v0.y, o[1]);
            o[2] = fmaf(w, v0.z, o[2]);  o[3] = fmaf(w, v0.w, o[3]);
            o[4] = fmaf(w, v1.x, o[4]);  o[5] = fmaf(w, v1.y, o[5]);
            o[6] = fmaf(w, v1.z, o[6]);  o[7] = fmaf(w, v1.w, o[7]);
        }
    }

    float inv = (L > 0.0f) ? 1.0f / L : 0.0f;
    float* dst = &g_att[q * HID + h * HD + dq];
#pragma unroll
    for (int d = 0; d < 8; d++) dst[d] = o[d] * inv;
}

// ============================================================================
// masked row-sum of eig_filter (double accumulation)
// ============================================================================
__global__ void k_zero_xsum() {
    g_xsum[threadIdx.x] = 0.0;
}

__global__ void __launch_bounds__(128) k_rowsum(const int* __restrict__ snp) {
    const int sn  = *snp;
    const int tid = threadIdx.x;
    const int m0  = blockIdx.x * 128;
    double acc = 0.0;
    for (int r = 0; r < 128; r++) {
        int row = m0 + r;
        if (row < sn) acc += (double)g_eigf[row * HID + tid];
    }
    atomicAdd(&g_xsum[tid], acc);
}

// ============================================================================
// pooled coefficients (single block)
// ============================================================================
__global__ void __launch_bounds__(128) k_pool(const float* __restrict__ dscW, const float* __restrict__ dscb,
                                              const float* __restrict__ dwvW, const float* __restrict__ dwvb,
                                              const float* __restrict__ dssW, const float* __restrict__ dssb,
                                              const int* __restrict__ lenp, const int* __restrict__ snp) {
    const int tid = threadIdx.x;
    __shared__ float sig[104];
    __shared__ float ssum[2];
    const float lenf = (float)(*lenp);
    const float snf  = (float)(*snp);

    if (tid < 104) {
        const float* W; const float* bb; int c; int NCc;
        if (tid < 50)       { W = dscW; bb = dscb; c = tid;       NCc = NCOE; }
        else if (tid < 100) { W = dwvW; bb = dwvb; c = tid - 50;  NCc = NCOE; }
        else                { W = dssW; bb = dssb; c = tid - 100; NCc = NSCALES; }
        double acc = 0.0;
        for (int k = 0; k < HID; k++) acc += g_xsum[k] * (double)W[k * NCc + c];
        float pooled = (float)((acc + (double)(snf * bb[c])) / (double)(lenf + 1e-8f));
        sig[tid] = 1.0f / (1.0f + expf(-pooled));
    }
    __syncthreads();
    if (tid == 0) { float t = 0.f; for (int i = 0;  i < 50;  i++) t += sig[i]; ssum[0] = t; }
    if (tid == 1) { float t = 0.f; for (int i = 50; i < 100; i++) t += sig[i]; ssum[1] = t; }
    __syncthreads();
    if (tid < 50)       g_coef[tid] = sig[tid] / (ssum[0] + 1e-8f);
    else if (tid < 100) g_coef[tid] = sig[tid] / (ssum[1] + 1e-8f);
    else if (tid < 104) g_coef[tid] = sig[tid] * 5.0f;   // THRE
}

// ============================================================================
// Chebyshev synthesis + L2 normalize  ->  out[S, 5]
// ============================================================================
__global__ void __launch_bounds__(128) k_final(const float* __restrict__ eve,
                                               float* __restrict__ out) {
    __shared__ float cs[NCOE], cw[NCOE], sc[NSCALES];
    const int tid = threadIdx.x;
    if (tid < 50)        cs[tid]       = g_coef[tid];
    else if (tid < 100)  cw[tid - 50]  = g_coef[tid];
    else if (tid < 104)  sc[tid - 100] = g_coef[tid];
    __syncthreads();

    const int s = blockIdx.x * 128 + tid;
    const float e = eve[s];
    float vals[5];

    {   // scaling channel: y = e - 1; coefficients on T_1,T_3,...
        float y  = e - 1.0f;
        float te = 1.0f, to = y;
        float acc = cs[0] * (0.5f * (1.0f - to));
#pragma unroll
        for (int c = 1; c < NCOE; c++) {
            te = 2.0f * y * to - te;          // T_{2c}
            to = 2.0f * y * te - to;          // T_{2c+1}
            acc += cs[c] * (0.5f * (1.0f - to));
        }
        vals[0] = acc;
    }

#pragma unroll
    for (int j = 0; j < NSCALES; j++) {       // wavelet channels: T_0,T_2,...
        float f = e * sc[j];
        if (f > 2.0f) f = 0.0f;
        float y  = f - 1.0f;
        float te = 1.0f, to = y;
        float acc = 0.0f;                      // cw[0] * 0.5*(1-T_0) = 0
#pragma unroll
        for (int c = 1; c < NCOE; c++) {
            te = 2.0f * y * to - te;          // T_{2c}
            acc += cw[c] * (0.5f * (1.0f - te));
            to = 2.0f * y * te - to;          // T_{2c+1}
        }
        vals[1 + j] = acc;
    }

    float n2 = 0.0f;
#pragma unroll
    for (int i = 0; i < 5; i++) n2 += vals[i] * vals[i];
    float inv = 1.0f / (sqrtf(n2) + 1e-8f);
#pragma unroll
    for (int i = 0; i < 5; i++) out[s * 5 + i] = vals[i] * inv;
}

// ============================================================================
// launch
// ============================================================================
extern "C" void kernel_launch(void* const* d_in, const int* in_sizes, int n_in,
                              void* d_out, int out_size) {
    const float* eve      = (const float*)d_in[0];
    const int*   lenp     = (const int*)  d_in[1];
    const int*   snp      = (const int*)  d_in[2];
    const float* eig_w_W  = (const float*)d_in[3];
    const float* eig_w_b  = (const float*)d_in[4];
    const float* mha_ln_g = (const float*)d_in[5];
    const float* mha_ln_b = (const float*)d_in[6];
    const float* in_W     = (const float*)d_in[7];
    const float* in_b     = (const float*)d_in[8];
    const float* out_W    = (const float*)d_in[9];
    const float* out_b    = (const float*)d_in[10];
    const float* ffn_ln_g = (const float*)d_in[11];
    const float* ffn_ln_b = (const float*)d_in[12];
    const float* ffn1_W   = (const float*)d_in[13];
    const float* ffn1_b   = (const float*)d_in[14];
    const float* ffn2_W   = (const float*)d_in[15];
    const float* ffn2_b   = (const float*)d_in[16];
    const float* dsc_W    = (const float*)d_in[17];
    const float* dsc_b    = (const float*)d_in[18];
    const float* dwv_W    = (const float*)d_in[19];
    const float* dwv_b    = (const float*)d_in[20];
    const float* dss_W    = (const float*)d_in[21];
    const float* dss_b    = (const float*)d_in[22];
    float* out = (float*)d_out;

    float *p_eig, *p_qkv, *p_att, *p_h1, *p_eigf;
    cudaGetSymbolAddress((void**)&p_eig,  g_eig);
    cudaGetSymbolAddress((void**)&p_qkv,  g_qkv);
    cudaGetSymbolAddress((void**)&p_att,  g_att);
    cudaGetSymbolAddress((void**)&p_h1,   g_h1);
    cudaGetSymbolAddress((void**)&p_eigf, g_eigf);

    // 1) eig = sine_encoding(eve) @ W + b
    k_sine_enc<<<S / 8, 128>>>(eve, eig_w_W, eig_w_b);
    // 2) qkv = LN(eig) @ in_W + in_b        (LN fused)
    k_gemm<3, 0, 0, 1><<<S / 8, 128>>>(p_eig, in_W, in_b, nullptr, p_qkv, mha_ln_g, mha_ln_b);
    // 3) pre-swizzle K/V tiles to fp16 hi/lo images
    k_prep<<<dim3(S / KT, NHEADS), 256>>>(p_qkv);
    // 4) attention (tensor-core split-K partials + combine)
    k_attn_mma<<<dim3(S / QT, NHEADS, NKC), 256>>>(p_qkv, snp);
    k_attn_comb<<<dim3(S / 128, NHEADS, 4), 128>>>();
    // 5) eig = eig + att @ out_W + out_b
    k_gemm<1, 0, 1, 0><<<S / 8, 128>>>(p_att, out_W, out_b, p_eig, p_eig, nullptr, nullptr);
    // 6) h1 = gelu(LN(eig) @ ffn1_W + b)    (LN fused)
    k_gemm<1, 1, 0, 1><<<S / 8, 128>>>(p_eig, ffn1_W, ffn1_b, nullptr, p_h1, ffn_ln_g, ffn_ln_b);
    // 7) eigf = eig + h1 @ ffn2_W + b
    k_gemm<1, 0, 1, 0><<<S / 8, 128>>>(p_h1, ffn2_W, ffn2_b, p_eig, p_eigf, nullptr, nullptr);
    // 8) masked row-sum (double)
    k_zero_xsum<<<1, 128>>>();
    k_rowsum<<<S / 128, 128>>>(snp);
    // 9) pooled coefficients
    k_pool<<<1, 128>>>(dsc_W, dsc_b, dwv_W, dwv_b, dss_W, dss_b, lenp, snp);
    // 10) Chebyshev synthesis + normalize
    k_final<<<S / 128, 128>>>(eve, out);
}

// round 7
// speedup vs baseline: 1.6235x; 1.6235x over previous
#include <cuda_runtime.h>
#include <cuda_fp16.h>
#include <math.h>
#include <stdint.h>

// ---------------- problem constants ----------------
#define S 4096
#define HID 128
#define NHEADS 4
#define HD 32
#define NCOE 50
#define NSCALES 4
#define NKC 4              // split-K chunks for attention
#define CHUNK (S / NKC)    // 1024 keys per chunk
#define QT 128             // queries per block (8 warps x 16)
#define KT 64              // key tile
#define NT_CH (CHUNK / KT) // 16 tiles per chunk

// KV tile image geometry (halves). Padded rows for conflict-free LDS.
#define KROW 40                      // per-key: 32 hi + 8 pad
#define KIMG (KT * KROW)             // 2560 halves
#define VROW 136                     // per-dim: 64 hi + 64 lo + 8 pad
#define VIMG (HD * VROW)             // 4352 halves
#define TILE_H (KIMG + VIMG)         // 6912 halves = 13824 B
#define TILE_U4 (TILE_H / 8)         // 864 uint4

// ---------------- scratch (__device__ globals; no allocs allowed) ----------------
__device__ float  g_eig [S * HID];
__device__ float  g_qkv [S * 3 * HID];
__device__ float  g_att [S * HID];
__device__ float  g_h1  [S * HID];
__device__ float  g_eigf[S * HID];
__device__ __align__(16) __half g_kv[NHEADS * (S / KT) * TILE_H];  // pre-swizzled K/V tiles
__device__ float  g_pm  [NHEADS * NKC * S];        // partial max
__device__ float  g_pl  [NHEADS * NKC * S];        // partial sum
__device__ float  g_po  [NHEADS * NKC * S * HD];   // partial (unnormalized) out
__device__ double g_xsum[HID];
__device__ float  g_coef[128];   // [0:50) scaling, [50:100) wavelet, [100:104) scales

// ---------------- mma / async helpers ----------------
__device__ __forceinline__ void mma16816(float& c0, float& c1, float& c2, float& c3,
                                         uint32_t a0, uint32_t a1, uint32_t a2, uint32_t a3,
                                         uint32_t b0, uint32_t b1) {
    asm volatile("mma.sync.aligned.m16n8k16.row.col.f32.f16.f16.f32 "
                 "{%0,%1,%2,%3}, {%4,%5,%6,%7}, {%8,%9}, {%0,%1,%2,%3};\n"
                 : "+f"(c0), "+f"(c1), "+f"(c2), "+f"(c3)
                 : "r"(a0), "r"(a1), "r"(a2), "r"(a3), "r"(b0), "r"(b1));
}

__device__ __forceinline__ void cp16(uint32_t dst, const void* src) {
    asm volatile("cp.async.cg.shared.global [%0], [%1], 16;\n" :: "r"(dst), "l"(src));
}
__device__ __forceinline__ void cp_commit() {
    asm volatile("cp.async.commit_group;\n");
}
__device__ __forceinline__ void cp_wait_all() {
    asm volatile("cp.async.wait_group 0;\n");
}

__device__ __forceinline__ uint32_t packh2(__half a, __half b) {
    __half2 t = __halves2half2(a, b);     // a -> low half
    return *reinterpret_cast<uint32_t*>(&t);
}

// split x into hi (fp16) and lo (fp16 of remainder)
__device__ __forceinline__ void hsplit(float x, __half& h, __half& l) {
    h = __float2half_rn(x);
    l = __float2half_rn(x - __half2float(h));
}

__device__ __forceinline__ void packsplit2h(float x, float y, uint32_t& hi, uint32_t& lo) {
    __half xh, xl, yh, yl;
    hsplit(x, xh, xl);
    hsplit(y, yh, yl);
    hi = packh2(xh, yh);
    lo = packh2(xl, yl);
}

__device__ __forceinline__ uint32_t pack2f(float x, float y) {
    __half2 t = __floats2half2_rn(x, y);  // x -> low
    return *reinterpret_cast<uint32_t*>(&t);
}

// ============================================================================
// K1: sine encoding + GEMM  ->  g_eig = eeig[S,129] @ W[129,128] + b
// 16 rows per block, 128 threads
// ============================================================================
__global__ void __launch_bounds__(128) k_sine_enc(const float* __restrict__ eve,
                                                  const float* __restrict__ W,
                                                  const float* __restrict__ b) {
    __shared__ float ee[16][132];   // 129 used
    const int m0  = blockIdx.x * 16;
    const int tid = threadIdx.x;
    const float kLog = -9.210340371976184f / 128.0f;   // -ln(1e4)/128

    for (int idx = tid; idx < 16 * 129; idx += 128) {
        int r = idx / 129, j = idx - r * 129;
        float e = eve[m0 + r];
        float val;
        if (j == 0) {
            val = e;
        } else if (j <= 64) {
            int i = j - 1;
            float div = __expf((2.0f * i) * kLog);
            val = sinf(e * 100.0f * div);
        } else {
            int i = j - 65;
            float div = __expf((2.0f * i) * kLog);
            val = cosf(e * 100.0f * div);
        }
        ee[r][j] = val;
    }
    __syncthreads();

    float acc[16];
#pragma unroll
    for (int r = 0; r < 16; r++) acc[r] = 0.0f;

    for (int k = 0; k < 129; k++) {
        float wv = W[k * HID + tid];
#pragma unroll
        for (int r = 0; r < 16; r++) acc[r] = fmaf(ee[r][k], wv, acc[r]);
    }
    float bb = b[tid];
#pragma unroll
    for (int r = 0; r < 16; r++) g_eig[(m0 + r) * HID + tid] = acc[r] + bb;
}

// ============================================================================
// GEMM  C[M,N] = act( LN?(A)[M,128] @ W[128,N] + bias ) (+ R)
// 16 rows per block, 128 threads. NC = N/128 columns per thread.
// ============================================================================
template <int NC, int ACT, int RESID, int LNORM>
__global__ void __launch_bounds__(128) k_gemm(const float* __restrict__ A,
                                              const float* __restrict__ W,
                                              const float* __restrict__ bias,
                                              const float* __restrict__ R,
                                              float* __restrict__ C,
                                              const float* __restrict__ lng,
                                              const float* __restrict__ lnb) {
    constexpr int N = NC * 128;
    __shared__ float As[16][HID];
    __shared__ float rowMean[16], rowRstd[16];
    const int m0  = blockIdx.x * 16;
    const int tid = threadIdx.x;

    for (int idx = tid; idx < 16 * HID; idx += 128)
        As[idx >> 7][idx & 127] = A[m0 * HID + idx];
    __syncthreads();

    if (LNORM) {
        const int r = tid >> 3, l8 = tid & 7;
        float s = 0.0f, s2 = 0.0f;
        for (int j = l8; j < HID; j += 8) {
            float v = As[r][j];
            s += v; s2 += v * v;
        }
#pragma unroll
        for (int o = 4; o; o >>= 1) {
            s  += __shfl_xor_sync(0xffffffffu, s,  o);
            s2 += __shfl_xor_sync(0xffffffffu, s2, o);
        }
        if (l8 == 0) {
            float mean = s * (1.0f / HID);
            float var  = s2 * (1.0f / HID) - mean * mean;
            rowMean[r] = mean;
            rowRstd[r] = rsqrtf(var + 1e-5f);
        }
        __syncthreads();
        float gg = lng[tid], bb2 = lnb[tid];
#pragma unroll
        for (int r2 = 0; r2 < 16; r2++)
            As[r2][tid] = (As[r2][tid] - rowMean[r2]) * rowRstd[r2] * gg + bb2;
        __syncthreads();
    }

    float acc[NC][16];
#pragma unroll
    for (int c = 0; c < NC; c++)
#pragma unroll
        for (int r = 0; r < 16; r++) acc[c][r] = 0.0f;

    for (int k = 0; k < HID; k += 4) {
        float wv[4][NC];
#pragma unroll
        for (int i = 0; i < 4; i++)
#pragma unroll
            for (int c = 0; c < NC; c++)
                wv[i][c] = W[(k + i) * N + c * 128 + tid];
#pragma unroll
        for (int r = 0; r < 16; r++) {
            float4 a4 = *reinterpret_cast<const float4*>(&As[r][k]);
#pragma unroll
            for (int c = 0; c < NC; c++) {
                acc[c][r] = fmaf(a4.x, wv[0][c], acc[c][r]);
                acc[c][r] = fmaf(a4.y, wv[1][c], acc[c][r]);
                acc[c][r] = fmaf(a4.z, wv[2][c], acc[c][r]);
                acc[c][r] = fmaf(a4.w, wv[3][c], acc[c][r]);
            }
        }
    }

#pragma unroll
    for (int c = 0; c < NC; c++) {
        int col = c * 128 + tid;
        float bb = bias[col];
#pragma unroll
        for (int r = 0; r < 16; r++) {
            float v = acc[c][r] + bb;
            if (ACT == 1) v = 0.5f * v * (1.0f + erff(v * 0.70710678118654752f));
            if (RESID)    v += R[(m0 + r) * HID + tid];
            C[(m0 + r) * N + col] = v;
        }
    }
}

// ============================================================================
// K-prep: build per-(head, 64-key tile) smem-image of K (hi) and V^T (hi/lo)
// in fp16 with the exact padded layout the attention kernel uses.
// grid = (S/KT, NHEADS), 256 threads.
// ============================================================================
__global__ void __launch_bounds__(256) k_prep(const float* __restrict__ qkv) {
    __shared__ __align__(16) __half img[TILE_H];
    const int tid = threadIdx.x;
    const int kb  = blockIdx.x * KT;
    const int h   = blockIdx.y;

    for (int i = tid; i < KT * HD; i += 256) {
        int key = i >> 5, d = i & 31;
        const float* base = qkv + (size_t)(kb + key) * 384 + h * HD + d;
        float kx = base[128];
        float vx = base[256];
        __half vh, vl;
        hsplit(vx, vh, vl);
        img[key * KROW + d] = __float2half_rn(kx);
        img[KIMG + d * VROW + key]      = vh;
        img[KIMG + d * VROW + 64 + key] = vl;
    }
    __syncthreads();

    uint4* dst = reinterpret_cast<uint4*>(g_kv + (size_t)(h * (S / KT) + blockIdx.x) * TILE_H);
    const uint4* src = reinterpret_cast<const uint4*>(img);
    for (int i = tid; i < TILE_U4; i += 256) dst[i] = src[i];
}

// ============================================================================
// K4a: MMA flash attention partial (fp16; exact-Q x Khi QK, PV 2-term).
// cp.async double-buffered tile staging.
// grid = (S/QT, NHEADS, NKC), block = 256 (8 warps x 16 queries).
// ============================================================================
__global__ void __launch_bounds__(256) k_attn_mma(const float* __restrict__ qkv,
                                                  const int* __restrict__ snp) {
    __shared__ __align__(16) __half tile[2][TILE_H];

    const int tid  = threadIdx.x;
    const int warp = tid >> 5;
    const int lane = tid & 31;
    const int g    = lane >> 2;    // group (row within fragment)
    const int t4   = lane & 3;     // thread-in-group
    const int h    = blockIdx.y;
    const int kc   = blockIdx.z;
    const int sn   = *snp;
    const float scale = 0.17677669529663687f;   // 1/sqrt(32)

    const int qbase = blockIdx.x * QT + warp * 16;
    const int r0 = qbase + g;        // query rows owned by this thread
    const int r1 = r0 + 8;

    const uint32_t sm0 = (uint32_t)__cvta_generic_to_shared(&tile[0][0]);
    const uint32_t sm1 = (uint32_t)__cvta_generic_to_shared(&tile[1][0]);

    // ---- load Q fragments (2 k-steps), split hi/lo fp16 ----
    uint32_t Qhi[2][4], Qlo[2][4];
#pragma unroll
    for (int ks = 0; ks < 2; ks++) {
#pragma unroll
        for (int hh = 0; hh < 2; hh++) {     // k-half (+0 / +8)
#pragma unroll
            for (int rr = 0; rr < 2; rr++) { // row g / g+8
                int row = rr ? r1 : r0;
                int d0  = ks * 16 + hh * 8 + 2 * t4;
                float x0 = qkv[row * 384 + h * HD + d0]     * scale;
                float x1 = qkv[row * 384 + h * HD + d0 + 1] * scale;
                int ri = hh * 2 + rr;
                packsplit2h(x0, x1, Qhi[ks][ri], Qlo[ks][ri]);
            }
        }
    }

    float O[4][4];                    // [d-tile][frag] fp32 accumulators
#pragma unroll
    for (int nt = 0; nt < 4; nt++)
#pragma unroll
        for (int i = 0; i < 4; i++) O[nt][i] = 0.0f;
    float m0v = -INFINITY, m1v = -INFINITY, l0v = 0.0f, l1v = 0.0f;

    const int tile0 = (kc * CHUNK) >> 6;    // first tile index in this chunk

    // prefetch tile 0 into buffer 0
    {
        const uint4* src = reinterpret_cast<const uint4*>(
            g_kv + (size_t)(h * (S / KT) + tile0) * TILE_H);
        for (int i = tid; i < TILE_U4; i += 256)
            cp16(sm0 + i * 16, src + i);
        cp_commit();
    }

    for (int it = 0; it < NT_CH; it++) {
        cp_wait_all();
        __syncthreads();

        // prefetch next tile into the other buffer (overlaps compute below)
        if (it + 1 < NT_CH) {
            const uint4* src = reinterpret_cast<const uint4*>(
                g_kv + (size_t)(h * (S / KT) + tile0 + it + 1) * TILE_H);
            uint32_t dstb = ((it + 1) & 1) ? sm1 : sm0;
            for (int i = tid; i < TILE_U4; i += 256)
                cp16(dstb + i * 16, src + i);
            cp_commit();
        }

        const __half* tl = tile[it & 1];
        const int kb = kc * CHUNK + it * KT;

        // ---- QK^T: 8 n-tiles of 8 keys; exact-Q (hi+lo) x Khi ----
        float Sf[8][4];
#pragma unroll
        for (int nt = 0; nt < 8; nt++) {
#pragma unroll
            for (int i = 0; i < 4; i++) Sf[nt][i] = 0.0f;
            int key = nt * 8 + g;
            const __half* krow = &tl[key * KROW];
#pragma unroll
            for (int ks = 0; ks < 2; ks++) {
                uint32_t bh0 = *reinterpret_cast<const uint32_t*>(&krow[ks * 16 + 2 * t4]);
                uint32_t bh1 = *reinterpret_cast<const uint32_t*>(&krow[ks * 16 + 8 + 2 * t4]);
                mma16816(Sf[nt][0], Sf[nt][1], Sf[nt][2], Sf[nt][3],
                         Qhi[ks][0], Qhi[ks][1], Qhi[ks][2], Qhi[ks][3], bh0, bh1);
                mma16816(Sf[nt][0], Sf[nt][1], Sf[nt][2], Sf[nt][3],
                         Qlo[ks][0], Qlo[ks][1], Qlo[ks][2], Qlo[ks][3], bh0, bh1);
            }
        }

        // ---- mask ----
        if (kb + KT > sn) {
#pragma unroll
            for (int nt = 0; nt < 8; nt++) {
                int k0 = kb + nt * 8 + 2 * t4;
                if (k0     >= sn) { Sf[nt][0] = -INFINITY; Sf[nt][2] = -INFINITY; }
                if (k0 + 1 >= sn) { Sf[nt][1] = -INFINITY; Sf[nt][3] = -INFINITY; }
            }
        }

        // ---- online softmax ----
        float mx0 = -INFINITY, mx1 = -INFINITY;
#pragma unroll
        for (int nt = 0; nt < 8; nt++) {
            mx0 = fmaxf(mx0, fmaxf(Sf[nt][0], Sf[nt][1]));
            mx1 = fmaxf(mx1, fmaxf(Sf[nt][2], Sf[nt][3]));
        }
#pragma unroll
        for (int o = 1; o <= 2; o <<= 1) {
            mx0 = fmaxf(mx0, __shfl_xor_sync(0xffffffffu, mx0, o));
            mx1 = fmaxf(mx1, __shfl_xor_sync(0xffffffffu, mx1, o));
        }
        float mn0 = fmaxf(m0v, mx0);
        float mn1 = fmaxf(m1v, mx1);
        if (mn0 == -INFINITY) mn0 = 0.0f;   // fully-masked guard
        if (mn1 == -INFINITY) mn1 = 0.0f;
        float c0 = __expf(m0v - mn0);
        float c1 = __expf(m1v - mn1);
        l0v *= c0;  l1v *= c1;
#pragma unroll
        for (int nt = 0; nt < 4; nt++) {
            O[nt][0] *= c0; O[nt][1] *= c0;
            O[nt][2] *= c1; O[nt][3] *= c1;
        }
        m0v = mn0; m1v = mn1;

        float rs0 = 0.0f, rs1 = 0.0f;
        uint32_t Ph[4][4];               // single fp16 P fragments
#pragma unroll
        for (int j = 0; j < 4; j++) {    // key-step j covers tiles 2j, 2j+1
#pragma unroll
            for (int tt = 0; tt < 2; tt++) {
                int nt = 2 * j + tt;
                float p0 = __expf(Sf[nt][0] - mn0);
                float p1 = __expf(Sf[nt][1] - mn0);
                float p2 = __expf(Sf[nt][2] - mn1);
                float p3 = __expf(Sf[nt][3] - mn1);
                rs0 += p0 + p1;
                rs1 += p2 + p3;
                Ph[j][tt * 2]     = pack2f(p0, p1);
                Ph[j][tt * 2 + 1] = pack2f(p2, p3);
            }
        }
#pragma unroll
        for (int o = 1; o <= 2; o <<= 1) {
            rs0 += __shfl_xor_sync(0xffffffffu, rs0, o);
            rs1 += __shfl_xor_sync(0xffffffffu, rs1, o);
        }
        l0v += rs0;  l1v += rs1;

        // ---- PV: 4 d-tiles x 4 key-steps, 2-term (P fp16, V hi/lo) ----
#pragma unroll
        for (int nt = 0; nt < 4; nt++) {
            int d = nt * 8 + g;
            const __half* vrow = &tl[KIMG + d * VROW];
#pragma unroll
            for (int ks = 0; ks < 4; ks++) {
                uint32_t bh0 = *reinterpret_cast<const uint32_t*>(&vrow[ks * 16 + 2 * t4]);
                uint32_t bh1 = *reinterpret_cast<const uint32_t*>(&vrow[ks * 16 + 8 + 2 * t4]);
                uint32_t bl0 = *reinterpret_cast<const uint32_t*>(&vrow[64 + ks * 16 + 2 * t4]);
                uint32_t bl1 = *reinterpret_cast<const uint32_t*>(&vrow[64 + ks * 16 + 8 + 2 * t4]);
                mma16816(O[nt][0], O[nt][1], O[nt][2], O[nt][3],
                         Ph[ks][0], Ph[ks][1], Ph[ks][2], Ph[ks][3], bh0, bh1);
                mma16816(O[nt][0], O[nt][1], O[nt][2], O[nt][3],
                         Ph[ks][0], Ph[ks][1], Ph[ks][2], Ph[ks][3], bl0, bl1);
            }
        }
        __syncthreads();
    }

    // ---- write partials (unnormalized) ----
    const int p0 = (h * NKC + kc) * S + r0;
    const int p1 = (h * NKC + kc) * S + r1;
    if (t4 == 0) {
        g_pm[p0] = m0v;  g_pl[p0] = l0v;
        g_pm[p1] = m1v;  g_pl[p1] = l1v;
    }
#pragma unroll
    for (int nt = 0; nt < 4; nt++) {
        int d = nt * 8 + 2 * t4;
        g_po[(size_t)p0 * HD + d]     = O[nt][0];
        g_po[(size_t)p0 * HD + d + 1] = O[nt][1];
        g_po[(size_t)p1 * HD + d]     = O[nt][2];
        g_po[(size_t)p1 * HD + d + 1] = O[nt][3];
    }
}

// ============================================================================
// K4b: split-K combine. grid = (S/128, NHEADS, 4 d-quarters), 128 threads.
// ============================================================================
__global__ void __launch_bounds__(128) k_attn_comb(void) {
    const int h  = blockIdx.y;
    const int q  = blockIdx.x * 128 + threadIdx.x;
    const int dq = blockIdx.z * 8;

    float M = -INFINITY;
#pragma unroll
    for (int kc = 0; kc < NKC; kc++)
        M = fmaxf(M, g_pm[(h * NKC + kc) * S + q]);

    float L = 0.0f;
    float o[8];
#pragma unroll
    for (int d = 0; d < 8; d++) o[d] = 0.0f;

#pragma unroll
    for (int kc = 0; kc < NKC; kc++) {
        const int p = (h * NKC + kc) * S + q;
        float li = g_pl[p];
        if (li > 0.0f) {
            float w = __expf(g_pm[p] - M);
            L += li * w;
            const float4* po = reinterpret_cast<const float4*>(&g_po[(size_t)p * HD + dq]);
            float4 v0 = po[0], v1 = po[1];
            o[0] = fmaf(w, v0.x, o[0]);  o[1] = fmaf(w, v0.y, o[1]);
            o[2] = fmaf(w, v0.z, o[2]);  o[3] = fmaf(w, v0.w, o[3]);
            o[4] = fmaf(w, v1.x, o[4]);  o[5] = fmaf(w, v1.y, o[5]);
            o[6] = fmaf(w, v1.z, o[6]);  o[7] = fmaf(w, v1.w, o[7]);
        }
    }

    float inv = (L > 0.0f) ? 1.0f / L : 0.0f;
    float* dst = &g_att[q * HID + h * HD + dq];
#pragma unroll
    for (int d = 0; d < 8; d++) dst[d] = o[d] * inv;
}

// ============================================================================
// masked row-sum of eig_filter (double accumulation)
// ============================================================================
__global__ void k_zero_xsum() {
    g_xsum[threadIdx.x] = 0.0;
}

__global__ void __launch_bounds__(128) k_rowsum(const int* __restrict__ snp) {
    const int sn  = *snp;
    const int tid = threadIdx.x;
    const int m0  = blockIdx.x * 128;
    double acc = 0.0;
    for (int r = 0; r < 128; r++) {
        int row = m0 + r;
        if (row < sn) acc += (double)g_eigf[row * HID + tid];
    }
    atomicAdd(&g_xsum[tid], acc);
}

// ============================================================================
// pooled coefficients (single block)
// ============================================================================
__global__ void __launch_bounds__(128) k_pool(const float* __restrict__ dscW, const float* __restrict__ dscb,
                                              const float* __restrict__ dwvW, const float* __restrict__ dwvb,
                                              const float* __restrict__ dssW, const float* __restrict__ dssb,
                                              const int* __restrict__ lenp, const int* __restrict__ snp) {
    const int tid = threadIdx.x;
    __shared__ float sig[104];
    __shared__ float ssum[2];
    const float lenf = (float)(*lenp);
    const float snf  = (float)(*snp);

    if (tid < 104) {
        const float* W; const float* bb; int c; int NCc;
        if (tid < 50)       { W = dscW; bb = dscb; c = tid;       NCc = NCOE; }
        else if (tid < 100) { W = dwvW; bb = dwvb; c = tid - 50;  NCc = NCOE; }
        else                { W = dssW; bb = dssb; c = tid - 100; NCc = NSCALES; }
        double acc = 0.0;
        for (int k = 0; k < HID; k++) acc += g_xsum[k] * (double)W[k * NCc + c];
        float pooled = (float)((acc + (double)(snf * bb[c])) / (double)(lenf + 1e-8f));
        sig[tid] = 1.0f / (1.0f + expf(-pooled));
    }
    __syncthreads();
    if (tid == 0) { float t = 0.f; for (int i = 0;  i < 50;  i++) t += sig[i]; ssum[0] = t; }
    if (tid == 1) { float t = 0.f; for (int i = 50; i < 100; i++) t += sig[i]; ssum[1] = t; }
    __syncthreads();
    if (tid < 50)       g_coef[tid] = sig[tid] / (ssum[0] + 1e-8f);
    else if (tid < 100) g_coef[tid] = sig[tid] / (ssum[1] + 1e-8f);
    else if (tid < 104) g_coef[tid] = sig[tid] * 5.0f;   // THRE
}

// ============================================================================
// Chebyshev synthesis + L2 normalize  ->  out[S, 5]
// ============================================================================
__global__ void __launch_bounds__(128) k_final(const float* __restrict__ eve,
                                               float* __restrict__ out) {
    __shared__ float cs[NCOE], cw[NCOE], sc[NSCALES];
    const int tid = threadIdx.x;
    if (tid < 50)        cs[tid]       = g_coef[tid];
    else if (tid < 100)  cw[tid - 50]  = g_coef[tid];
    else if (tid < 104)  sc[tid - 100] = g_coef[tid];
    __syncthreads();

    const int s = blockIdx.x * 128 + tid;
    const float e = eve[s];
    float vals[5];

    {   // scaling channel: y = e - 1; coefficients on T_1,T_3,...
        float y  = e - 1.0f;
        float te = 1.0f, to = y;
        float acc = cs[0] * (0.5f * (1.0f - to));
#pragma unroll
        for (int c = 1; c < NCOE; c++) {
            te = 2.0f * y * to - te;          // T_{2c}
            to = 2.0f * y * te - to;          // T_{2c+1}
            acc += cs[c] * (0.5f * (1.0f - to));
        }
        vals[0] = acc;
    }

#pragma unroll
    for (int j = 0; j < NSCALES; j++) {       // wavelet channels: T_0,T_2,...
        float f = e * sc[j];
        if (f > 2.0f) f = 0.0f;
        float y  = f - 1.0f;
        float te = 1.0f, to = y;
        float acc = 0.0f;                      // cw[0] * 0.5*(1-T_0) = 0
#pragma unroll
        for (int c = 1; c < NCOE; c++) {
            te = 2.0f * y * to - te;          // T_{2c}
            acc += cw[c] * (0.5f * (1.0f - te));
            to = 2.0f * y * te - to;          // T_{2c+1}
        }
        vals[1 + j] = acc;
    }

    float n2 = 0.0f;
#pragma unroll
    for (int i = 0; i < 5; i++) n2 += vals[i] * vals[i];
    float inv = 1.0f / (sqrtf(n2) + 1e-8f);
#pragma unroll
    for (int i = 0; i < 5; i++) out[s * 5 + i] = vals[i] * inv;
}

// ============================================================================
// launch
// ============================================================================
extern "C" void kernel_launch(void* const* d_in, const int* in_sizes, int n_in,
                              void* d_out, int out_size) {
    const float* eve      = (const float*)d_in[0];
    const int*   lenp     = (const int*)  d_in[1];
    const int*   snp      = (const int*)  d_in[2];
    const float* eig_w_W  = (const float*)d_in[3];
    const float* eig_w_b  = (const float*)d_in[4];
    const float* mha_ln_g = (const float*)d_in[5];
    const float* mha_ln_b = (const float*)d_in[6];
    const float* in_W     = (const float*)d_in[7];
    const float* in_b     = (const float*)d_in[8];
    const float* out_W    = (const float*)d_in[9];
    const float* out_b    = (const float*)d_in[10];
    const float* ffn_ln_g = (const float*)d_in[11];
    const float* ffn_ln_b = (const float*)d_in[12];
    const float* ffn1_W   = (const float*)d_in[13];
    const float* ffn1_b   = (const float*)d_in[14];
    const float* ffn2_W   = (const float*)d_in[15];
    const float* ffn2_b   = (const float*)d_in[16];
    const float* dsc_W    = (const float*)d_in[17];
    const float* dsc_b    = (const float*)d_in[18];
    const float* dwv_W    = (const float*)d_in[19];
    const float* dwv_b    = (const float*)d_in[20];
    const float* dss_W    = (const float*)d_in[21];
    const float* dss_b    = (const float*)d_in[22];
    float* out = (float*)d_out;

    float *p_eig, *p_qkv, *p_att, *p_h1, *p_eigf;
    cudaGetSymbolAddress((void**)&p_eig,  g_eig);
    cudaGetSymbolAddress((void**)&p_qkv,  g_qkv);
    cudaGetSymbolAddress((void**)&p_att,  g_att);
    cudaGetSymbolAddress((void**)&p_h1,   g_h1);
    cudaGetSymbolAddress((void**)&p_eigf, g_eigf);

    // 1) eig = sine_encoding(eve) @ W + b
    k_sine_enc<<<S / 16, 128>>>(eve, eig_w_W, eig_w_b);
    // 2) qkv = LN(eig) @ in_W + in_b        (LN fused)
    k_gemm<3, 0, 0, 1><<<S / 16, 128>>>(p_eig, in_W, in_b, nullptr, p_qkv, mha_ln_g, mha_ln_b);
    // 3) pre-swizzle K/V tiles to fp16 images
    k_prep<<<dim3(S / KT, NHEADS), 256>>>(p_qkv);
    // 4) attention (tensor-core split-K partials + combine)
    k_attn_mma<<<dim3(S / QT, NHEADS, NKC), 256>>>(p_qkv, snp);
    k_attn_comb<<<dim3(S / 128, NHEADS, 4), 128>>>();
    // 5) eig = eig + att @ out_W + out_b
    k_gemm<1, 0, 1, 0><<<S / 16, 128>>>(p_att, out_W, out_b, p_eig, p_eig, nullptr, nullptr);
    // 6) h1 = gelu(LN(eig) @ ffn1_W + b)    (LN fused)
    k_gemm<1, 1, 0, 1><<<S / 16, 128>>>(p_eig, ffn1_W, ffn1_b, nullptr, p_h1, ffn_ln_g, ffn_ln_b);
    // 7) eigf = eig + h1 @ ffn2_W + b
    k_gemm<1, 0, 1, 0><<<S / 16, 128>>>(p_h1, ffn2_W, ffn2_b, p_eig, p_eigf, nullptr, nullptr);
    // 8) masked row-sum (double)
    k_zero_xsum<<<1, 128>>>();
    k_rowsum<<<S / 128, 128>>>(snp);
    // 9) pooled coefficients
    k_pool<<<1, 128>>>(dsc_W, dsc_b, dwv_W, dwv_b, dss_W, dss_b, lenp, snp);
    // 10) Chebyshev synthesis + normalize
    k_final<<<S / 128, 128>>>(eve, out);
}

// round 10
// speedup vs baseline: 1.9442x; 1.1975x over previous
#include <cuda_runtime.h>
#include <cuda_fp16.h>
#include <math.h>
#include <stdint.h>

// ---------------- problem constants ----------------
#define S 4096
#define HID 128
#define NHEADS 4
#define HD 32
#define NCOE 50
#define NSCALES 4
#define NKC 4              // split-K chunks for attention
#define CHUNK (S / NKC)    // 1024 keys per chunk
#define QT 128             // queries per block (8 warps x 16)
#define KT 64              // key tile
#define NT_CH (CHUNK / KT) // 16 tiles per chunk

// KV tile image geometry (halves). Padded rows for conflict-free LDS.
#define KROW 40                      // per-key: 32 hi + 8 pad
#define KIMG (KT * KROW)             // 2560 halves
#define VROW 136                     // per-dim: 64 hi + 64 lo + 8 pad
#define VIMG (HD * VROW)             // 4352 halves
#define TILE_H (KIMG + VIMG)         // 6912 halves = 13824 B
#define TILE_U4 (TILE_H / 8)         // 864 uint4

// ---------------- scratch (__device__ globals; no allocs allowed) ----------------
__device__ float  g_eig [S * HID];
__device__ float  g_qkv [S * 3 * HID];
__device__ float  g_att [S * HID];
__device__ float  g_h1  [S * HID];
__device__ float  g_eigf[S * HID];
__device__ __align__(16) __half g_kv[NHEADS * (S / KT) * TILE_H];  // pre-swizzled K/V tiles
__device__ __align__(16) uint4  g_wf[6 * 4096];   // 6 weight images, fragment-ordered
__device__ float  g_pm  [NHEADS * NKC * S];        // partial max
__device__ float  g_pl  [NHEADS * NKC * S];        // partial sum
__device__ float  g_po  [NHEADS * NKC * S * HD];   // partial (unnormalized) out
__device__ double g_xsum[HID];
__device__ float  g_coef[128];   // [0:50) scaling, [50:100) wavelet, [100:104) scales

// ---------------- mma / async helpers ----------------
__device__ __forceinline__ void mma16816(float& c0, float& c1, float& c2, float& c3,
                                         uint32_t a0, uint32_t a1, uint32_t a2, uint32_t a3,
                                         uint32_t b0, uint32_t b1) {
    asm volatile("mma.sync.aligned.m16n8k16.row.col.f32.f16.f16.f32 "
                 "{%0,%1,%2,%3}, {%4,%5,%6,%7}, {%8,%9}, {%0,%1,%2,%3};\n"
                 : "+f"(c0), "+f"(c1), "+f"(c2), "+f"(c3)
                 : "r"(a0), "r"(a1), "r"(a2), "r"(a3), "r"(b0), "r"(b1));
}

__device__ __forceinline__ void cp16(uint32_t dst, const void* src) {
    asm volatile("cp.async.cg.shared.global [%0], [%1], 16;\n" :: "r"(dst), "l"(src));
}
__device__ __forceinline__ void cp_commit() {
    asm volatile("cp.async.commit_group;\n");
}
__device__ __forceinline__ void cp_wait_all() {
    asm volatile("cp.async.wait_group 0;\n");
}

__device__ __forceinline__ uint32_t packh2(__half a, __half b) {
    __half2 t = __halves2half2(a, b);     // a -> low half
    return *reinterpret_cast<uint32_t*>(&t);
}

// split x into hi (fp16) and lo (fp16 of remainder)
__device__ __forceinline__ void hsplit(float x, __half& h, __half& l) {
    h = __float2half_rn(x);
    l = __float2half_rn(x - __half2float(h));
}

__device__ __forceinline__ void packsplit2h(float x, float y, uint32_t& hi, uint32_t& lo) {
    __half xh, xl, yh, yl;
    hsplit(x, xh, xl);
    hsplit(y, yh, yl);
    hi = packh2(xh, yh);
    lo = packh2(xl, yl);
}

__device__ __forceinline__ uint32_t pack2f(float x, float y) {
    __half2 t = __floats2half2_rn(x, y);  // x -> low
    return *reinterpret_cast<uint32_t*>(&t);
}

// ============================================================================
// W-prep: build fragment-ordered fp16 hi/lo images for all 6 [128,128] weights.
// Image layout: g_wf[img*4096 + (nt*8+ks)*32 + lane] = {bh0, bh1, bl0, bl1}
// grid = (16, 6), 256 threads.
// ============================================================================
__global__ void __launch_bounds__(256) k_wprep(const float* __restrict__ inW,
                                               const float* __restrict__ outW,
                                               const float* __restrict__ f1W,
                                               const float* __restrict__ f2W) {
    const int tid  = threadIdx.x;
    const int lane = tid & 31;
    const int g    = lane >> 2;
    const int t4   = lane & 3;
    const int wid  = blockIdx.x * 8 + (tid >> 5);   // fragment id 0..127
    const int nt   = wid >> 3;
    const int ks   = wid & 7;

    const float* W; int ldw, c0;
    switch (blockIdx.y) {
        case 0:  W = inW;  ldw = 384; c0 = 0;   break;
        case 1:  W = inW;  ldw = 384; c0 = 128; break;
        case 2:  W = inW;  ldw = 384; c0 = 256; break;
        case 3:  W = outW; ldw = 128; c0 = 0;   break;
        case 4:  W = f1W;  ldw = 128; c0 = 0;   break;
        default: W = f2W;  ldw = 128; c0 = 0;   break;
    }

    const int n  = nt * 8 + g;
    const int k0 = ks * 16 + 2 * t4;
    float w00 = W[(k0    ) * ldw + c0 + n];
    float w01 = W[(k0 + 1) * ldw + c0 + n];
    float w80 = W[(k0 + 8) * ldw + c0 + n];
    float w81 = W[(k0 + 9) * ldw + c0 + n];
    __half h00, l00, h01, l01, h80, l80, h81, l81;
    hsplit(w00, h00, l00);  hsplit(w01, h01, l01);
    hsplit(w80, h80, l80);  hsplit(w81, h81, l81);
    uint4 f;
    f.x = packh2(h00, h01);
    f.y = packh2(h80, h81);
    f.z = packh2(l00, l01);
    f.w = packh2(l80, l81);
    g_wf[blockIdx.y * 4096 + wid * 32 + lane] = f;
}

// ============================================================================
// MMA GEMM: C[:, c0:c0+128] = act( LN?(A)[4096,128] @ Wimg + bias ) (+ R)
// grid = (128, MULTI?3:1), 256 threads (8 warps). 32 rows per block.
// Warp w: m-tile (w&1), n-chunk (w>>2 ... w>>1) of 32 cols (4 n-tiles).
// ============================================================================
template <int ACT, int RESID, int LNORM, int MULTI>
__global__ void __launch_bounds__(256) k_gemm_mma(const float* __restrict__ A,
                                                  int img0,
                                                  const float* __restrict__ bias,
                                                  const float* __restrict__ R,
                                                  float* __restrict__ C,
                                                  int outStride,
                                                  const float* __restrict__ lng,
                                                  const float* __restrict__ lnb) {
    __shared__ __align__(16) __half Ahi[32 * 136];
    __shared__ __align__(16) __half Alo[32 * 136];
    const int tid = threadIdx.x;
    const int m0  = blockIdx.x * 32;
    const int c0  = MULTI ? blockIdx.y * 128 : 0;
    const int img = img0 + (MULTI ? blockIdx.y : 0);

    // ---- stage A tile (optional LN), fp16 hi/lo ----
    {
        const int r = tid >> 3, l8 = tid & 7;
        float x[16];
        const float4* ap = reinterpret_cast<const float4*>(A + (m0 + r) * HID + l8 * 16);
#pragma unroll
        for (int j = 0; j < 4; j++) {
            float4 v = ap[j];
            x[j * 4 + 0] = v.x; x[j * 4 + 1] = v.y;
            x[j * 4 + 2] = v.z; x[j * 4 + 3] = v.w;
        }
        if (LNORM) {
            float s = 0.0f, s2 = 0.0f;
#pragma unroll
            for (int j = 0; j < 16; j++) { s += x[j]; s2 += x[j] * x[j]; }
#pragma unroll
            for (int o = 4; o; o >>= 1) {
                s  += __shfl_xor_sync(0xffffffffu, s,  o);
                s2 += __shfl_xor_sync(0xffffffffu, s2, o);
            }
            float mean = s * (1.0f / HID);
            float rstd = rsqrtf(s2 * (1.0f / HID) - mean * mean + 1e-5f);
#pragma unroll
            for (int j = 0; j < 16; j++) {
                int col = l8 * 16 + j;
                x[j] = (x[j] - mean) * rstd * lng[col] + lnb[col];
            }
        }
        uint32_t phi[8], plo[8];
#pragma unroll
        for (int j = 0; j < 8; j++) {
            __half h0, l0, h1, l1;
            hsplit(x[2 * j],     h0, l0);
            hsplit(x[2 * j + 1], h1, l1);
            phi[j] = packh2(h0, h1);
            plo[j] = packh2(l0, l1);
        }
        uint4* dhi = reinterpret_cast<uint4*>(&Ahi[r * 136 + l8 * 16]);
        uint4* dlo = reinterpret_cast<uint4*>(&Alo[r * 136 + l8 * 16]);
        dhi[0] = make_uint4(phi[0], phi[1], phi[2], phi[3]);
        dhi[1] = make_uint4(phi[4], phi[5], phi[6], phi[7]);
        dlo[0] = make_uint4(plo[0], plo[1], plo[2], plo[3]);
        dlo[1] = make_uint4(plo[4], plo[5], plo[6], plo[7]);
    }
    __syncthreads();

    // ---- main MMA loop ----
    const int warp = tid >> 5, lane = tid & 31;
    const int g = lane >> 2, t4 = lane & 3;
    const int mt = warp & 1, ch = warp >> 1;
    const uint4* img_p = &g_wf[(size_t)img * 4096];

    float acc[4][4];
#pragma unroll
    for (int nt = 0; nt < 4; nt++)
#pragma unroll
        for (int i = 0; i < 4; i++) acc[nt][i] = 0.0f;

    const __half* ahb = &Ahi[(mt * 16 + g) * 136];
    const __half* alb = &Alo[(mt * 16 + g) * 136];

#pragma unroll
    for (int ks = 0; ks < 8; ks++) {
        const int co = ks * 16 + 2 * t4;
        uint32_t ah0 = *reinterpret_cast<const uint32_t*>(&ahb[co]);
        uint32_t ah1 = *reinterpret_cast<const uint32_t*>(&ahb[8 * 136 + co]);
        uint32_t ah2 = *reinterpret_cast<const uint32_t*>(&ahb[co + 8]);
        uint32_t ah3 = *reinterpret_cast<const uint32_t*>(&ahb[8 * 136 + co + 8]);
        uint32_t al0 = *reinterpret_cast<const uint32_t*>(&alb[co]);
        uint32_t al1 = *reinterpret_cast<const uint32_t*>(&alb[8 * 136 + co]);
        uint32_t al2 = *reinterpret_cast<const uint32_t*>(&alb[co + 8]);
        uint32_t al3 = *reinterpret_cast<const uint32_t*>(&alb[8 * 136 + co + 8]);
#pragma unroll
        for (int nt = 0; nt < 4; nt++) {
            uint4 f = img_p[((4 * ch + nt) * 8 + ks) * 32 + lane];
            mma16816(acc[nt][0], acc[nt][1], acc[nt][2], acc[nt][3],
                     ah0, ah1, ah2, ah3, f.x, f.y);
            mma16816(acc[nt][0], acc[nt][1], acc[nt][2], acc[nt][3],
                     al0, al1, al2, al3, f.x, f.y);
            mma16816(acc[nt][0], acc[nt][1], acc[nt][2], acc[nt][3],
                     ah0, ah1, ah2, ah3, f.z, f.w);
        }
    }

    // ---- epilogue ----
#pragma unroll
    for (int nt = 0; nt < 4; nt++) {
        const int ncol = c0 + (4 * ch + nt) * 8 + 2 * t4;
        const int row0 = m0 + mt * 16 + g, row1 = row0 + 8;
        float b0 = bias[ncol], b1 = bias[ncol + 1];
        float v00 = acc[nt][0] + b0, v01 = acc[nt][1] + b1;
        float v10 = acc[nt][2] + b0, v11 = acc[nt][3] + b1;
        if (ACT == 1) {
            const float k = 0.70710678118654752f;
            v00 = 0.5f * v00 * (1.0f + erff(v00 * k));
            v01 = 0.5f * v01 * (1.0f + erff(v01 * k));
            v10 = 0.5f * v10 * (1.0f + erff(v10 * k));
            v11 = 0.5f * v11 * (1.0f + erff(v11 * k));
        }
        if (RESID) {
            v00 += R[row0 * HID + ncol];  v01 += R[row0 * HID + ncol + 1];
            v10 += R[row1 * HID + ncol];  v11 += R[row1 * HID + ncol + 1];
        }
        C[row0 * outStride + ncol]     = v00;
        C[row0 * outStride + ncol + 1] = v01;
        C[row1 * outStride + ncol]     = v10;
        C[row1 * outStride + ncol + 1] = v11;
    }
}

// ============================================================================
// K1: sine encoding + GEMM  ->  g_eig = eeig[S,129] @ W[129,128] + b
// 16 rows per block, 128 threads; sincosf fuses sin/cos of the same argument.
// ============================================================================
__global__ void __launch_bounds__(128) k_sine_enc(const float* __restrict__ eve,
                                                  const float* __restrict__ W,
                                                  const float* __restrict__ b) {
    __shared__ float ee[16][132];   // 129 used
    const int m0  = blockIdx.x * 16;
    const int tid = threadIdx.x;
    const float kLog = -9.210340371976184f / 128.0f;   // -ln(1e4)/128

    for (int idx = tid; idx < 16 * 64; idx += 128) {
        int r = idx >> 6, i = idx & 63;
        float e  = eve[m0 + r];
        float pe = e * 100.0f * __expf((2.0f * i) * kLog);
        float sv, cv;
        sincosf(pe, &sv, &cv);
        ee[r][1 + i]  = sv;
        ee[r][65 + i] = cv;
    }
    if (tid < 16) ee[tid][0] = eve[m0 + tid];
    __syncthreads();

    float acc[16];
#pragma unroll
    for (int r = 0; r < 16; r++) acc[r] = 0.0f;

    for (int k = 0; k < 129; k++) {
        float wv = W[k * HID + tid];
#pragma unroll
        for (int r = 0; r < 16; r++) acc[r] = fmaf(ee[r][k], wv, acc[r]);
    }
    float bb = b[tid];
#pragma unroll
    for (int r = 0; r < 16; r++) g_eig[(m0 + r) * HID + tid] = acc[r] + bb;
}

// ============================================================================
// K-prep: build per-(head, 64-key tile) smem-image of K (hi) and V^T (hi/lo)
// grid = (S/KT, NHEADS), 256 threads.
// ============================================================================
__global__ void __launch_bounds__(256) k_prep(const float* __restrict__ qkv) {
    __shared__ __align__(16) __half img[TILE_H];
    const int tid = threadIdx.x;
    const int kb  = blockIdx.x * KT;
    const int h   = blockIdx.y;

    for (int i = tid; i < KT * HD; i += 256) {
        int key = i >> 5, d = i & 31;
        const float* base = qkv + (size_t)(kb + key) * 384 + h * HD + d;
        float kx = base[128];
        float vx = base[256];
        __half vh, vl;
        hsplit(vx, vh, vl);
        img[key * KROW + d] = __float2half_rn(kx);
        img[KIMG + d * VROW + key]      = vh;
        img[KIMG + d * VROW + 64 + key] = vl;
    }
    __syncthreads();

    uint4* dst = reinterpret_cast<uint4*>(g_kv + (size_t)(h * (S / KT) + blockIdx.x) * TILE_H);
    const uint4* src = reinterpret_cast<const uint4*>(img);
    for (int i = tid; i < TILE_U4; i += 256) dst[i] = src[i];
}

// ============================================================================
// K4a: MMA flash attention partial (fp16; exact-Q x Khi QK, PV 2-term).
// cp.async double-buffered tile staging.
// grid = (S/QT, NHEADS, NKC), block = 256 (8 warps x 16 queries).
// ============================================================================
__global__ void __launch_bounds__(256, 3) k_attn_mma(const float* __restrict__ qkv,
                                                     const int* __restrict__ snp) {
    __shared__ __align__(16) __half tile[2][TILE_H];

    const int tid  = threadIdx.x;
    const int warp = tid >> 5;
    const int lane = tid & 31;
    const int g    = lane >> 2;    // group (row within fragment)
    const int t4   = lane & 3;     // thread-in-group
    const int h    = blockIdx.y;
    const int kc   = blockIdx.z;
    const int sn   = *snp;
    const float scale = 0.17677669529663687f;   // 1/sqrt(32)

    const int qbase = blockIdx.x * QT + warp * 16;
    const int r0 = qbase + g;        // query rows owned by this thread
    const int r1 = r0 + 8;

    const uint32_t sm0 = (uint32_t)__cvta_generic_to_shared(&tile[0][0]);
    const uint32_t sm1 = (uint32_t)__cvta_generic_to_shared(&tile[1][0]);

    // ---- load Q fragments (2 k-steps), split hi/lo fp16 ----
    uint32_t Qhi[2][4], Qlo[2][4];
#pragma unroll
    for (int ks = 0; ks < 2; ks++) {
#pragma unroll
        for (int hh = 0; hh < 2; hh++) {     // k-half (+0 / +8)
#pragma unroll
            for (int rr = 0; rr < 2; rr++) { // row g / g+8
                int row = rr ? r1 : r0;
                int d0  = ks * 16 + hh * 8 + 2 * t4;
                float x0 = qkv[row * 384 + h * HD + d0]     * scale;
                float x1 = qkv[row * 384 + h * HD + d0 + 1] * scale;
                int ri = hh * 2 + rr;
                packsplit2h(x0, x1, Qhi[ks][ri], Qlo[ks][ri]);
            }
        }
    }

    float O[4][4];                    // [d-tile][frag] fp32 accumulators
#pragma unroll
    for (int nt = 0; nt < 4; nt++)
#pragma unroll
        for (int i = 0; i < 4; i++) O[nt][i] = 0.0f;
    float m0v = -INFINITY, m1v = -INFINITY, l0v = 0.0f, l1v = 0.0f;

    const int tile0 = (kc * CHUNK) >> 6;    // first tile index in this chunk

    // prefetch tile 0 into buffer 0
    {
        const uint4* src = reinterpret_cast<const uint4*>(
            g_kv + (size_t)(h * (S / KT) + tile0) * TILE_H);
        for (int i = tid; i < TILE_U4; i += 256)
            cp16(sm0 + i * 16, src + i);
        cp_commit();
    }

    for (int it = 0; it < NT_CH; it++) {
        cp_wait_all();
        __syncthreads();

        // prefetch next tile into the other buffer (overlaps compute below)
        if (it + 1 < NT_CH) {
            const uint4* src = reinterpret_cast<const uint4*>(
                g_kv + (size_t)(h * (S / KT) + tile0 + it + 1) * TILE_H);
            uint32_t dstb = ((it + 1) & 1) ? sm1 : sm0;
            for (int i = tid; i < TILE_U4; i += 256)
                cp16(dstb + i * 16, src + i);
            cp_commit();
        }

        const __half* tl = tile[it & 1];
        const int kb = kc * CHUNK + it * KT;

        // ---- QK^T: 8 n-tiles of 8 keys; exact-Q (hi+lo) x Khi ----
        float Sf[8][4];
#pragma unroll
        for (int nt = 0; nt < 8; nt++) {
#pragma unroll
            for (int i = 0; i < 4; i++) Sf[nt][i] = 0.0f;
            int key = nt * 8 + g;
            const __half* krow = &tl[key * KROW];
#pragma unroll
            for (int ks = 0; ks < 2; ks++) {
                uint32_t bh0 = *reinterpret_cast<const uint32_t*>(&krow[ks * 16 + 2 * t4]);
                uint32_t bh1 = *reinterpret_cast<const uint32_t*>(&krow[ks * 16 + 8 + 2 * t4]);
                mma16816(Sf[nt][0], Sf[nt][1], Sf[nt][2], Sf[nt][3],
                         Qhi[ks][0], Qhi[ks][1], Qhi[ks][2], Qhi[ks][3], bh0, bh1);
                mma16816(Sf[nt][0], Sf[nt][1], Sf[nt][2], Sf[nt][3],
                         Qlo[ks][0], Qlo[ks][1], Qlo[ks][2], Qlo[ks][3], bh0, bh1);
            }
        }

        // ---- mask ----
        if (kb + KT > sn) {
#pragma unroll
            for (int nt = 0; nt < 8; nt++) {
                int k0 = kb + nt * 8 + 2 * t4;
                if (k0     >= sn) { Sf[nt][0] = -INFINITY; Sf[nt][2] = -INFINITY; }
                if (k0 + 1 >= sn) { Sf[nt][1] = -INFINITY; Sf[nt][3] = -INFINITY; }
            }
        }

        // ---- online softmax ----
        float mx0 = -INFINITY, mx1 = -INFINITY;
#pragma unroll
        for (int nt = 0; nt < 8; nt++) {
            mx0 = fmaxf(mx0, fmaxf(Sf[nt][0], Sf[nt][1]));
            mx1 = fmaxf(mx1, fmaxf(Sf[nt][2], Sf[nt][3]));
        }
#pragma unroll
        for (int o = 1; o <= 2; o <<= 1) {
            mx0 = fmaxf(mx0, __shfl_xor_sync(0xffffffffu, mx0, o));
            mx1 = fmaxf(mx1, __shfl_xor_sync(0xffffffffu, mx1, o));
        }
        float mn0 = fmaxf(m0v, mx0);
        float mn1 = fmaxf(m1v, mx1);
        if (mn0 == -INFINITY) mn0 = 0.0f;   // fully-masked guard
        if (mn1 == -INFINITY) mn1 = 0.0f;
        float c0 = __expf(m0v - mn0);
        float c1 = __expf(m1v - mn1);
        l0v *= c0;  l1v *= c1;
#pragma unroll
        for (int nt = 0; nt < 4; nt++) {
            O[nt][0] *= c0; O[nt][1] *= c0;
            O[nt][2] *= c1; O[nt][3] *= c1;
        }
        m0v = mn0; m1v = mn1;

        float rs0 = 0.0f, rs1 = 0.0f;
        uint32_t Ph[4][4];               // single fp16 P fragments
#pragma unroll
        for (int j = 0; j < 4; j++) {    // key-step j covers tiles 2j, 2j+1
#pragma unroll
            for (int tt = 0; tt < 2; tt++) {
                int nt = 2 * j + tt;
                float p0 = __expf(Sf[nt][0] - mn0);
                float p1 = __expf(Sf[nt][1] - mn0);
                float p2 = __expf(Sf[nt][2] - mn1);
                float p3 = __expf(Sf[nt][3] - mn1);
                rs0 += p0 + p1;
                rs1 += p2 + p3;
                Ph[j][tt * 2]     = pack2f(p0, p1);
                Ph[j][tt * 2 + 1] = pack2f(p2, p3);
            }
        }
#pragma unroll
        for (int o = 1; o <= 2; o <<= 1) {
            rs0 += __shfl_xor_sync(0xffffffffu, rs0, o);
            rs1 += __shfl_xor_sync(0xffffffffu, rs1, o);
        }
        l0v += rs0;  l1v += rs1;

        // ---- PV: 4 d-tiles x 4 key-steps, 2-term (P fp16, V hi/lo) ----
#pragma unroll
        for (int nt = 0; nt < 4; nt++) {
            int d = nt * 8 + g;
            const __half* vrow = &tl[KIMG + d * VROW];
#pragma unroll
            for (int ks = 0; ks < 4; ks++) {
                uint32_t bh0 = *reinterpret_cast<const uint32_t*>(&vrow[ks * 16 + 2 * t4]);
                uint32_t bh1 = *reinterpret_cast<const uint32_t*>(&vrow[ks * 16 + 8 + 2 * t4]);
                uint32_t bl0 = *reinterpret_cast<const uint32_t*>(&vrow[64 + ks * 16 + 2 * t4]);
                uint32_t bl1 = *reinterpret_cast<const uint32_t*>(&vrow[64 + ks * 16 + 8 + 2 * t4]);
                mma16816(O[nt][0], O[nt][1], O[nt][2], O[nt][3],
                         Ph[ks][0], Ph[ks][1], Ph[ks][2], Ph[ks][3], bh0, bh1);
                mma16816(O[nt][0], O[nt][1], O[nt][2], O[nt][3],
                         Ph[ks][0], Ph[ks][1], Ph[ks][2], Ph[ks][3], bl0, bl1);
            }
        }
        __syncthreads();
    }

    // ---- write partials (unnormalized) ----
    const int p0 = (h * NKC + kc) * S + r0;
    const int p1 = (h * NKC + kc) * S + r1;
    if (t4 == 0) {
        g_pm[p0] = m0v;  g_pl[p0] = l0v;
        g_pm[p1] = m1v;  g_pl[p1] = l1v;
    }
#pragma unroll
    for (int nt = 0; nt < 4; nt++) {
        int d = nt * 8 + 2 * t4;
        g_po[(size_t)p0 * HD + d]     = O[nt][0];
        g_po[(size_t)p0 * HD + d + 1] = O[nt][1];
        g_po[(size_t)p1 * HD + d]     = O[nt][2];
        g_po[(size_t)p1 * HD + d + 1] = O[nt][3];
    }
}

// ============================================================================
// K4b: split-K combine. grid = (S/128, NHEADS, 4 d-quarters), 128 threads.
// ============================================================================
__global__ void __launch_bounds__(128) k_attn_comb(void) {
    const int h  = blockIdx.y;
    const int q  = blockIdx.x * 128 + threadIdx.x;
    const int dq = blockIdx.z * 8;

    float M = -INFINITY;
#pragma unroll
    for (int kc = 0; kc < NKC; kc++)
        M = fmaxf(M, g_pm[(h * NKC + kc) * S + q]);

    float L = 0.0f;
    float o[8];
#pragma unroll
    for (int d = 0; d < 8; d++) o[d] = 0.0f;

#pragma unroll
    for (int kc = 0; kc < NKC; kc++) {
        const int p = (h * NKC + kc) * S + q;
        float li = g_pl[p];
        if (li > 0.0f) {
            float w = __expf(g_pm[p] - M);
            L += li * w;
            const float4* po = reinterpret_cast<const float4*>(&g_po[(size_t)p * HD + dq]);
            float4 v0 = po[0], v1 = po[1];
            o[0] = fmaf(w, v0.x, o[0]);  o[1] = fmaf(w, v0.y, o[1]);
            o[2] = fmaf(w, v0.z, o[2]);  o[3] = fmaf(w, v0.w, o[3]);
            o[4] = fmaf(w, v1.x, o[4]);  o[5] = fmaf(w, v1.y, o[5]);
            o[6] = fmaf(w, v1.z, o[6]);  o[7] = fmaf(w, v1.w, o[7]);
        }
    }

    float inv = (L > 0.0f) ? 1.0f / L : 0.0f;
    float* dst = &g_att[q * HID + h * HD + dq];
#pragma unroll
    for (int d = 0; d < 8; d++) dst[d] = o[d] * inv;
}

// ============================================================================
// masked row-sum of eig_filter (double accumulation, 2 chains)
// ============================================================================
__global__ void k_zero_xsum() {
    g_xsum[threadIdx.x] = 0.0;
}

__global__ void __launch_bounds__(128) k_rowsum(const int* __restrict__ snp) {
    const int sn  = *snp;
    const int tid = threadIdx.x;
    const int m0  = blockIdx.x * 128;
    double a0 = 0.0, a1 = 0.0;
    for (int r = 0; r < 128; r += 2) {
        int row = m0 + r;
        if (row < sn)     a0 += (double)g_eigf[row * HID + tid];
        if (row + 1 < sn) a1 += (double)g_eigf[(row + 1) * HID + tid];
    }
    atomicAdd(&g_xsum[tid], a0 + a1);
}

// ============================================================================
// pooled coefficients (single block)
// ============================================================================
__global__ void __launch_bounds__(128) k_pool(const float* __restrict__ dscW, const float* __restrict__ dscb,
                                              const float* __restrict__ dwvW, const float* __restrict__ dwvb,
                                              const float* __restrict__ dssW, const float* __restrict__ dssb,
                                              const int* __restrict__ lenp, const int* __restrict__ snp) {
    const int tid = threadIdx.x;
    __shared__ float sig[104];
    __shared__ float ssum[2];
    const float lenf = (float)(*lenp);
    const float snf  = (float)(*snp);

    if (tid < 104) {
        const float* W; const float* bb; int c; int NCc;
        if (tid < 50)       { W = dscW; bb = dscb; c = tid;       NCc = NCOE; }
        else if (tid < 100) { W = dwvW; bb = dwvb; c = tid - 50;  NCc = NCOE; }
        else                { W = dssW; bb = dssb; c = tid - 100; NCc = NSCALES; }
        double acc = 0.0;
        for (int k = 0; k < HID; k++) acc += g_xsum[k] * (double)W[k * NCc + c];
        float pooled = (float)((acc + (double)(snf * bb[c])) / (double)(lenf + 1e-8f));
        sig[tid] = 1.0f / (1.0f + expf(-pooled));
    }
    __syncthreads();
    if (tid == 0) { float t = 0.f; for (int i = 0;  i < 50;  i++) t += sig[i]; ssum[0] = t; }
    if (tid == 1) { float t = 0.f; for (int i = 50; i < 100; i++) t += sig[i]; ssum[1] = t; }
    __syncthreads();
    if (tid < 50)       g_coef[tid] = sig[tid] / (ssum[0] + 1e-8f);
    else if (tid < 100) g_coef[tid] = sig[tid] / (ssum[1] + 1e-8f);
    else if (tid < 104) g_coef[tid] = sig[tid] * 5.0f;   // THRE
}

// ============================================================================
// Chebyshev synthesis + L2 normalize  ->  out[S, 5]
// ============================================================================
__global__ void __launch_bounds__(128) k_final(const float* __restrict__ eve,
                                               float* __restrict__ out) {
    __shared__ float cs[NCOE], cw[NCOE], sc[NSCALES];
    const int tid = threadIdx.x;
    if (tid < 50)        cs[tid]       = g_coef[tid];
    else if (tid < 100)  cw[tid - 50]  = g_coef[tid];
    else if (tid < 104)  sc[tid - 100] = g_coef[tid];
    __syncthreads();

    const int s = blockIdx.x * 128 + tid;
    const float e = eve[s];
    float vals[5];

    {   // scaling channel: y = e - 1; coefficients on T_1,T_3,...
        float y  = e - 1.0f;
        float te = 1.0f, to = y;
        float acc = cs[0] * (0.5f * (1.0f - to));
#pragma unroll
        for (int c = 1; c < NCOE; c++) {
            te = 2.0f * y * to - te;          // T_{2c}
            to = 2.0f * y * te - to;          // T_{2c+1}
            acc += cs[c] * (0.5f * (1.0f - to));
        }
        vals[0] = acc;
    }

#pragma unroll
    for (int j = 0; j < NSCALES; j++) {       // wavelet channels: T_0,T_2,...
        float f = e * sc[j];
        if (f > 2.0f) f = 0.0f;
        float y  = f - 1.0f;
        float te = 1.0f, to = y;
        float acc = 0.0f;                      // cw[0] * 0.5*(1-T_0) = 0
#pragma unroll
        for (int c = 1; c < NCOE; c++) {
            te = 2.0f * y * to - te;          // T_{2c}
            acc += cw[c] * (0.5f * (1.0f - te));
            to = 2.0f * y * te - to;          // T_{2c+1}
        }
        vals[1 + j] = acc;
    }

    float n2 = 0.0f;
#pragma unroll
    for (int i = 0; i < 5; i++) n2 += vals[i] * vals[i];
    float inv = 1.0f / (sqrtf(n2) + 1e-8f);
#pragma unroll
    for (int i = 0; i < 5; i++) out[s * 5 + i] = vals[i] * inv;
}

// ============================================================================
// launch
// ============================================================================
extern "C" void kernel_launch(void* const* d_in, const int* in_sizes, int n_in,
                              void* d_out, int out_size) {
    const float* eve      = (const float*)d_in[0];
    const int*   lenp     = (const int*)  d_in[1];
    const int*   snp      = (const int*)  d_in[2];
    const float* eig_w_W  = (const float*)d_in[3];
    const float* eig_w_b  = (const float*)d_in[4];
    const float* mha_ln_g = (const float*)d_in[5];
    const float* mha_ln_b = (const float*)d_in[6];
    const float* in_W     = (const float*)d_in[7];
    const float* in_b     = (const float*)d_in[8];
    const float* out_W    = (const float*)d_in[9];
    const float* out_b    = (const float*)d_in[10];
    const float* ffn_ln_g = (const float*)d_in[11];
    const float* ffn_ln_b = (const float*)d_in[12];
    const float* ffn1_W   = (const float*)d_in[13];
    const float* ffn1_b   = (const float*)d_in[14];
    const float* ffn2_W   = (const float*)d_in[15];
    const float* ffn2_b   = (const float*)d_in[16];
    const float* dsc_W    = (const float*)d_in[17];
    const float* dsc_b    = (const float*)d_in[18];
    const float* dwv_W    = (const float*)d_in[19];
    const float* dwv_b    = (const float*)d_in[20];
    const float* dss_W    = (const float*)d_in[21];
    const float* dss_b    = (const float*)d_in[22];
    float* out = (float*)d_out;

    float *p_eig, *p_qkv, *p_att, *p_h1, *p_eigf;
    cudaGetSymbolAddress((void**)&p_eig,  g_eig);
    cudaGetSymbolAddress((void**)&p_qkv,  g_qkv);
    cudaGetSymbolAddress((void**)&p_att,  g_att);
    cudaGetSymbolAddress((void**)&p_h1,   g_h1);
    cudaGetSymbolAddress((void**)&p_eigf, g_eigf);

    // 0) weight images (independent of activations)
    k_wprep<<<dim3(16, 6), 256>>>(in_W, out_W, ffn1_W, ffn2_W);
    // 1) eig = sine_encoding(eve) @ W + b
    k_sine_enc<<<S / 16, 128>>>(eve, eig_w_W, eig_w_b);
    // 2) qkv = LN(eig) @ in_W + in_b   (MMA, 3 column-blocks via grid.y)
    k_gemm_mma<0, 0, 1, 1><<<dim3(128, 3), 256>>>(p_eig, 0, in_b, nullptr, p_qkv, 384, mha_ln_g, mha_ln_b);
    // 3) pre-swizzle K/V tiles to fp16 images
    k_prep<<<dim3(S / KT, NHEADS), 256>>>(p_qkv);
    // 4) attention (tensor-core split-K partials + combine)
    k_attn_mma<<<dim3(S / QT, NHEADS, NKC), 256>>>(p_qkv, snp);
    k_attn_comb<<<dim3(S / 128, NHEADS, 4), 128>>>();
    // 5) eig = eig + att @ out_W + out_b
    k_gemm_mma<0, 1, 0, 0><<<dim3(128), 256>>>(p_att, 3, out_b, p_eig, p_eig, 128, nullptr, nullptr);
    // 6) h1 = gelu(LN(eig) @ ffn1_W + b)
    k_gemm_mma<1, 0, 1, 0><<<dim3(128), 256>>>(p_eig, 4, ffn1_b, nullptr, p_h1, 128, ffn_ln_g, ffn_ln_b);
    // 7) eigf = eig + h1 @ ffn2_W + b
    k_gemm_mma<0, 1, 0, 0><<<dim3(128), 256>>>(p_h1, 5, ffn2_b, p_eig, p_eigf, 128, nullptr, nullptr);
    // 8) masked row-sum (double)
    k_zero_xsum<<<1, 128>>>();
    k_rowsum<<<S / 128, 128>>>(snp);
    // 9) pooled coefficients
    k_pool<<<1, 128>>>(dsc_W, dsc_b, dwv_W, dwv_b, dss_W, dss_b, lenp, snp);
    // 10) Chebyshev synthesis + normalize
    k_final<<<S / 128, 128>>>(eve, out);
}

// round 11
// speedup vs baseline: 2.1824x; 1.1225x over previous
#include <cuda_runtime.h>
#include <cuda_fp16.h>
#include <math.h>
#include <stdint.h>

// ---------------- problem constants ----------------
#define S 4096
#define HID 128
#define NHEADS 4
#define HD 32
#define NCOE 50
#define NSCALES 4
#define NKC 4              // split-K chunks for attention
#define CHUNK (S / NKC)    // 1024 keys per chunk
#define QT 128             // queries per block (8 warps x 16)
#define KT 64              // key tile
#define NT_CH (CHUNK / KT) // 16 tiles per chunk

// KV tile image geometry (halves). Padded rows for conflict-free LDS.
#define KROW 40                      // per-key: 32 hi + 8 pad
#define KIMG (KT * KROW)             // 2560 halves
#define VROW 72                      // per-dim: 64 keys + 8 pad
#define VIMG (40 * VROW)             // rows 0..31 = V, 32 = ones, 33..39 = zero pad
#define TILE_H (KIMG + VIMG)         // 5440 halves = 10880 B
#define TILE_U4 (TILE_H / 8)         // 680 uint4

// log2(e)/sqrt(32): scores come out of QK in log2 domain
#define QSCALE 0.2550458572864341f

// ---------------- scratch (__device__ globals; no allocs allowed) ----------------
__device__ float  g_eig [S * HID];
__device__ float  g_qkv [S * 3 * HID];
__device__ float  g_h1  [S * HID];
__device__ __align__(16) __half g_kv[NHEADS * (S / KT) * TILE_H];  // pre-swizzled K/V tiles
__device__ __align__(16) uint4  g_wf[6 * 4096];   // 6 weight images, fragment-ordered
__device__ float  g_pm  [NHEADS * NKC * S];        // partial max (log2 domain)
__device__ float  g_pl  [NHEADS * NKC * S];        // partial sum
__device__ float  g_po  [NHEADS * NKC * S * HD];   // partial (unnormalized) out
__device__ double g_xsum[HID];
__device__ float  g_coef[128];   // [0:50) scaling, [50:100) wavelet, [100:104) scales

// ---------------- mma / async helpers ----------------
__device__ __forceinline__ void mma16816(float& c0, float& c1, float& c2, float& c3,
                                         uint32_t a0, uint32_t a1, uint32_t a2, uint32_t a3,
                                         uint32_t b0, uint32_t b1) {
    asm volatile("mma.sync.aligned.m16n8k16.row.col.f32.f16.f16.f32 "
                 "{%0,%1,%2,%3}, {%4,%5,%6,%7}, {%8,%9}, {%0,%1,%2,%3};\n"
                 : "+f"(c0), "+f"(c1), "+f"(c2), "+f"(c3)
                 : "r"(a0), "r"(a1), "r"(a2), "r"(a3), "r"(b0), "r"(b1));
}

__device__ __forceinline__ void cp16(uint32_t dst, const void* src) {
    asm volatile("cp.async.cg.shared.global [%0], [%1], 16;\n" :: "r"(dst), "l"(src));
}
__device__ __forceinline__ void cp_commit() {
    asm volatile("cp.async.commit_group;\n");
}
__device__ __forceinline__ void cp_wait_all() {
    asm volatile("cp.async.wait_group 0;\n");
}

__device__ __forceinline__ uint32_t packh2(__half a, __half b) {
    __half2 t = __halves2half2(a, b);     // a -> low half
    return *reinterpret_cast<uint32_t*>(&t);
}

// split x into hi (fp16) and lo (fp16 of remainder)
__device__ __forceinline__ void hsplit(float x, __half& h, __half& l) {
    h = __float2half_rn(x);
    l = __float2half_rn(x - __half2float(h));
}

__device__ __forceinline__ void packsplit2h(float x, float y, uint32_t& hi, uint32_t& lo) {
    __half xh, xl, yh, yl;
    hsplit(x, xh, xl);
    hsplit(y, yh, yl);
    hi = packh2(xh, yh);
    lo = packh2(xl, yl);
}

// 2^a, 2^b as packed fp16x2 (one MUFU op for both lanes)
__device__ __forceinline__ uint32_t exp2h2(float a, float b) {
    __half2 t = __floats2half2_rn(a, b);   // a -> low half
    uint32_t hi = *reinterpret_cast<uint32_t*>(&t);
    uint32_t r;
    asm("ex2.approx.f16x2 %0, %1;" : "=r"(r) : "r"(hi));
    return r;
}

// ============================================================================
// W-prep: build fragment-ordered fp16 hi/lo images for all 6 [128,128] weights.
// Also zeroes g_xsum (runs first every launch).
// grid = (16, 6), 256 threads.
// ============================================================================
__global__ void __launch_bounds__(256) k_wprep(const float* __restrict__ inW,
                                               const float* __restrict__ outW,
                                               const float* __restrict__ f1W,
                                               const float* __restrict__ f2W) {
    const int tid  = threadIdx.x;
    if (blockIdx.x == 0 && blockIdx.y == 0 && tid < HID) g_xsum[tid] = 0.0;

    const int lane = tid & 31;
    const int g    = lane >> 2;
    const int t4   = lane & 3;
    const int wid  = blockIdx.x * 8 + (tid >> 5);   // fragment id 0..127
    const int nt   = wid >> 3;
    const int ks   = wid & 7;

    const float* W; int ldw, c0;
    switch (blockIdx.y) {
        case 0:  W = inW;  ldw = 384; c0 = 0;   break;
        case 1:  W = inW;  ldw = 384; c0 = 128; break;
        case 2:  W = inW;  ldw = 384; c0 = 256; break;
        case 3:  W = outW; ldw = 128; c0 = 0;   break;
        case 4:  W = f1W;  ldw = 128; c0 = 0;   break;
        default: W = f2W;  ldw = 128; c0 = 0;   break;
    }

    const int n  = nt * 8 + g;
    const int k0 = ks * 16 + 2 * t4;
    float w00 = W[(k0    ) * ldw + c0 + n];
    float w01 = W[(k0 + 1) * ldw + c0 + n];
    float w80 = W[(k0 + 8) * ldw + c0 + n];
    float w81 = W[(k0 + 9) * ldw + c0 + n];
    __half h00, l00, h01, l01, h80, l80, h81, l81;
    hsplit(w00, h00, l00);  hsplit(w01, h01, l01);
    hsplit(w80, h80, l80);  hsplit(w81, h81, l81);
    uint4 f;
    f.x = packh2(h00, h01);
    f.y = packh2(h80, h81);
    f.z = packh2(l00, l01);
    f.w = packh2(l80, l81);
    g_wf[blockIdx.y * 4096 + wid * 32 + lane] = f;
}

// ============================================================================
// MMA GEMM: C[:, c0:c0+128] = act( X @ Wimg + bias ) (+ R)
// X = A (optionally LayerNormed) or the split-K attention combine (COMB).
// SUMOUT: skip store; instead accumulate masked column sums into g_xsum.
// grid = (128, MULTI?3:1), 256 threads (8 warps). 32 rows per block.
// ============================================================================
template <int ACT, int RESID, int LNORM, int MULTI, int COMB, int SUMOUT>
__global__ void __launch_bounds__(256) k_gemm_mma(const float* __restrict__ A,
                                                  int img0,
                                                  const float* __restrict__ bias,
                                                  const float* __restrict__ R,
                                                  float* __restrict__ C,
                                                  int outStride,
                                                  const float* __restrict__ lng,
                                                  const float* __restrict__ lnb,
                                                  const int* __restrict__ snp) {
    __shared__ __align__(16) __half Ahi[32 * 136];
    __shared__ __align__(16) __half Alo[32 * 136];
    __shared__ float colsum[128];
    const int tid = threadIdx.x;
    const int m0  = blockIdx.x * 32;
    const int c0  = MULTI ? blockIdx.y * 128 : 0;
    const int img = img0 + (MULTI ? blockIdx.y : 0);

    // ---- stage X tile (plain / LN / attention-combine), fp16 hi/lo ----
    {
        const int r = tid >> 3, l8 = tid & 7;
        float x[16];
        if (COMB) {
            // split-K combine: head = l8>>1, dims (l8&1)*16 .. +16
            const int row    = m0 + r;
            const int head   = l8 >> 1;
            const int hd_off = (l8 & 1) * 16;
            float M = -INFINITY;
#pragma unroll
            for (int kc = 0; kc < NKC; kc++)
                M = fmaxf(M, g_pm[(head * NKC + kc) * S + row]);
#pragma unroll
            for (int j = 0; j < 16; j++) x[j] = 0.0f;
            float L = 0.0f;
#pragma unroll
            for (int kc = 0; kc < NKC; kc++) {
                const int p = (head * NKC + kc) * S + row;
                float li = g_pl[p];
                if (li > 0.0f) {
                    float w = exp2f(g_pm[p] - M);
                    L += li * w;
                    const float4* po = reinterpret_cast<const float4*>(&g_po[(size_t)p * HD + hd_off]);
#pragma unroll
                    for (int jj = 0; jj < 4; jj++) {
                        float4 v = po[jj];
                        x[jj * 4 + 0] = fmaf(w, v.x, x[jj * 4 + 0]);
                        x[jj * 4 + 1] = fmaf(w, v.y, x[jj * 4 + 1]);
                        x[jj * 4 + 2] = fmaf(w, v.z, x[jj * 4 + 2]);
                        x[jj * 4 + 3] = fmaf(w, v.w, x[jj * 4 + 3]);
                    }
                }
            }
            float inv = (L > 0.0f) ? 1.0f / L : 0.0f;
#pragma unroll
            for (int j = 0; j < 16; j++) x[j] *= inv;
        } else {
            const float4* ap = reinterpret_cast<const float4*>(A + (m0 + r) * HID + l8 * 16);
#pragma unroll
            for (int j = 0; j < 4; j++) {
                float4 v = ap[j];
                x[j * 4 + 0] = v.x; x[j * 4 + 1] = v.y;
                x[j * 4 + 2] = v.z; x[j * 4 + 3] = v.w;
            }
        }
        if (LNORM) {
            float s = 0.0f, s2 = 0.0f;
#pragma unroll
            for (int j = 0; j < 16; j++) { s += x[j]; s2 += x[j] * x[j]; }
#pragma unroll
            for (int o = 4; o; o >>= 1) {
                s  += __shfl_xor_sync(0xffffffffu, s,  o);
                s2 += __shfl_xor_sync(0xffffffffu, s2, o);
            }
            float mean = s * (1.0f / HID);
            float rstd = rsqrtf(s2 * (1.0f / HID) - mean * mean + 1e-5f);
#pragma unroll
            for (int j = 0; j < 16; j++) {
                int col = l8 * 16 + j;
                x[j] = (x[j] - mean) * rstd * lng[col] + lnb[col];
            }
        }
        uint32_t phi[8], plo[8];
#pragma unroll
        for (int j = 0; j < 8; j++) {
            __half h0, l0, h1, l1;
            hsplit(x[2 * j],     h0, l0);
            hsplit(x[2 * j + 1], h1, l1);
            phi[j] = packh2(h0, h1);
            plo[j] = packh2(l0, l1);
        }
        uint4* dhi = reinterpret_cast<uint4*>(&Ahi[r * 136 + l8 * 16]);
        uint4* dlo = reinterpret_cast<uint4*>(&Alo[r * 136 + l8 * 16]);
        dhi[0] = make_uint4(phi[0], phi[1], phi[2], phi[3]);
        dhi[1] = make_uint4(phi[4], phi[5], phi[6], phi[7]);
        dlo[0] = make_uint4(plo[0], plo[1], plo[2], plo[3]);
        dlo[1] = make_uint4(plo[4], plo[5], plo[6], plo[7]);
    }
    if (SUMOUT && tid < 128) colsum[tid] = 0.0f;
    __syncthreads();

    // ---- main MMA loop ----
    const int warp = tid >> 5, lane = tid & 31;
    const int g = lane >> 2, t4 = lane & 3;
    const int mt = warp & 1, ch = warp >> 1;
    const uint4* img_p = &g_wf[(size_t)img * 4096];

    float acc[4][4];
#pragma unroll
    for (int nt = 0; nt < 4; nt++)
#pragma unroll
        for (int i = 0; i < 4; i++) acc[nt][i] = 0.0f;

    const __half* ahb = &Ahi[(mt * 16 + g) * 136];
    const __half* alb = &Alo[(mt * 16 + g) * 136];

#pragma unroll
    for (int ks = 0; ks < 8; ks++) {
        const int co = ks * 16 + 2 * t4;
        uint32_t ah0 = *reinterpret_cast<const uint32_t*>(&ahb[co]);
        uint32_t ah1 = *reinterpret_cast<const uint32_t*>(&ahb[8 * 136 + co]);
        uint32_t ah2 = *reinterpret_cast<const uint32_t*>(&ahb[co + 8]);
        uint32_t ah3 = *reinterpret_cast<const uint32_t*>(&ahb[8 * 136 + co + 8]);
        uint32_t al0 = *reinterpret_cast<const uint32_t*>(&alb[co]);
        uint32_t al1 = *reinterpret_cast<const uint32_t*>(&alb[8 * 136 + co]);
        uint32_t al2 = *reinterpret_cast<const uint32_t*>(&alb[co + 8]);
        uint32_t al3 = *reinterpret_cast<const uint32_t*>(&alb[8 * 136 + co + 8]);
#pragma unroll
        for (int nt = 0; nt < 4; nt++) {
            uint4 f = img_p[((4 * ch + nt) * 8 + ks) * 32 + lane];
            mma16816(acc[nt][0], acc[nt][1], acc[nt][2], acc[nt][3],
                     ah0, ah1, ah2, ah3, f.x, f.y);
            mma16816(acc[nt][0], acc[nt][1], acc[nt][2], acc[nt][3],
                     al0, al1, al2, al3, f.x, f.y);
            mma16816(acc[nt][0], acc[nt][1], acc[nt][2], acc[nt][3],
                     ah0, ah1, ah2, ah3, f.z, f.w);
        }
    }

    // ---- epilogue ----
    const int sn = SUMOUT ? *snp : 0;
#pragma unroll
    for (int nt = 0; nt < 4; nt++) {
        const int ncol = c0 + (4 * ch + nt) * 8 + 2 * t4;
        const int row0 = m0 + mt * 16 + g, row1 = row0 + 8;
        float b0 = bias[ncol], b1 = bias[ncol + 1];
        float v00 = acc[nt][0] + b0, v01 = acc[nt][1] + b1;
        float v10 = acc[nt][2] + b0, v11 = acc[nt][3] + b1;
        if (ACT == 1) {
            const float k = 0.70710678118654752f;
            v00 = 0.5f * v00 * (1.0f + erff(v00 * k));
            v01 = 0.5f * v01 * (1.0f + erff(v01 * k));
            v10 = 0.5f * v10 * (1.0f + erff(v10 * k));
            v11 = 0.5f * v11 * (1.0f + erff(v11 * k));
        }
        if (RESID) {
            v00 += R[row0 * HID + ncol];  v01 += R[row0 * HID + ncol + 1];
            v10 += R[row1 * HID + ncol];  v11 += R[row1 * HID + ncol + 1];
        }
        if (SUMOUT) {
            float a0 = (row0 < sn ? v00 : 0.0f) + (row1 < sn ? v10 : 0.0f);
            float a1 = (row0 < sn ? v01 : 0.0f) + (row1 < sn ? v11 : 0.0f);
            atomicAdd(&colsum[ncol], a0);
            atomicAdd(&colsum[ncol + 1], a1);
        } else {
            C[row0 * outStride + ncol]     = v00;
            C[row0 * outStride + ncol + 1] = v01;
            C[row1 * outStride + ncol]     = v10;
            C[row1 * outStride + ncol + 1] = v11;
        }
    }
    if (SUMOUT) {
        __syncthreads();
        if (tid < 128) atomicAdd(&g_xsum[tid], (double)colsum[tid]);
    }
}

// ============================================================================
// K1: sine encoding + GEMM  ->  g_eig = eeig[S,129] @ W[129,128] + b
// 32 rows per block, 256 threads; sincosf fuses sin/cos of the same argument.
// ============================================================================
__global__ void __launch_bounds__(256) k_sine_enc(const float* __restrict__ eve,
                                                  const float* __restrict__ W,
                                                  const float* __restrict__ b) {
    __shared__ float ee[32][132];   // 129 used
    const int m0  = blockIdx.x * 32;
    const int tid = threadIdx.x;
    const float kLog = -9.210340371976184f / 128.0f;   // -ln(1e4)/128

    for (int idx = tid; idx < 32 * 64; idx += 256) {
        int r = idx >> 6, i = idx & 63;
        float e  = eve[m0 + r];
        float pe = e * 100.0f * __expf((2.0f * i) * kLog);
        float sv, cv;
        sincosf(pe, &sv, &cv);
        ee[r][1 + i]  = sv;
        ee[r][65 + i] = cv;
    }
    if (tid < 32) ee[tid][0] = eve[m0 + tid];
    __syncthreads();

    const int col  = tid & 127;
    const int half = tid >> 7;     // 0: rows 0-15, 1: rows 16-31
    float acc[16];
#pragma unroll
    for (int r = 0; r < 16; r++) acc[r] = 0.0f;

    for (int k = 0; k < 129; k++) {
        float wv = W[k * HID + col];
#pragma unroll
        for (int r = 0; r < 16; r++) acc[r] = fmaf(ee[half * 16 + r][k], wv, acc[r]);
    }
    float bb = b[col];
#pragma unroll
    for (int r = 0; r < 16; r++)
        g_eig[(m0 + half * 16 + r) * HID + col] = acc[r] + bb;
}

// ============================================================================
// K-prep: per-(head, 64-key tile) image: K hi [key][dim], V^T hi [dim][key],
// plus an all-ones dim row (row 32) so PV MMA emits the softmax denominator.
// grid = (S/KT, NHEADS), 256 threads.
// ============================================================================
__global__ void __launch_bounds__(256) k_prep(const float* __restrict__ qkv) {
    __shared__ __align__(16) __half img[TILE_H];
    const int tid = threadIdx.x;
    const int kb  = blockIdx.x * KT;
    const int h   = blockIdx.y;

    {   // zero entire image (covers pad + rows 33..39)
        uint4 z = make_uint4(0, 0, 0, 0);
        uint4* p = reinterpret_cast<uint4*>(img);
        for (int i = tid; i < TILE_U4; i += 256) p[i] = z;
    }
    __syncthreads();

    for (int i = tid; i < KT * HD; i += 256) {
        int key = i >> 5, d = i & 31;
        const float* base = qkv + (size_t)(kb + key) * 384 + h * HD + d;
        img[key * KROW + d]        = __float2half_rn(base[128]);   // K
        img[KIMG + d * VROW + key] = __float2half_rn(base[256]);   // V^T
    }
    if (tid < KT) img[KIMG + 32 * VROW + tid] = __float2half(1.0f);  // ones row
    __syncthreads();

    uint4* dst = reinterpret_cast<uint4*>(g_kv + (size_t)(h * (S / KT) + blockIdx.x) * TILE_H);
    const uint4* src = reinterpret_cast<const uint4*>(img);
    for (int i = tid; i < TILE_U4; i += 256) dst[i] = src[i];
}

// ============================================================================
// K4a: MMA flash attention partial.
// Scores in log2 domain; P via ex2.approx.f16x2; denominator l via ones-row
// in the PV MMA (5th d-tile). QK 2-term, PV 1-term fp16.
// grid = (S/QT, NHEADS, NKC), block = 256 (8 warps x 16 queries).
// ============================================================================
__global__ void __launch_bounds__(256) k_attn_mma(const float* __restrict__ qkv,
                                                  const int* __restrict__ snp) {
    __shared__ __align__(16) __half tile[2][TILE_H];

    const int tid  = threadIdx.x;
    const int warp = tid >> 5;
    const int lane = tid & 31;
    const int g    = lane >> 2;    // group (row within fragment)
    const int t4   = lane & 3;     // thread-in-group
    const int h    = blockIdx.y;
    const int kc   = blockIdx.z;
    const int sn   = *snp;

    const int qbase = blockIdx.x * QT + warp * 16;
    const int r0 = qbase + g;        // query rows owned by this thread
    const int r1 = r0 + 8;

    const uint32_t sm0 = (uint32_t)__cvta_generic_to_shared(&tile[0][0]);
    const uint32_t sm1 = (uint32_t)__cvta_generic_to_shared(&tile[1][0]);

    // ---- load Q fragments (2 k-steps), split hi/lo fp16; log2e folded in ----
    uint32_t Qhi[2][4], Qlo[2][4];
#pragma unroll
    for (int ks = 0; ks < 2; ks++) {
#pragma unroll
        for (int hh = 0; hh < 2; hh++) {     // k-half (+0 / +8)
#pragma unroll
            for (int rr = 0; rr < 2; rr++) { // row g / g+8
                int row = rr ? r1 : r0;
                int d0  = ks * 16 + hh * 8 + 2 * t4;
                float x0 = qkv[row * 384 + h * HD + d0]     * QSCALE;
                float x1 = qkv[row * 384 + h * HD + d0 + 1] * QSCALE;
                int ri = hh * 2 + rr;
                packsplit2h(x0, x1, Qhi[ks][ri], Qlo[ks][ri]);
            }
        }
    }

    float O[5][4];                    // [d-tile][frag]; nt=4 carries l (ones row)
#pragma unroll
    for (int nt = 0; nt < 5; nt++)
#pragma unroll
        for (int i = 0; i < 4; i++) O[nt][i] = 0.0f;
    float m0v = -INFINITY, m1v = -INFINITY;

    const int tile0 = (kc * CHUNK) >> 6;    // first tile index in this chunk

    // prefetch tile 0 into buffer 0
    {
        const uint4* src = reinterpret_cast<const uint4*>(
            g_kv + (size_t)(h * (S / KT) + tile0) * TILE_H);
        for (int i = tid; i < TILE_U4; i += 256)
            cp16(sm0 + i * 16, src + i);
        cp_commit();
    }

    for (int it = 0; it < NT_CH; it++) {
        cp_wait_all();
        __syncthreads();

        // prefetch next tile into the other buffer (overlaps compute below)
        if (it + 1 < NT_CH) {
            const uint4* src = reinterpret_cast<const uint4*>(
                g_kv + (size_t)(h * (S / KT) + tile0 + it + 1) * TILE_H);
            uint32_t dstb = ((it + 1) & 1) ? sm1 : sm0;
            for (int i = tid; i < TILE_U4; i += 256)
                cp16(dstb + i * 16, src + i);
            cp_commit();
        }

        const __half* tl = tile[it & 1];
        const int kb = kc * CHUNK + it * KT;

        // ---- QK^T: 8 n-tiles of 8 keys; exact-Q (hi+lo) x Khi ----
        float Sf[8][4];
#pragma unroll
        for (int nt = 0; nt < 8; nt++) {
#pragma unroll
            for (int i = 0; i < 4; i++) Sf[nt][i] = 0.0f;
            int key = nt * 8 + g;
            const __half* krow = &tl[key * KROW];
#pragma unroll
            for (int ks = 0; ks < 2; ks++) {
                uint32_t bh0 = *reinterpret_cast<const uint32_t*>(&krow[ks * 16 + 2 * t4]);
                uint32_t bh1 = *reinterpret_cast<const uint32_t*>(&krow[ks * 16 + 8 + 2 * t4]);
                mma16816(Sf[nt][0], Sf[nt][1], Sf[nt][2], Sf[nt][3],
                         Qhi[ks][0], Qhi[ks][1], Qhi[ks][2], Qhi[ks][3], bh0, bh1);
                mma16816(Sf[nt][0], Sf[nt][1], Sf[nt][2], Sf[nt][3],
                         Qlo[ks][0], Qlo[ks][1], Qlo[ks][2], Qlo[ks][3], bh0, bh1);
            }
        }

        // ---- mask ----
        if (kb + KT > sn) {
#pragma unroll
            for (int nt = 0; nt < 8; nt++) {
                int k0 = kb + nt * 8 + 2 * t4;
                if (k0     >= sn) { Sf[nt][0] = -INFINITY; Sf[nt][2] = -INFINITY; }
                if (k0 + 1 >= sn) { Sf[nt][1] = -INFINITY; Sf[nt][3] = -INFINITY; }
            }
        }

        // ---- online softmax (log2 domain) ----
        float mx0 = -INFINITY, mx1 = -INFINITY;
#pragma unroll
        for (int nt = 0; nt < 8; nt++) {
            mx0 = fmaxf(mx0, fmaxf(Sf[nt][0], Sf[nt][1]));
            mx1 = fmaxf(mx1, fmaxf(Sf[nt][2], Sf[nt][3]));
        }
#pragma unroll
        for (int o = 1; o <= 2; o <<= 1) {
            mx0 = fmaxf(mx0, __shfl_xor_sync(0xffffffffu, mx0, o));
            mx1 = fmaxf(mx1, __shfl_xor_sync(0xffffffffu, mx1, o));
        }
        float mn0 = fmaxf(m0v, mx0);
        float mn1 = fmaxf(m1v, mx1);
        if (mn0 == -INFINITY) mn0 = 0.0f;   // fully-masked guard
        if (mn1 == -INFINITY) mn1 = 0.0f;
        float c0 = exp2f(m0v - mn0);        // -inf -> 0 on first tile
        float c1 = exp2f(m1v - mn1);
#pragma unroll
        for (int nt = 0; nt < 5; nt++) {    // includes l accumulators (nt=4)
            O[nt][0] *= c0; O[nt][1] *= c0;
            O[nt][2] *= c1; O[nt][3] *= c1;
        }
        m0v = mn0; m1v = mn1;

        uint32_t Ph[4][4];                  // fp16 P fragments via f16x2 EX2
#pragma unroll
        for (int j = 0; j < 4; j++) {       // key-step j covers tiles 2j, 2j+1
#pragma unroll
            for (int tt = 0; tt < 2; tt++) {
                int nt = 2 * j + tt;
                Ph[j][tt * 2]     = exp2h2(Sf[nt][0] - mn0, Sf[nt][1] - mn0);
                Ph[j][tt * 2 + 1] = exp2h2(Sf[nt][2] - mn1, Sf[nt][3] - mn1);
            }
        }

        // ---- PV: 5 d-tiles (incl. ones row) x 4 key-steps, 1-term fp16 ----
#pragma unroll
        for (int nt = 0; nt < 5; nt++) {
            int d = nt * 8 + g;
            const __half* vrow = &tl[KIMG + d * VROW];
#pragma unroll
            for (int ks = 0; ks < 4; ks++) {
                uint32_t bh0 = *reinterpret_cast<const uint32_t*>(&vrow[ks * 16 + 2 * t4]);
                uint32_t bh1 = *reinterpret_cast<const uint32_t*>(&vrow[ks * 16 + 8 + 2 * t4]);
                mma16816(O[nt][0], O[nt][1], O[nt][2], O[nt][3],
                         Ph[ks][0], Ph[ks][1], Ph[ks][2], Ph[ks][3], bh0, bh1);
            }
        }
        __syncthreads();
    }

    // ---- write partials (unnormalized); l lives in O[4] at col 32 (t4==0) ----
    const int p0 = (h * NKC + kc) * S + r0;
    const int p1 = (h * NKC + kc) * S + r1;
    if (t4 == 0) {
        g_pm[p0] = m0v;  g_pl[p0] = O[4][0];
        g_pm[p1] = m1v;  g_pl[p1] = O[4][2];
    }
#pragma unroll
    for (int nt = 0; nt < 4; nt++) {
        int d = nt * 8 + 2 * t4;
        g_po[(size_t)p0 * HD + d]     = O[nt][0];
        g_po[(size_t)p0 * HD + d + 1] = O[nt][1];
        g_po[(size_t)p1 * HD + d]     = O[nt][2];
        g_po[(size_t)p1 * HD + d + 1] = O[nt][3];
    }
}

// ============================================================================
// pooled coefficients (single block)
// ============================================================================
__global__ void __launch_bounds__(128) k_pool(const float* __restrict__ dscW, const float* __restrict__ dscb,
                                              const float* __restrict__ dwvW, const float* __restrict__ dwvb,
                                              const float* __restrict__ dssW, const float* __restrict__ dssb,
                                              const int* __restrict__ lenp, const int* __restrict__ snp) {
    const int tid = threadIdx.x;
    __shared__ float sig[104];
    __shared__ float ssum[2];
    const float lenf = (float)(*lenp);
    const float snf  = (float)(*snp);

    if (tid < 104) {
        const float* W; const float* bb; int c; int NCc;
        if (tid < 50)       { W = dscW; bb = dscb; c = tid;       NCc = NCOE; }
        else if (tid < 100) { W = dwvW; bb = dwvb; c = tid - 50;  NCc = NCOE; }
        else                { W = dssW; bb = dssb; c = tid - 100; NCc = NSCALES; }
        double acc = 0.0;
        for (int k = 0; k < HID; k++) acc += g_xsum[k] * (double)W[k * NCc + c];
        float pooled = (float)((acc + (double)(snf * bb[c])) / (double)(lenf + 1e-8f));
        sig[tid] = 1.0f / (1.0f + expf(-pooled));
    }
    __syncthreads();
    if (tid == 0) { float t = 0.f; for (int i = 0;  i < 50;  i++) t += sig[i]; ssum[0] = t; }
    if (tid == 1) { float t = 0.f; for (int i = 50; i < 100; i++) t += sig[i]; ssum[1] = t; }
    __syncthreads();
    if (tid < 50)       g_coef[tid] = sig[tid] / (ssum[0] + 1e-8f);
    else if (tid < 100) g_coef[tid] = sig[tid] / (ssum[1] + 1e-8f);
    else if (tid < 104) g_coef[tid] = sig[tid] * 5.0f;   // THRE
}

// ============================================================================
// Chebyshev synthesis + L2 normalize  ->  out[S, 5]
// ============================================================================
__global__ void __launch_bounds__(128) k_final(const float* __restrict__ eve,
                                               float* __restrict__ out) {
    __shared__ float cs[NCOE], cw[NCOE], sc[NSCALES];
    const int tid = threadIdx.x;
    if (tid < 50)        cs[tid]       = g_coef[tid];
    else if (tid < 100)  cw[tid - 50]  = g_coef[tid];
    else if (tid < 104)  sc[tid - 100] = g_coef[tid];
    __syncthreads();

    const int s = blockIdx.x * 128 + tid;
    const float e = eve[s];
    float vals[5];

    {   // scaling channel: y = e - 1; coefficients on T_1,T_3,...
        float y  = e - 1.0f;
        float te = 1.0f, to = y;
        float acc = cs[0] * (0.5f * (1.0f - to));
#pragma unroll
        for (int c = 1; c < NCOE; c++) {
            te = 2.0f * y * to - te;          // T_{2c}
            to = 2.0f * y * te - to;          // T_{2c+1}
            acc += cs[c] * (0.5f * (1.0f - to));
        }
        vals[0] = acc;
    }

#pragma unroll
    for (int j = 0; j < NSCALES; j++) {       // wavelet channels: T_0,T_2,...
        float f = e * sc[j];
        if (f > 2.0f) f = 0.0f;
        float y  = f - 1.0f;
        float te = 1.0f, to = y;
        float acc = 0.0f;                      // cw[0] * 0.5*(1-T_0) = 0
#pragma unroll
        for (int c = 1; c < NCOE; c++) {
            te = 2.0f * y * to - te;          // T_{2c}
            acc += cw[c] * (0.5f * (1.0f - te));
            to = 2.0f * y * te - to;          // T_{2c+1}
        }
        vals[1 + j] = acc;
    }

    float n2 = 0.0f;
#pragma unroll
    for (int i = 0; i < 5; i++) n2 += vals[i] * vals[i];
    float inv = 1.0f / (sqrtf(n2) + 1e-8f);
#pragma unroll
    for (int i = 0; i < 5; i++) out[s * 5 + i] = vals[i] * inv;
}

// ============================================================================
// launch
// ============================================================================
extern "C" void kernel_launch(void* const* d_in, const int* in_sizes, int n_in,
                              void* d_out, int out_size) {
    const float* eve      = (const float*)d_in[0];
    const int*   lenp     = (const int*)  d_in[1];
    const int*   snp      = (const int*)  d_in[2];
    const float* eig_w_W  = (const float*)d_in[3];
    const float* eig_w_b  = (const float*)d_in[4];
    const float* mha_ln_g = (const float*)d_in[5];
    const float* mha_ln_b = (const float*)d_in[6];
    const float* in_W     = (const float*)d_in[7];
    const float* in_b     = (const float*)d_in[8];
    const float* out_W    = (const float*)d_in[9];
    const float* out_b    = (const float*)d_in[10];
    const float* ffn_ln_g = (const float*)d_in[11];
    const float* ffn_ln_b = (const float*)d_in[12];
    const float* ffn1_W   = (const float*)d_in[13];
    const float* ffn1_b   = (const float*)d_in[14];
    const float* ffn2_W   = (const float*)d_in[15];
    const float* ffn2_b   = (const float*)d_in[16];
    const float* dsc_W    = (const float*)d_in[17];
    const float* dsc_b    = (const float*)d_in[18];
    const float* dwv_W    = (const float*)d_in[19];
    const float* dwv_b    = (const float*)d_in[20];
    const float* dss_W    = (const float*)d_in[21];
    const float* dss_b    = (const float*)d_in[22];
    float* out = (float*)d_out;

    float *p_eig, *p_qkv, *p_h1;
    cudaGetSymbolAddress((void**)&p_eig,  g_eig);
    cudaGetSymbolAddress((void**)&p_qkv,  g_qkv);
    cudaGetSymbolAddress((void**)&p_h1,   g_h1);

    // 0) weight images + zero xsum
    k_wprep<<<dim3(16, 6), 256>>>(in_W, out_W, ffn1_W, ffn2_W);
    // 1) eig = sine_encoding(eve) @ W + b
    k_sine_enc<<<S / 32, 256>>>(eve, eig_w_W, eig_w_b);
    // 2) qkv = LN(eig) @ in_W + in_b   (MMA, 3 column-blocks via grid.y)
    k_gemm_mma<0, 0, 1, 1, 0, 0><<<dim3(128, 3), 256>>>(p_eig, 0, in_b, nullptr, p_qkv, 384, mha_ln_g, mha_ln_b, nullptr);
    // 3) pre-swizzle K/V tiles (+ones row) to fp16 images
    k_prep<<<dim3(S / KT, NHEADS), 256>>>(p_qkv);
    // 4) attention split-K partials (combine fused into step 5)
    k_attn_mma<<<dim3(S / QT, NHEADS, NKC), 256>>>(p_qkv, snp);
    // 5) eig = eig + combine(partials) @ out_W + out_b   (COMB staging)
    k_gemm_mma<0, 1, 0, 0, 1, 0><<<dim3(128), 256>>>(nullptr, 3, out_b, p_eig, p_eig, 128, nullptr, nullptr, nullptr);
    // 6) h1 = gelu(LN(eig) @ ffn1_W + b)
    k_gemm_mma<1, 0, 1, 0, 0, 0><<<dim3(128), 256>>>(p_eig, 4, ffn1_b, nullptr, p_h1, 128, ffn_ln_g, ffn_ln_b, nullptr);
    // 7) eigf column-sums = sum_rows<sn (eig + h1 @ ffn2_W + b)  (no store)
    k_gemm_mma<0, 1, 0, 0, 0, 1><<<dim3(128), 256>>>(p_h1, 5, ffn2_b, p_eig, nullptr, 128, nullptr, nullptr, snp);
    // 8) pooled coefficients
    k_pool<<<1, 128>>>(dsc_W, dsc_b, dwv_W, dwv_b, dss_W, dss_b, lenp, snp);
    // 9) Chebyshev synthesis + normalize
    k_final<<<S / 128, 128>>>(eve, out);
}

// round 12
// speedup vs baseline: 2.3971x; 1.0984x over previous
#include <cuda_runtime.h>
#include <cuda_fp16.h>
#include <math.h>
#include <stdint.h>

// ---------------- problem constants ----------------
#define S 4096
#define HID 128
#define NHEADS 4
#define HD 32
#define NCOE 50
#define NSCALES 4
#define NKC 2              // split-K chunks for attention
#define CHUNK (S / NKC)    // 2048 keys per chunk
#define QT 128             // queries per block (8 warps x 16)
#define KT 64              // key tile
#define NT_CH (CHUNK / KT) // 32 tiles per chunk

// KV tile image geometry (halves). Padded rows for conflict-free LDS.
#define KROW 40                      // per-key: 32 hi + 8 pad
#define KIMG (KT * KROW)             // 2560 halves
#define VROW 72                      // per-dim: 64 keys + 8 pad
#define VIMG (40 * VROW)             // rows 0..31 = V, 32 = ones, 33..39 = zero pad
#define TILE_H (KIMG + VIMG)         // 5440 halves = 10880 B
#define TILE_U4 (TILE_H / 8)         // 680 uint4

// log2(e)/sqrt(32): scores come out of QK in log2 domain
#define QSCALE 0.2550458572864341f

// ---------------- scratch (__device__ globals; no allocs allowed) ----------------
__device__ float  g_eig [S * HID];
__device__ float  g_qkv [S * 3 * HID];
__device__ float  g_h1  [S * HID];
__device__ __align__(16) __half g_kv[NHEADS * (S / KT) * TILE_H];  // pre-swizzled K/V tiles
__device__ __align__(16) uint4  g_wf[6 * 4096];   // 6 weight images, fragment-ordered
__device__ float  g_pm  [NHEADS * NKC * S];        // partial max (log2 domain)
__device__ float  g_pl  [NHEADS * NKC * S];        // partial sum
__device__ float  g_po  [NHEADS * NKC * S * HD];   // partial (unnormalized) out
__device__ double g_xsum[HID];
__device__ float  g_coef[128];   // [0:50) scaling, [50:100) wavelet, [100:104) scales

// ---------------- mma / async helpers ----------------
__device__ __forceinline__ void mma16816(float& c0, float& c1, float& c2, float& c3,
                                         uint32_t a0, uint32_t a1, uint32_t a2, uint32_t a3,
                                         uint32_t b0, uint32_t b1) {
    asm volatile("mma.sync.aligned.m16n8k16.row.col.f32.f16.f16.f32 "
                 "{%0,%1,%2,%3}, {%4,%5,%6,%7}, {%8,%9}, {%0,%1,%2,%3};\n"
                 : "+f"(c0), "+f"(c1), "+f"(c2), "+f"(c3)
                 : "r"(a0), "r"(a1), "r"(a2), "r"(a3), "r"(b0), "r"(b1));
}

__device__ __forceinline__ void cp16(uint32_t dst, const void* src) {
    asm volatile("cp.async.cg.shared.global [%0], [%1], 16;\n" :: "r"(dst), "l"(src));
}
__device__ __forceinline__ void cp_commit() {
    asm volatile("cp.async.commit_group;\n");
}
__device__ __forceinline__ void cp_wait_all() {
    asm volatile("cp.async.wait_group 0;\n");
}

__device__ __forceinline__ uint32_t packh2(__half a, __half b) {
    __half2 t = __halves2half2(a, b);     // a -> low half
    return *reinterpret_cast<uint32_t*>(&t);
}

// split x into hi (fp16) and lo (fp16 of remainder)
__device__ __forceinline__ void hsplit(float x, __half& h, __half& l) {
    h = __float2half_rn(x);
    l = __float2half_rn(x - __half2float(h));
}

__device__ __forceinline__ uint32_t pack2f(float x, float y) {
    __half2 t = __floats2half2_rn(x, y);  // x -> low
    return *reinterpret_cast<uint32_t*>(&t);
}

// 2^a, 2^b as packed fp16x2 (one MUFU op for both lanes)
__device__ __forceinline__ uint32_t exp2h2(float a, float b) {
    uint32_t hi = pack2f(a, b);
    uint32_t r;
    asm("ex2.approx.f16x2 %0, %1;" : "=r"(r) : "r"(hi));
    return r;
}

// ============================================================================
// W-prep: build fragment-ordered fp16 hi/lo images for all 6 [128,128] weights.
// Also zeroes g_xsum (runs first every launch).
// grid = (16, 6), 256 threads.
// ============================================================================
__global__ void __launch_bounds__(256) k_wprep(const float* __restrict__ inW,
                                               const float* __restrict__ outW,
                                               const float* __restrict__ f1W,
                                               const float* __restrict__ f2W) {
    const int tid  = threadIdx.x;
    if (blockIdx.x == 0 && blockIdx.y == 0 && tid < HID) g_xsum[tid] = 0.0;

    const int lane = tid & 31;
    const int g    = lane >> 2;
    const int t4   = lane & 3;
    const int wid  = blockIdx.x * 8 + (tid >> 5);   // fragment id 0..127
    const int nt   = wid >> 3;
    const int ks   = wid & 7;

    const float* W; int ldw, c0;
    switch (blockIdx.y) {
        case 0:  W = inW;  ldw = 384; c0 = 0;   break;
        case 1:  W = inW;  ldw = 384; c0 = 128; break;
        case 2:  W = inW;  ldw = 384; c0 = 256; break;
        case 3:  W = outW; ldw = 128; c0 = 0;   break;
        case 4:  W = f1W;  ldw = 128; c0 = 0;   break;
        default: W = f2W;  ldw = 128; c0 = 0;   break;
    }

    const int n  = nt * 8 + g;
    const int k0 = ks * 16 + 2 * t4;
    float w00 = W[(k0    ) * ldw + c0 + n];
    float w01 = W[(k0 + 1) * ldw + c0 + n];
    float w80 = W[(k0 + 8) * ldw + c0 + n];
    float w81 = W[(k0 + 9) * ldw + c0 + n];
    __half h00, l00, h01, l01, h80, l80, h81, l81;
    hsplit(w00, h00, l00);  hsplit(w01, h01, l01);
    hsplit(w80, h80, l80);  hsplit(w81, h81, l81);
    uint4 f;
    f.x = packh2(h00, h01);
    f.y = packh2(h80, h81);
    f.z = packh2(l00, l01);
    f.w = packh2(l80, l81);
    g_wf[blockIdx.y * 4096 + wid * 32 + lane] = f;
}

// ============================================================================
// MMA GEMM: C[:, c0:c0+128] = act( X @ Wimg + bias ) (+ R)
// X = A (optionally LayerNormed) or the split-K attention combine (COMB).
// SUMOUT: skip store; instead accumulate masked column sums into g_xsum.
// grid = (128, MULTI?3:1), 256 threads (8 warps). 32 rows per block.
// ============================================================================
template <int ACT, int RESID, int LNORM, int MULTI, int COMB, int SUMOUT>
__global__ void __launch_bounds__(256) k_gemm_mma(const float* __restrict__ A,
                                                  int img0,
                                                  const float* __restrict__ bias,
                                                  const float* __restrict__ R,
                                                  float* __restrict__ C,
                                                  int outStride,
                                                  const float* __restrict__ lng,
                                                  const float* __restrict__ lnb,
                                                  const int* __restrict__ snp) {
    __shared__ __align__(16) __half Ahi[32 * 136];
    __shared__ __align__(16) __half Alo[32 * 136];
    __shared__ float colsum[128];
    const int tid = threadIdx.x;
    const int m0  = blockIdx.x * 32;
    const int c0  = MULTI ? blockIdx.y * 128 : 0;
    const int img = img0 + (MULTI ? blockIdx.y : 0);

    // ---- stage X tile (plain / LN / attention-combine), fp16 hi/lo ----
    {
        const int r = tid >> 3, l8 = tid & 7;
        float x[16];
        if (COMB) {
            // split-K combine: head = l8>>1, dims (l8&1)*16 .. +16
            const int row    = m0 + r;
            const int head   = l8 >> 1;
            const int hd_off = (l8 & 1) * 16;
            float M = -INFINITY;
#pragma unroll
            for (int kc = 0; kc < NKC; kc++)
                M = fmaxf(M, g_pm[(head * NKC + kc) * S + row]);
#pragma unroll
            for (int j = 0; j < 16; j++) x[j] = 0.0f;
            float L = 0.0f;
#pragma unroll
            for (int kc = 0; kc < NKC; kc++) {
                const int p = (head * NKC + kc) * S + row;
                float li = g_pl[p];
                if (li > 0.0f) {
                    float w = exp2f(g_pm[p] - M);
                    L += li * w;
                    const float4* po = reinterpret_cast<const float4*>(&g_po[(size_t)p * HD + hd_off]);
#pragma unroll
                    for (int jj = 0; jj < 4; jj++) {
                        float4 v = po[jj];
                        x[jj * 4 + 0] = fmaf(w, v.x, x[jj * 4 + 0]);
                        x[jj * 4 + 1] = fmaf(w, v.y, x[jj * 4 + 1]);
                        x[jj * 4 + 2] = fmaf(w, v.z, x[jj * 4 + 2]);
                        x[jj * 4 + 3] = fmaf(w, v.w, x[jj * 4 + 3]);
                    }
                }
            }
            float inv = (L > 0.0f) ? 1.0f / L : 0.0f;
#pragma unroll
            for (int j = 0; j < 16; j++) x[j] *= inv;
        } else {
            const float4* ap = reinterpret_cast<const float4*>(A + (m0 + r) * HID + l8 * 16);
#pragma unroll
            for (int j = 0; j < 4; j++) {
                float4 v = ap[j];
                x[j * 4 + 0] = v.x; x[j * 4 + 1] = v.y;
                x[j * 4 + 2] = v.z; x[j * 4 + 3] = v.w;
            }
        }
        if (LNORM) {
            float s = 0.0f, s2 = 0.0f;
#pragma unroll
            for (int j = 0; j < 16; j++) { s += x[j]; s2 += x[j] * x[j]; }
#pragma unroll
            for (int o = 4; o; o >>= 1) {
                s  += __shfl_xor_sync(0xffffffffu, s,  o);
                s2 += __shfl_xor_sync(0xffffffffu, s2, o);
            }
            float mean = s * (1.0f / HID);
            float rstd = rsqrtf(s2 * (1.0f / HID) - mean * mean + 1e-5f);
#pragma unroll
            for (int j = 0; j < 16; j++) {
                int col = l8 * 16 + j;
                x[j] = (x[j] - mean) * rstd * lng[col] + lnb[col];
            }
        }
        uint32_t phi[8], plo[8];
#pragma unroll
        for (int j = 0; j < 8; j++) {
            __half h0, l0, h1, l1;
            hsplit(x[2 * j],     h0, l0);
            hsplit(x[2 * j + 1], h1, l1);
            phi[j] = packh2(h0, h1);
            plo[j] = packh2(l0, l1);
        }
        uint4* dhi = reinterpret_cast<uint4*>(&Ahi[r * 136 + l8 * 16]);
        uint4* dlo = reinterpret_cast<uint4*>(&Alo[r * 136 + l8 * 16]);
        dhi[0] = make_uint4(phi[0], phi[1], phi[2], phi[3]);
        dhi[1] = make_uint4(phi[4], phi[5], phi[6], phi[7]);
        dlo[0] = make_uint4(plo[0], plo[1], plo[2], plo[3]);
        dlo[1] = make_uint4(plo[4], plo[5], plo[6], plo[7]);
    }
    if (SUMOUT && tid < 128) colsum[tid] = 0.0f;
    __syncthreads();

    // ---- main MMA loop ----
    const int warp = tid >> 5, lane = tid & 31;
    const int g = lane >> 2, t4 = lane & 3;
    const int mt = warp & 1, ch = warp >> 1;
    const uint4* img_p = &g_wf[(size_t)img * 4096];

    float acc[4][4];
#pragma unroll
    for (int nt = 0; nt < 4; nt++)
#pragma unroll
        for (int i = 0; i < 4; i++) acc[nt][i] = 0.0f;

    const __half* ahb = &Ahi[(mt * 16 + g) * 136];
    const __half* alb = &Alo[(mt * 16 + g) * 136];

#pragma unroll
    for (int ks = 0; ks < 8; ks++) {
        const int co = ks * 16 + 2 * t4;
        uint32_t ah0 = *reinterpret_cast<const uint32_t*>(&ahb[co]);
        uint32_t ah1 = *reinterpret_cast<const uint32_t*>(&ahb[8 * 136 + co]);
        uint32_t ah2 = *reinterpret_cast<const uint32_t*>(&ahb[co + 8]);
        uint32_t ah3 = *reinterpret_cast<const uint32_t*>(&ahb[8 * 136 + co + 8]);
        uint32_t al0 = *reinterpret_cast<const uint32_t*>(&alb[co]);
        uint32_t al1 = *reinterpret_cast<const uint32_t*>(&alb[8 * 136 + co]);
        uint32_t al2 = *reinterpret_cast<const uint32_t*>(&alb[co + 8]);
        uint32_t al3 = *reinterpret_cast<const uint32_t*>(&alb[8 * 136 + co + 8]);
#pragma unroll
        for (int nt = 0; nt < 4; nt++) {
            uint4 f = img_p[((4 * ch + nt) * 8 + ks) * 32 + lane];
            mma16816(acc[nt][0], acc[nt][1], acc[nt][2], acc[nt][3],
                     ah0, ah1, ah2, ah3, f.x, f.y);
            mma16816(acc[nt][0], acc[nt][1], acc[nt][2], acc[nt][3],
                     al0, al1, al2, al3, f.x, f.y);
            mma16816(acc[nt][0], acc[nt][1], acc[nt][2], acc[nt][3],
                     ah0, ah1, ah2, ah3, f.z, f.w);
        }
    }

    // ---- epilogue ----
    const int sn = SUMOUT ? *snp : 0;
#pragma unroll
    for (int nt = 0; nt < 4; nt++) {
        const int ncol = c0 + (4 * ch + nt) * 8 + 2 * t4;
        const int row0 = m0 + mt * 16 + g, row1 = row0 + 8;
        float b0 = bias[ncol], b1 = bias[ncol + 1];
        float v00 = acc[nt][0] + b0, v01 = acc[nt][1] + b1;
        float v10 = acc[nt][2] + b0, v11 = acc[nt][3] + b1;
        if (ACT == 1) {
            const float k = 0.70710678118654752f;
            v00 = 0.5f * v00 * (1.0f + erff(v00 * k));
            v01 = 0.5f * v01 * (1.0f + erff(v01 * k));
            v10 = 0.5f * v10 * (1.0f + erff(v10 * k));
            v11 = 0.5f * v11 * (1.0f + erff(v11 * k));
        }
        if (RESID) {
            v00 += R[row0 * HID + ncol];  v01 += R[row0 * HID + ncol + 1];
            v10 += R[row1 * HID + ncol];  v11 += R[row1 * HID + ncol + 1];
        }
        if (SUMOUT) {
            float a0 = (row0 < sn ? v00 : 0.0f) + (row1 < sn ? v10 : 0.0f);
            float a1 = (row0 < sn ? v01 : 0.0f) + (row1 < sn ? v11 : 0.0f);
            atomicAdd(&colsum[ncol], a0);
            atomicAdd(&colsum[ncol + 1], a1);
        } else {
            C[row0 * outStride + ncol]     = v00;
            C[row0 * outStride + ncol + 1] = v01;
            C[row1 * outStride + ncol]     = v10;
            C[row1 * outStride + ncol + 1] = v11;
        }
    }
    if (SUMOUT) {
        __syncthreads();
        if (tid < 128) atomicAdd(&g_xsum[tid], (double)colsum[tid]);
    }
}

// ============================================================================
// K1: sine encoding + GEMM  ->  g_eig = eeig[S,129] @ W[129,128] + b
// 32 rows per block, 256 threads; sincosf fuses sin/cos of the same argument.
// ============================================================================
__global__ void __launch_bounds__(256) k_sine_enc(const float* __restrict__ eve,
                                                  const float* __restrict__ W,
                                                  const float* __restrict__ b) {
    __shared__ float ee[32][132];   // 129 used
    const int m0  = blockIdx.x * 32;
    const int tid = threadIdx.x;
    const float kLog = -9.210340371976184f / 128.0f;   // -ln(1e4)/128

    for (int idx = tid; idx < 32 * 64; idx += 256) {
        int r = idx >> 6, i = idx & 63;
        float e  = eve[m0 + r];
        float pe = e * 100.0f * __expf((2.0f * i) * kLog);
        float sv, cv;
        sincosf(pe, &sv, &cv);
        ee[r][1 + i]  = sv;
        ee[r][65 + i] = cv;
    }
    if (tid < 32) ee[tid][0] = eve[m0 + tid];
    __syncthreads();

    const int col  = tid & 127;
    const int half = tid >> 7;     // 0: rows 0-15, 1: rows 16-31
    float acc[16];
#pragma unroll
    for (int r = 0; r < 16; r++) acc[r] = 0.0f;

    for (int k = 0; k < 129; k++) {
        float wv = W[k * HID + col];
#pragma unroll
        for (int r = 0; r < 16; r++) acc[r] = fmaf(ee[half * 16 + r][k], wv, acc[r]);
    }
    float bb = b[col];
#pragma unroll
    for (int r = 0; r < 16; r++)
        g_eig[(m0 + half * 16 + r) * HID + col] = acc[r] + bb;
}

// ============================================================================
// K-prep: per-(head, 64-key tile) image: K hi [key][dim], V^T hi [dim][key],
// plus an all-ones dim row (row 32) so PV MMA emits the softmax denominator.
// grid = (S/KT, NHEADS), 512 threads.
// ============================================================================
__global__ void __launch_bounds__(512) k_prep(const float* __restrict__ qkv) {
    __shared__ __align__(16) __half img[TILE_H];
    const int tid = threadIdx.x;
    const int kb  = blockIdx.x * KT;
    const int h   = blockIdx.y;

    {   // zero entire image (covers pad + rows 33..39)
        uint4 z = make_uint4(0, 0, 0, 0);
        uint4* p = reinterpret_cast<uint4*>(img);
        for (int i = tid; i < TILE_U4; i += 512) p[i] = z;
    }
    __syncthreads();

    for (int i = tid; i < KT * HD; i += 512) {
        int key = i >> 5, d = i & 31;
        const float* base = qkv + (size_t)(kb + key) * 384 + h * HD + d;
        img[key * KROW + d]        = __float2half_rn(base[128]);   // K
        img[KIMG + d * VROW + key] = __float2half_rn(base[256]);   // V^T
    }
    if (tid < KT) img[KIMG + 32 * VROW + tid] = __float2half(1.0f);  // ones row
    __syncthreads();

    uint4* dst = reinterpret_cast<uint4*>(g_kv + (size_t)(h * (S / KT) + blockIdx.x) * TILE_H);
    const uint4* src = reinterpret_cast<const uint4*>(img);
    for (int i = tid; i < TILE_U4; i += 512) dst[i] = src[i];
}

// ============================================================================
// K4a: MMA flash attention partial.
// Scores in log2 domain; P via ex2.approx.f16x2; denominator l via ones-row
// in the PV MMA (5th d-tile). QK 1-term, PV 1-term fp16.
// grid = (S/QT, NHEADS, NKC), block = 256 (8 warps x 16 queries).
// ============================================================================
__global__ void __launch_bounds__(256) k_attn_mma(const float* __restrict__ qkv,
                                                  const int* __restrict__ snp) {
    __shared__ __align__(16) __half tile[2][TILE_H];

    const int tid  = threadIdx.x;
    const int warp = tid >> 5;
    const int lane = tid & 31;
    const int g    = lane >> 2;    // group (row within fragment)
    const int t4   = lane & 3;     // thread-in-group
    const int h    = blockIdx.y;
    const int kc   = blockIdx.z;
    const int sn   = *snp;

    const int qbase = blockIdx.x * QT + warp * 16;
    const int r0 = qbase + g;        // query rows owned by this thread
    const int r1 = r0 + 8;

    const uint32_t sm0 = (uint32_t)__cvta_generic_to_shared(&tile[0][0]);
    const uint32_t sm1 = (uint32_t)__cvta_generic_to_shared(&tile[1][0]);

    // ---- load Q fragments (2 k-steps), fp16 hi only; log2e folded in ----
    uint32_t Q[2][4];
#pragma unroll
    for (int ks = 0; ks < 2; ks++) {
#pragma unroll
        for (int hh = 0; hh < 2; hh++) {     // k-half (+0 / +8)
#pragma unroll
            for (int rr = 0; rr < 2; rr++) { // row g / g+8
                int row = rr ? r1 : r0;
                int d0  = ks * 16 + hh * 8 + 2 * t4;
                float x0 = qkv[row * 384 + h * HD + d0]     * QSCALE;
                float x1 = qkv[row * 384 + h * HD + d0 + 1] * QSCALE;
                Q[ks][hh * 2 + rr] = pack2f(x0, x1);
            }
        }
    }

    float O[5][4];                    // [d-tile][frag]; nt=4 carries l (ones row)
#pragma unroll
    for (int nt = 0; nt < 5; nt++)
#pragma unroll
        for (int i = 0; i < 4; i++) O[nt][i] = 0.0f;
    float m0v = -INFINITY, m1v = -INFINITY;

    const int tile0 = (kc * CHUNK) >> 6;    // first tile index in this chunk

    // prefetch tile 0 into buffer 0
    {
        const uint4* src = reinterpret_cast<const uint4*>(
            g_kv + (size_t)(h * (S / KT) + tile0) * TILE_H);
        for (int i = tid; i < TILE_U4; i += 256)
            cp16(sm0 + i * 16, src + i);
        cp_commit();
    }

    for (int it = 0; it < NT_CH; it++) {
        cp_wait_all();
        __syncthreads();

        // prefetch next tile into the other buffer (overlaps compute below)
        if (it + 1 < NT_CH) {
            const uint4* src = reinterpret_cast<const uint4*>(
                g_kv + (size_t)(h * (S / KT) + tile0 + it + 1) * TILE_H);
            uint32_t dstb = ((it + 1) & 1) ? sm1 : sm0;
            for (int i = tid; i < TILE_U4; i += 256)
                cp16(dstb + i * 16, src + i);
            cp_commit();
        }

        const __half* tl = tile[it & 1];
        const int kb = kc * CHUNK + it * KT;

        // ---- QK^T: 8 n-tiles of 8 keys; Qhi x Khi (1-term) ----
        float Sf[8][4];
#pragma unroll
        for (int nt = 0; nt < 8; nt++) {
#pragma unroll
            for (int i = 0; i < 4; i++) Sf[nt][i] = 0.0f;
            int key = nt * 8 + g;
            const __half* krow = &tl[key * KROW];
#pragma unroll
            for (int ks = 0; ks < 2; ks++) {
                uint32_t bh0 = *reinterpret_cast<const uint32_t*>(&krow[ks * 16 + 2 * t4]);
                uint32_t bh1 = *reinterpret_cast<const uint32_t*>(&krow[ks * 16 + 8 + 2 * t4]);
                mma16816(Sf[nt][0], Sf[nt][1], Sf[nt][2], Sf[nt][3],
                         Q[ks][0], Q[ks][1], Q[ks][2], Q[ks][3], bh0, bh1);
            }
        }

        // ---- mask ----
        if (kb + KT > sn) {
#pragma unroll
            for (int nt = 0; nt < 8; nt++) {
                int k0 = kb + nt * 8 + 2 * t4;
                if (k0     >= sn) { Sf[nt][0] = -INFINITY; Sf[nt][2] = -INFINITY; }
                if (k0 + 1 >= sn) { Sf[nt][1] = -INFINITY; Sf[nt][3] = -INFINITY; }
            }
        }

        // ---- online softmax (log2 domain) ----
        float mx0 = -INFINITY, mx1 = -INFINITY;
#pragma unroll
        for (int nt = 0; nt < 8; nt++) {
            mx0 = fmaxf(mx0, fmaxf(Sf[nt][0], Sf[nt][1]));
            mx1 = fmaxf(mx1, fmaxf(Sf[nt][2], Sf[nt][3]));
        }
#pragma unroll
        for (int o = 1; o <= 2; o <<= 1) {
            mx0 = fmaxf(mx0, __shfl_xor_sync(0xffffffffu, mx0, o));
            mx1 = fmaxf(mx1, __shfl_xor_sync(0xffffffffu, mx1, o));
        }
        float mn0 = fmaxf(m0v, mx0);
        float mn1 = fmaxf(m1v, mx1);
        if (mn0 == -INFINITY) mn0 = 0.0f;   // fully-masked guard
        if (mn1 == -INFINITY) mn1 = 0.0f;
        float c0 = exp2f(m0v - mn0);        // -inf -> 0 on first tile
        float c1 = exp2f(m1v - mn1);
#pragma unroll
        for (int nt = 0; nt < 5; nt++) {    // includes l accumulators (nt=4)
            O[nt][0] *= c0; O[nt][1] *= c0;
            O[nt][2] *= c1; O[nt][3] *= c1;
        }
        m0v = mn0; m1v = mn1;

        uint32_t Ph[4][4];                  // fp16 P fragments via f16x2 EX2
#pragma unroll
        for (int j = 0; j < 4; j++) {       // key-step j covers tiles 2j, 2j+1
#pragma unroll
            for (int tt = 0; tt < 2; tt++) {
                int nt = 2 * j + tt;
                Ph[j][tt * 2]     = exp2h2(Sf[nt][0] - mn0, Sf[nt][1] - mn0);
                Ph[j][tt * 2 + 1] = exp2h2(Sf[nt][2] - mn1, Sf[nt][3] - mn1);
            }
        }

        // ---- PV: 5 d-tiles (incl. ones row) x 4 key-steps, 1-term fp16 ----
#pragma unroll
        for (int nt = 0; nt < 5; nt++) {
            int d = nt * 8 + g;
            const __half* vrow = &tl[KIMG + d * VROW];
#pragma unroll
            for (int ks = 0; ks < 4; ks++) {
                uint32_t bh0 = *reinterpret_cast<const uint32_t*>(&vrow[ks * 16 + 2 * t4]);
                uint32_t bh1 = *reinterpret_cast<const uint32_t*>(&vrow[ks * 16 + 8 + 2 * t4]);
                mma16816(O[nt][0], O[nt][1], O[nt][2], O[nt][3],
                         Ph[ks][0], Ph[ks][1], Ph[ks][2], Ph[ks][3], bh0, bh1);
            }
        }
        __syncthreads();
    }

    // ---- write partials (unnormalized); l lives in O[4] at col 32 (t4==0) ----
    const int p0 = (h * NKC + kc) * S + r0;
    const int p1 = (h * NKC + kc) * S + r1;
    if (t4 == 0) {
        g_pm[p0] = m0v;  g_pl[p0] = O[4][0];
        g_pm[p1] = m1v;  g_pl[p1] = O[4][2];
    }
#pragma unroll
    for (int nt = 0; nt < 4; nt++) {
        int d = nt * 8 + 2 * t4;
        g_po[(size_t)p0 * HD + d]     = O[nt][0];
        g_po[(size_t)p0 * HD + d + 1] = O[nt][1];
        g_po[(size_t)p1 * HD + d]     = O[nt][2];
        g_po[(size_t)p1 * HD + d + 1] = O[nt][3];
    }
}

// ============================================================================
// pooled coefficients (single block)
// ============================================================================
__global__ void __launch_bounds__(128) k_pool(const float* __restrict__ dscW, const float* __restrict__ dscb,
                                              const float* __restrict__ dwvW, const float* __restrict__ dwvb,
                                              const float* __restrict__ dssW, const float* __restrict__ dssb,
                                              const int* __restrict__ lenp, const int* __restrict__ snp) {
    const int tid = threadIdx.x;
    __shared__ float sig[104];
    __shared__ float ssum[2];
    const float lenf = (float)(*lenp);
    const float snf  = (float)(*snp);

    if (tid < 104) {
        const float* W; const float* bb; int c; int NCc;
        if (tid < 50)       { W = dscW; bb = dscb; c = tid;       NCc = NCOE; }
        else if (tid < 100) { W = dwvW; bb = dwvb; c = tid - 50;  NCc = NCOE; }
        else                { W = dssW; bb = dssb; c = tid - 100; NCc = NSCALES; }
        double acc = 0.0;
        for (int k = 0; k < HID; k++) acc += g_xsum[k] * (double)W[k * NCc + c];
        float pooled = (float)((acc + (double)(snf * bb[c])) / (double)(lenf + 1e-8f));
        sig[tid] = 1.0f / (1.0f + expf(-pooled));
    }
    __syncthreads();
    if (tid == 0) { float t = 0.f; for (int i = 0;  i < 50;  i++) t += sig[i]; ssum[0] = t; }
    if (tid == 1) { float t = 0.f; for (int i = 50; i < 100; i++) t += sig[i]; ssum[1] = t; }
    __syncthreads();
    if (tid < 50)       g_coef[tid] = sig[tid] / (ssum[0] + 1e-8f);
    else if (tid < 100) g_coef[tid] = sig[tid] / (ssum[1] + 1e-8f);
    else if (tid < 104) g_coef[tid] = sig[tid] * 5.0f;   // THRE
}

// ============================================================================
// Chebyshev synthesis + L2 normalize  ->  out[S, 5]
// ============================================================================
__global__ void __launch_bounds__(128) k_final(const float* __restrict__ eve,
                                               float* __restrict__ out) {
    __shared__ float cs[NCOE], cw[NCOE], sc[NSCALES];
    const int tid = threadIdx.x;
    if (tid < 50)        cs[tid]       = g_coef[tid];
    else if (tid < 100)  cw[tid - 50]  = g_coef[tid];
    else if (tid < 104)  sc[tid - 100] = g_coef[tid];
    __syncthreads();

    const int s = blockIdx.x * 128 + tid;
    const float e = eve[s];
    float vals[5];

    {   // scaling channel: y = e - 1; coefficients on T_1,T_3,...
        float y  = e - 1.0f;
        float te = 1.0f, to = y;
        float acc = cs[0] * (0.5f * (1.0f - to));
#pragma unroll
        for (int c = 1; c < NCOE; c++) {
            te = 2.0f * y * to - te;          // T_{2c}
            to = 2.0f * y * te - to;          // T_{2c+1}
            acc += cs[c] * (0.5f * (1.0f - to));
        }
        vals[0] = acc;
    }

#pragma unroll
    for (int j = 0; j < NSCALES; j++) {       // wavelet channels: T_0,T_2,...
        float f = e * sc[j];
        if (f > 2.0f) f = 0.0f;
        float y  = f - 1.0f;
        float te = 1.0f, to = y;
        float acc = 0.0f;                      // cw[0] * 0.5*(1-T_0) = 0
#pragma unroll
        for (int c = 1; c < NCOE; c++) {
            te = 2.0f * y * to - te;          // T_{2c}
            acc += cw[c] * (0.5f * (1.0f - te));
            to = 2.0f * y * te - to;          // T_{2c+1}
        }
        vals[1 + j] = acc;
    }

    float n2 = 0.0f;
#pragma unroll
    for (int i = 0; i < 5; i++) n2 += vals[i] * vals[i];
    float inv = 1.0f / (sqrtf(n2) + 1e-8f);
#pragma unroll
    for (int i = 0; i < 5; i++) out[s * 5 + i] = vals[i] * inv;
}

// ============================================================================
// launch
// ============================================================================
extern "C" void kernel_launch(void* const* d_in, const int* in_sizes, int n_in,
                              void* d_out, int out_size) {
    const float* eve      = (const float*)d_in[0];
    const int*   lenp     = (const int*)  d_in[1];
    const int*   snp      = (const int*)  d_in[2];
    const float* eig_w_W  = (const float*)d_in[3];
    const float* eig_w_b  = (const float*)d_in[4];
    const float* mha_ln_g = (const float*)d_in[5];
    const float* mha_ln_b = (const float*)d_in[6];
    const float* in_W     = (const float*)d_in[7];
    const float* in_b     = (const float*)d_in[8];
    const float* out_W    = (const float*)d_in[9];
    const float* out_b    = (const float*)d_in[10];
    const float* ffn_ln_g = (const float*)d_in[11];
    const float* ffn_ln_b = (const float*)d_in[12];
    const float* ffn1_W   = (const float*)d_in[13];
    const float* ffn1_b   = (const float*)d_in[14];
    const float* ffn2_W   = (const float*)d_in[15];
    const float* ffn2_b   = (const float*)d_in[16];
    const float* dsc_W    = (const float*)d_in[17];
    const float* dsc_b    = (const float*)d_in[18];
    const float* dwv_W    = (const float*)d_in[19];
    const float* dwv_b    = (const float*)d_in[20];
    const float* dss_W    = (const float*)d_in[21];
    const float* dss_b    = (const float*)d_in[22];
    float* out = (float*)d_out;

    float *p_eig, *p_qkv, *p_h1;
    cudaGetSymbolAddress((void**)&p_eig,  g_eig);
    cudaGetSymbolAddress((void**)&p_qkv,  g_qkv);
    cudaGetSymbolAddress((void**)&p_h1,   g_h1);

    // 0) weight images + zero xsum
    k_wprep<<<dim3(16, 6), 256>>>(in_W, out_W, ffn1_W, ffn2_W);
    // 1) eig = sine_encoding(eve) @ W + b
    k_sine_enc<<<S / 32, 256>>>(eve, eig_w_W, eig_w_b);
    // 2) qkv = LN(eig) @ in_W + in_b   (MMA, 3 column-blocks via grid.y)
    k_gemm_mma<0, 0, 1, 1, 0, 0><<<dim3(128, 3), 256>>>(p_eig, 0, in_b, nullptr, p_qkv, 384, mha_ln_g, mha_ln_b, nullptr);
    // 3) pre-swizzle K/V tiles (+ones row) to fp16 images
    k_prep<<<dim3(S / KT, NHEADS), 512>>>(p_qkv);
    // 4) attention split-K partials (combine fused into step 5)
    k_attn_mma<<<dim3(S / QT, NHEADS, NKC), 256>>>(p_qkv, snp);
    // 5) eig = eig + combine(partials) @ out_W + out_b   (COMB staging)
    k_gemm_mma<0, 1, 0, 0, 1, 0><<<dim3(128), 256>>>(nullptr, 3, out_b, p_eig, p_eig, 128, nullptr, nullptr, nullptr);
    // 6) h1 = gelu(LN(eig) @ ffn1_W + b)
    k_gemm_mma<1, 0, 1, 0, 0, 0><<<dim3(128), 256>>>(p_eig, 4, ffn1_b, nullptr, p_h1, 128, ffn_ln_g, ffn_ln_b, nullptr);
    // 7) eigf column-sums = sum_rows<sn (eig + h1 @ ffn2_W + b)  (no store)
    k_gemm_mma<0, 1, 0, 0, 0, 1><<<dim3(128), 256>>>(p_h1, 5, ffn2_b, p_eig, nullptr, 128, nullptr, nullptr, snp);
    // 8) pooled coefficients
    k_pool<<<1, 128>>>(dsc_W, dsc_b, dwv_W, dwv_b, dss_W, dss_b, lenp, snp);
    // 9) Chebyshev synthesis + normalize
    k_final<<<S / 128, 128>>>(eve, out);
}

// round 13
// speedup vs baseline: 2.7387x; 1.1425x over previous
#include <cuda_runtime.h>
#include <cuda_fp16.h>
#include <math.h>
#include <stdint.h>

// ---------------- problem constants ----------------
#define S 4096
#define HID 128
#define NHEADS 4
#define HD 32
#define NCOE 50
#define NSCALES 4
#define NKC 2              // split-K chunks for attention
#define CHUNK (S / NKC)    // 2048 keys per chunk
#define QT 128             // queries per block (8 warps x 16)
#define KT 64              // key tile
#define NT_CH (CHUNK / KT) // 32 tiles per chunk

// KV tile image geometry (halves). Padded rows for conflict-free LDS.
#define KROW 40                      // per-key: 32 hi + 8 pad (pad never read)
#define KIMG (KT * KROW)             // 2560 halves
#define VROW 72                      // per-dim: 64 keys + 8 pad
#define VIMG (40 * VROW)             // rows 0..31 = V, 32 = ones, 33..39 = zero
#define TILE_H (KIMG + VIMG)         // 5440 halves = 10880 B
#define TILE_U4 (TILE_H / 8)         // 680 uint4
#define NIMG (NHEADS * (S / KT))     // 256 images
// ones row occupies uint4 slots [608, 616) within each image
#define ONES_LO ((KIMG + 32 * VROW) / 8)
#define ONES_HI (ONES_LO + KT / 8)

// log2(e)/sqrt(32): scores come out of QK in log2 domain
#define QSCALE 0.2550458572864341f

// ---------------- scratch (__device__ globals; no allocs allowed) ----------------
__device__ float  g_eig [S * HID];
__device__ float  g_qkv [S * 3 * HID];   // only Q region (cols 0..127) used now
__device__ float  g_h1  [S * HID];
__device__ __align__(16) __half g_kv[NIMG * TILE_H];  // pre-swizzled K/V tiles
__device__ __align__(16) uint4  g_wf[6 * 4096];   // 6 weight images, fragment-ordered
__device__ float  g_pm  [NHEADS * NKC * S];        // partial max (log2 domain)
__device__ float  g_pl  [NHEADS * NKC * S];        // partial sum
__device__ float  g_po  [NHEADS * NKC * S * HD];   // partial (unnormalized) out
__device__ double g_xsum[HID];
__device__ float  g_coef[128];   // [0:50) scaling, [50:100) wavelet, [100:104) scales

// ---------------- mma / async helpers ----------------
__device__ __forceinline__ void mma16816(float& c0, float& c1, float& c2, float& c3,
                                         uint32_t a0, uint32_t a1, uint32_t a2, uint32_t a3,
                                         uint32_t b0, uint32_t b1) {
    asm volatile("mma.sync.aligned.m16n8k16.row.col.f32.f16.f16.f32 "
                 "{%0,%1,%2,%3}, {%4,%5,%6,%7}, {%8,%9}, {%0,%1,%2,%3};\n"
                 : "+f"(c0), "+f"(c1), "+f"(c2), "+f"(c3)
                 : "r"(a0), "r"(a1), "r"(a2), "r"(a3), "r"(b0), "r"(b1));
}

__device__ __forceinline__ void cp16(uint32_t dst, const void* src) {
    asm volatile("cp.async.cg.shared.global [%0], [%1], 16;\n" :: "r"(dst), "l"(src));
}
__device__ __forceinline__ void cp_commit() {
    asm volatile("cp.async.commit_group;\n");
}
__device__ __forceinline__ void cp_wait_all() {
    asm volatile("cp.async.wait_group 0;\n");
}

__device__ __forceinline__ uint32_t packh2(__half a, __half b) {
    __half2 t = __halves2half2(a, b);     // a -> low half
    return *reinterpret_cast<uint32_t*>(&t);
}

// split x into hi (fp16) and lo (fp16 of remainder)
__device__ __forceinline__ void hsplit(float x, __half& h, __half& l) {
    h = __float2half_rn(x);
    l = __float2half_rn(x - __half2float(h));
}

__device__ __forceinline__ uint32_t pack2f(float x, float y) {
    __half2 t = __floats2half2_rn(x, y);  // x -> low
    return *reinterpret_cast<uint32_t*>(&t);
}

// 2^a, 2^b as packed fp16x2 (one MUFU op for both lanes)
__device__ __forceinline__ uint32_t exp2h2(float a, float b) {
    uint32_t hi = pack2f(a, b);
    uint32_t r;
    asm("ex2.approx.f16x2 %0, %1;" : "=r"(r) : "r"(hi));
    return r;
}

// ============================================================================
// W-prep: fragment-ordered fp16 hi/lo images for all 6 [128,128] weights.
// Also zeroes g_xsum and initializes g_kv static content (zeros + ones rows).
// grid = (16, 6), 256 threads.
// ============================================================================
__global__ void __launch_bounds__(256) k_wprep(const float* __restrict__ inW,
                                               const float* __restrict__ outW,
                                               const float* __restrict__ f1W,
                                               const float* __restrict__ f2W) {
    const int tid  = threadIdx.x;
    if (blockIdx.x == 0 && blockIdx.y == 0 && tid < HID) g_xsum[tid] = 0.0;

    // ---- initialize g_kv static image content (ones rows; zero V pad rows) ----
    {
        const int gthread = (blockIdx.y * 16 + blockIdx.x) * 256 + tid;   // 0..24575
        const uint4 zero4 = make_uint4(0, 0, 0, 0);
        const uint4 ones4 = make_uint4(0x3C003C00u, 0x3C003C00u, 0x3C003C00u, 0x3C003C00u);
        uint4* kvp = reinterpret_cast<uint4*>(g_kv);
        for (int i = gthread; i < NIMG * TILE_U4; i += 96 * 256) {
            int s = i % TILE_U4;
            if (s >= ONES_LO) kvp[i] = (s < ONES_HI) ? ones4 : zero4;
            // data slots (K rows, V rows 0..31) are overwritten by the qkv GEMM
            else if (s >= KIMG / 8 + 32 * (VROW / 8) || s < 0) kvp[i] = zero4;
        }
    }

    const int lane = tid & 31;
    const int g    = lane >> 2;
    const int t4   = lane & 3;
    const int wid  = blockIdx.x * 8 + (tid >> 5);   // fragment id 0..127
    const int nt   = wid >> 3;
    const int ks   = wid & 7;

    const float* W; int ldw, c0;
    switch (blockIdx.y) {
        case 0:  W = inW;  ldw = 384; c0 = 0;   break;
        case 1:  W = inW;  ldw = 384; c0 = 128; break;
        case 2:  W = inW;  ldw = 384; c0 = 256; break;
        case 3:  W = outW; ldw = 128; c0 = 0;   break;
        case 4:  W = f1W;  ldw = 128; c0 = 0;   break;
        default: W = f2W;  ldw = 128; c0 = 0;   break;
    }

    const int n  = nt * 8 + g;
    const int k0 = ks * 16 + 2 * t4;
    float w00 = W[(k0    ) * ldw + c0 + n];
    float w01 = W[(k0 + 1) * ldw + c0 + n];
    float w80 = W[(k0 + 8) * ldw + c0 + n];
    float w81 = W[(k0 + 9) * ldw + c0 + n];
    __half h00, l00, h01, l01, h80, l80, h81, l81;
    hsplit(w00, h00, l00);  hsplit(w01, h01, l01);
    hsplit(w80, h80, l80);  hsplit(w81, h81, l81);
    uint4 f;
    f.x = packh2(h00, h01);
    f.y = packh2(h80, h81);
    f.z = packh2(l00, l01);
    f.w = packh2(l80, l81);
    g_wf[blockIdx.y * 4096 + wid * 32 + lane] = f;
}

// ============================================================================
// MMA GEMM: C[:, c0:c0+128] = act( X @ Wimg + bias ) (+ R)
// X = A (optionally LayerNormed) or the split-K attention combine (COMB).
// 2-term: Ah*Wh + Ah*Wl (A staged hi-only; W images carry hi+lo).
// KVOUT: blockIdx.y==1/2 write results as fp16 into the g_kv attention images.
// SUMOUT: skip store; accumulate masked column sums into g_xsum.
// grid = (128, MULTI?3:1), 256 threads (8 warps). 32 rows per block.
// ============================================================================
template <int ACT, int RESID, int LNORM, int MULTI, int COMB, int SUMOUT, int KVOUT>
__global__ void __launch_bounds__(256) k_gemm_mma(const float* __restrict__ A,
                                                  int img0,
                                                  const float* __restrict__ bias,
                                                  const float* __restrict__ R,
                                                  float* __restrict__ C,
                                                  int outStride,
                                                  const float* __restrict__ lng,
                                                  const float* __restrict__ lnb,
                                                  const int* __restrict__ snp) {
    __shared__ __align__(16) __half Ahi[32 * 136];
    __shared__ float colsum[128];
    const int tid = threadIdx.x;
    const int m0  = blockIdx.x * 32;
    const int c0  = MULTI ? blockIdx.y * 128 : 0;
    const int img = img0 + (MULTI ? blockIdx.y : 0);

    // ---- stage X tile (plain / LN / attention-combine), fp16 hi ----
    {
        const int r = tid >> 3, l8 = tid & 7;
        float x[16];
        if (COMB) {
            // split-K combine: head = l8>>1, dims (l8&1)*16 .. +16
            const int row    = m0 + r;
            const int head   = l8 >> 1;
            const int hd_off = (l8 & 1) * 16;
            float M = -INFINITY;
#pragma unroll
            for (int kc = 0; kc < NKC; kc++)
                M = fmaxf(M, g_pm[(head * NKC + kc) * S + row]);
#pragma unroll
            for (int j = 0; j < 16; j++) x[j] = 0.0f;
            float L = 0.0f;
#pragma unroll
            for (int kc = 0; kc < NKC; kc++) {
                const int p = (head * NKC + kc) * S + row;
                float li = g_pl[p];
                if (li > 0.0f) {
                    float w = exp2f(g_pm[p] - M);
                    L += li * w;
                    const float4* po = reinterpret_cast<const float4*>(&g_po[(size_t)p * HD + hd_off]);
#pragma unroll
                    for (int jj = 0; jj < 4; jj++) {
                        float4 v = po[jj];
                        x[jj * 4 + 0] = fmaf(w, v.x, x[jj * 4 + 0]);
                        x[jj * 4 + 1] = fmaf(w, v.y, x[jj * 4 + 1]);
                        x[jj * 4 + 2] = fmaf(w, v.z, x[jj * 4 + 2]);
                        x[jj * 4 + 3] = fmaf(w, v.w, x[jj * 4 + 3]);
                    }
                }
            }
            float inv = (L > 0.0f) ? 1.0f / L : 0.0f;
#pragma unroll
            for (int j = 0; j < 16; j++) x[j] *= inv;
        } else {
            const float4* ap = reinterpret_cast<const float4*>(A + (m0 + r) * HID + l8 * 16);
#pragma unroll
            for (int j = 0; j < 4; j++) {
                float4 v = ap[j];
                x[j * 4 + 0] = v.x; x[j * 4 + 1] = v.y;
                x[j * 4 + 2] = v.z; x[j * 4 + 3] = v.w;
            }
        }
        if (LNORM) {
            float s = 0.0f, s2 = 0.0f;
#pragma unroll
            for (int j = 0; j < 16; j++) { s += x[j]; s2 += x[j] * x[j]; }
#pragma unroll
            for (int o = 4; o; o >>= 1) {
                s  += __shfl_xor_sync(0xffffffffu, s,  o);
                s2 += __shfl_xor_sync(0xffffffffu, s2, o);
            }
            float mean = s * (1.0f / HID);
            float rstd = rsqrtf(s2 * (1.0f / HID) - mean * mean + 1e-5f);
#pragma unroll
            for (int j = 0; j < 16; j++) {
                int col = l8 * 16 + j;
                x[j] = (x[j] - mean) * rstd * lng[col] + lnb[col];
            }
        }
        uint32_t phi[8];
#pragma unroll
        for (int j = 0; j < 8; j++)
            phi[j] = pack2f(x[2 * j], x[2 * j + 1]);
        uint4* dhi = reinterpret_cast<uint4*>(&Ahi[r * 136 + l8 * 16]);
        dhi[0] = make_uint4(phi[0], phi[1], phi[2], phi[3]);
        dhi[1] = make_uint4(phi[4], phi[5], phi[6], phi[7]);
    }
    if (SUMOUT && tid < 128) colsum[tid] = 0.0f;
    __syncthreads();

    // ---- main MMA loop (2-term) ----
    const int warp = tid >> 5, lane = tid & 31;
    const int g = lane >> 2, t4 = lane & 3;
    const int mt = warp & 1, ch = warp >> 1;
    const uint4* img_p = &g_wf[(size_t)img * 4096];

    float acc[4][4];
#pragma unroll
    for (int nt = 0; nt < 4; nt++)
#pragma unroll
        for (int i = 0; i < 4; i++) acc[nt][i] = 0.0f;

    const __half* ahb = &Ahi[(mt * 16 + g) * 136];

#pragma unroll
    for (int ks = 0; ks < 8; ks++) {
        const int co = ks * 16 + 2 * t4;
        uint32_t ah0 = *reinterpret_cast<const uint32_t*>(&ahb[co]);
        uint32_t ah1 = *reinterpret_cast<const uint32_t*>(&ahb[8 * 136 + co]);
        uint32_t ah2 = *reinterpret_cast<const uint32_t*>(&ahb[co + 8]);
        uint32_t ah3 = *reinterpret_cast<const uint32_t*>(&ahb[8 * 136 + co + 8]);
#pragma unroll
        for (int nt = 0; nt < 4; nt++) {
            uint4 f = img_p[((4 * ch + nt) * 8 + ks) * 32 + lane];
            mma16816(acc[nt][0], acc[nt][1], acc[nt][2], acc[nt][3],
                     ah0, ah1, ah2, ah3, f.x, f.y);
            mma16816(acc[nt][0], acc[nt][1], acc[nt][2], acc[nt][3],
                     ah0, ah1, ah2, ah3, f.z, f.w);
        }
    }

    // ---- epilogue ----
    const int sn = SUMOUT ? *snp : 0;
#pragma unroll
    for (int nt = 0; nt < 4; nt++) {
        const int ncol = c0 + (4 * ch + nt) * 8 + 2 * t4;
        const int row0 = m0 + mt * 16 + g, row1 = row0 + 8;
        float b0 = bias[ncol], b1 = bias[ncol + 1];
        float v00 = acc[nt][0] + b0, v01 = acc[nt][1] + b1;
        float v10 = acc[nt][2] + b0, v11 = acc[nt][3] + b1;
        if (ACT == 1) {
            const float k = 0.70710678118654752f;
            v00 = 0.5f * v00 * (1.0f + erff(v00 * k));
            v01 = 0.5f * v01 * (1.0f + erff(v01 * k));
            v10 = 0.5f * v10 * (1.0f + erff(v10 * k));
            v11 = 0.5f * v11 * (1.0f + erff(v11 * k));
        }
        if (RESID) {
            v00 += R[row0 * HID + ncol];  v01 += R[row0 * HID + ncol + 1];
            v10 += R[row1 * HID + ncol];  v11 += R[row1 * HID + ncol + 1];
        }
        if (SUMOUT) {
            float a0 = (row0 < sn ? v00 : 0.0f) + (row1 < sn ? v10 : 0.0f);
            float a1 = (row0 < sn ? v01 : 0.0f) + (row1 < sn ? v11 : 0.0f);
            atomicAdd(&colsum[ncol], a0);
            atomicAdd(&colsum[ncol + 1], a1);
        } else if (KVOUT && blockIdx.y > 0) {
            // K (y==1) / V (y==2) written as fp16 into the attention image
            const int lc   = ncol - c0;         // local col 0..127
            const int head = lc >> 5, d = lc & 31;
            const size_t base = (size_t)(head * (S / KT) + (row0 >> 6)) * TILE_H;
            const int key0 = row0 & 63, key1 = row1 & 63;
            if (blockIdx.y == 1) {
                *reinterpret_cast<__half2*>(&g_kv[base + key0 * KROW + d]) =
                    __floats2half2_rn(v00, v01);
                *reinterpret_cast<__half2*>(&g_kv[base + key1 * KROW + d]) =
                    __floats2half2_rn(v10, v11);
            } else {
                g_kv[base + KIMG + d * VROW + key0]       = __float2half_rn(v00);
                g_kv[base + KIMG + (d + 1) * VROW + key0] = __float2half_rn(v01);
                g_kv[base + KIMG + d * VROW + key1]       = __float2half_rn(v10);
                g_kv[base + KIMG + (d + 1) * VROW + key1] = __float2half_rn(v11);
            }
        } else {
            C[row0 * outStride + ncol]     = v00;
            C[row0 * outStride + ncol + 1] = v01;
            C[row1 * outStride + ncol]     = v10;
            C[row1 * outStride + ncol + 1] = v11;
        }
    }
    if (SUMOUT) {
        __syncthreads();
        if (tid < 128) atomicAdd(&g_xsum[tid], (double)colsum[tid]);
    }
}

// ============================================================================
// K1: sine encoding + GEMM  ->  g_eig = eeig[S,129] @ W[129,128] + b
// 16 rows per block, 256 threads (each thread: 8 rows of one column).
// ============================================================================
__global__ void __launch_bounds__(256) k_sine_enc(const float* __restrict__ eve,
                                                  const float* __restrict__ W,
                                                  const float* __restrict__ b) {
    __shared__ float ee[16][132];   // 129 used
    const int m0  = blockIdx.x * 16;
    const int tid = threadIdx.x;
    const float kLog = -9.210340371976184f / 128.0f;   // -ln(1e4)/128

    for (int idx = tid; idx < 16 * 64; idx += 256) {
        int r = idx >> 6, i = idx & 63;
        float e  = eve[m0 + r];
        float pe = e * 100.0f * __expf((2.0f * i) * kLog);
        float sv, cv;
        sincosf(pe, &sv, &cv);
        ee[r][1 + i]  = sv;
        ee[r][65 + i] = cv;
    }
    if (tid < 16) ee[tid][0] = eve[m0 + tid];
    __syncthreads();

    const int col  = tid & 127;
    const int half = tid >> 7;     // 0: rows 0-7, 1: rows 8-15
    float acc[8];
#pragma unroll
    for (int r = 0; r < 8; r++) acc[r] = 0.0f;

    for (int k = 0; k < 129; k++) {
        float wv = W[k * HID + col];
#pragma unroll
        for (int r = 0; r < 8; r++) acc[r] = fmaf(ee[half * 8 + r][k], wv, acc[r]);
    }
    float bb = b[col];
#pragma unroll
    for (int r = 0; r < 8; r++)
        g_eig[(m0 + half * 8 + r) * HID + col] = acc[r] + bb;
}

// ============================================================================
// K4a: MMA flash attention partial.
// Scores in log2 domain; P via ex2.approx.f16x2; denominator l via ones-row
// in the PV MMA (5th d-tile). QK 1-term, PV 1-term fp16.
// grid = (S/QT, NHEADS, NKC), block = 256 (8 warps x 16 queries).
// ============================================================================
__global__ void __launch_bounds__(256) k_attn_mma(const float* __restrict__ qkv,
                                                  const int* __restrict__ snp) {
    __shared__ __align__(16) __half tile[2][TILE_H];

    const int tid  = threadIdx.x;
    const int warp = tid >> 5;
    const int lane = tid & 31;
    const int g    = lane >> 2;    // group (row within fragment)
    const int t4   = lane & 3;     // thread-in-group
    const int h    = blockIdx.y;
    const int kc   = blockIdx.z;
    const int sn   = *snp;

    const int qbase = blockIdx.x * QT + warp * 16;
    const int r0 = qbase + g;        // query rows owned by this thread
    const int r1 = r0 + 8;

    const uint32_t sm0 = (uint32_t)__cvta_generic_to_shared(&tile[0][0]);
    const uint32_t sm1 = (uint32_t)__cvta_generic_to_shared(&tile[1][0]);

    // ---- load Q fragments (2 k-steps), fp16 hi only; log2e folded in ----
    uint32_t Q[2][4];
#pragma unroll
    for (int ks = 0; ks < 2; ks++) {
#pragma unroll
        for (int hh = 0; hh < 2; hh++) {     // k-half (+0 / +8)
#pragma unroll
            for (int rr = 0; rr < 2; rr++) { // row g / g+8
                int row = rr ? r1 : r0;
                int d0  = ks * 16 + hh * 8 + 2 * t4;
                float x0 = qkv[row * 384 + h * HD + d0]     * QSCALE;
                float x1 = qkv[row * 384 + h * HD + d0 + 1] * QSCALE;
                Q[ks][hh * 2 + rr] = pack2f(x0, x1);
            }
        }
    }

    float O[5][4];                    // [d-tile][frag]; nt=4 carries l (ones row)
#pragma unroll
    for (int nt = 0; nt < 5; nt++)
#pragma unroll
        for (int i = 0; i < 4; i++) O[nt][i] = 0.0f;
    float m0v = -INFINITY, m1v = -INFINITY;

    const int tile0 = (kc * CHUNK) >> 6;    // first tile index in this chunk

    // prefetch tile 0 into buffer 0
    {
        const uint4* src = reinterpret_cast<const uint4*>(
            g_kv + (size_t)(h * (S / KT) + tile0) * TILE_H);
        for (int i = tid; i < TILE_U4; i += 256)
            cp16(sm0 + i * 16, src + i);
        cp_commit();
    }

    for (int it = 0; it < NT_CH; it++) {
        cp_wait_all();
        __syncthreads();

        // prefetch next tile into the other buffer (overlaps compute below)
        if (it + 1 < NT_CH) {
            const uint4* src = reinterpret_cast<const uint4*>(
                g_kv + (size_t)(h * (S / KT) + tile0 + it + 1) * TILE_H);
            uint32_t dstb = ((it + 1) & 1) ? sm1 : sm0;
            for (int i = tid; i < TILE_U4; i += 256)
                cp16(dstb + i * 16, src + i);
            cp_commit();
        }

        const __half* tl = tile[it & 1];
        const int kb = kc * CHUNK + it * KT;

        // ---- QK^T: 8 n-tiles of 8 keys; Qhi x Khi (1-term) ----
        float Sf[8][4];
#pragma unroll
        for (int nt = 0; nt < 8; nt++) {
#pragma unroll
            for (int i = 0; i < 4; i++) Sf[nt][i] = 0.0f;
            int key = nt * 8 + g;
            const __half* krow = &tl[key * KROW];
#pragma unroll
            for (int ks = 0; ks < 2; ks++) {
                uint32_t bh0 = *reinterpret_cast<const uint32_t*>(&krow[ks * 16 + 2 * t4]);
                uint32_t bh1 = *reinterpret_cast<const uint32_t*>(&krow[ks * 16 + 8 + 2 * t4]);
                mma16816(Sf[nt][0], Sf[nt][1], Sf[nt][2], Sf[nt][3],
                         Q[ks][0], Q[ks][1], Q[ks][2], Q[ks][3], bh0, bh1);
            }
        }

        // ---- mask ----
        if (kb + KT > sn) {
#pragma unroll
            for (int nt = 0; nt < 8; nt++) {
                int k0 = kb + nt * 8 + 2 * t4;
                if (k0     >= sn) { Sf[nt][0] = -INFINITY; Sf[nt][2] = -INFINITY; }
                if (k0 + 1 >= sn) { Sf[nt][1] = -INFINITY; Sf[nt][3] = -INFINITY; }
            }
        }

        // ---- online softmax (log2 domain) ----
        float mx0 = -INFINITY, mx1 = -INFINITY;
#pragma unroll
        for (int nt = 0; nt < 8; nt++) {
            mx0 = fmaxf(mx0, fmaxf(Sf[nt][0], Sf[nt][1]));
            mx1 = fmaxf(mx1, fmaxf(Sf[nt][2], Sf[nt][3]));
        }
#pragma unroll
        for (int o = 1; o <= 2; o <<= 1) {
            mx0 = fmaxf(mx0, __shfl_xor_sync(0xffffffffu, mx0, o));
            mx1 = fmaxf(mx1, __shfl_xor_sync(0xffffffffu, mx1, o));
        }
        float mn0 = fmaxf(m0v, mx0);
        float mn1 = fmaxf(m1v, mx1);
        if (mn0 == -INFINITY) mn0 = 0.0f;   // fully-masked guard
        if (mn1 == -INFINITY) mn1 = 0.0f;
        float c0 = exp2f(m0v - mn0);        // -inf -> 0 on first tile
        float c1 = exp2f(m1v - mn1);
        if (c0 != 1.0f || c1 != 1.0f) {     // skip rescale when max unchanged
#pragma unroll
            for (int nt = 0; nt < 5; nt++) {
                O[nt][0] *= c0; O[nt][1] *= c0;
                O[nt][2] *= c1; O[nt][3] *= c1;
            }
        }
        m0v = mn0; m1v = mn1;

        uint32_t Ph[4][4];                  // fp16 P fragments via f16x2 EX2
#pragma unroll
        for (int j = 0; j < 4; j++) {       // key-step j covers tiles 2j, 2j+1
#pragma unroll
            for (int tt = 0; tt < 2; tt++) {
                int nt = 2 * j + tt;
                Ph[j][tt * 2]     = exp2h2(Sf[nt][0] - mn0, Sf[nt][1] - mn0);
                Ph[j][tt * 2 + 1] = exp2h2(Sf[nt][2] - mn1, Sf[nt][3] - mn1);
            }
        }

        // ---- PV: 5 d-tiles (incl. ones row) x 4 key-steps, 1-term fp16 ----
#pragma unroll
        for (int nt = 0; nt < 5; nt++) {
            int d = nt * 8 + g;
            const __half* vrow = &tl[KIMG + d * VROW];
#pragma unroll
            for (int ks = 0; ks < 4; ks++) {
                uint32_t bh0 = *reinterpret_cast<const uint32_t*>(&vrow[ks * 16 + 2 * t4]);
                uint32_t bh1 = *reinterpret_cast<const uint32_t*>(&vrow[ks * 16 + 8 + 2 * t4]);
                mma16816(O[nt][0], O[nt][1], O[nt][2], O[nt][3],
                         Ph[ks][0], Ph[ks][1], Ph[ks][2], Ph[ks][3], bh0, bh1);
            }
        }
        __syncthreads();
    }

    // ---- write partials (unnormalized); l lives in O[4] at col 32 (t4==0) ----
    const int p0 = (h * NKC + kc) * S + r0;
    const int p1 = (h * NKC + kc) * S + r1;
    if (t4 == 0) {
        g_pm[p0] = m0v;  g_pl[p0] = O[4][0];
        g_pm[p1] = m1v;  g_pl[p1] = O[4][2];
    }
#pragma unroll
    for (int nt = 0; nt < 4; nt++) {
        int d = nt * 8 + 2 * t4;
        g_po[(size_t)p0 * HD + d]     = O[nt][0];
        g_po[(size_t)p0 * HD + d + 1] = O[nt][1];
        g_po[(size_t)p1 * HD + d]     = O[nt][2];
        g_po[(size_t)p1 * HD + d + 1] = O[nt][3];
    }
}

// ============================================================================
// pooled coefficients (single block)
// ============================================================================
__global__ void __launch_bounds__(128) k_pool(const float* __restrict__ dscW, const float* __restrict__ dscb,
                                              const float* __restrict__ dwvW, const float* __restrict__ dwvb,
                                              const float* __restrict__ dssW, const float* __restrict__ dssb,
                                              const int* __restrict__ lenp, const int* __restrict__ snp) {
    const int tid = threadIdx.x;
    __shared__ float sig[104];
    __shared__ float ssum[2];
    const float lenf = (float)(*lenp);
    const float snf  = (float)(*snp);

    if (tid < 104) {
        const float* W; const float* bb; int c; int NCc;
        if (tid < 50)       { W = dscW; bb = dscb; c = tid;       NCc = NCOE; }
        else if (tid < 100) { W = dwvW; bb = dwvb; c = tid - 50;  NCc = NCOE; }
        else                { W = dssW; bb = dssb; c = tid - 100; NCc = NSCALES; }
        double acc = 0.0;
        for (int k = 0; k < HID; k++) acc += g_xsum[k] * (double)W[k * NCc + c];
        float pooled = (float)((acc + (double)(snf * bb[c])) / (double)(lenf + 1e-8f));
        sig[tid] = 1.0f / (1.0f + expf(-pooled));
    }
    __syncthreads();
    if (tid == 0) { float t = 0.f; for (int i = 0;  i < 50;  i++) t += sig[i]; ssum[0] = t; }
    if (tid == 1) { float t = 0.f; for (int i = 50; i < 100; i++) t += sig[i]; ssum[1] = t; }
    __syncthreads();
    if (tid < 50)       g_coef[tid] = sig[tid] / (ssum[0] + 1e-8f);
    else if (tid < 100) g_coef[tid] = sig[tid] / (ssum[1] + 1e-8f);
    else if (tid < 104) g_coef[tid] = sig[tid] * 5.0f;   // THRE
}

// ============================================================================
// Chebyshev synthesis + L2 normalize  ->  out[S, 5]
// ============================================================================
__global__ void __launch_bounds__(128) k_final(const float* __restrict__ eve,
                                               float* __restrict__ out) {
    __shared__ float cs[NCOE], cw[NCOE], sc[NSCALES];
    const int tid = threadIdx.x;
    if (tid < 50)        cs[tid]       = g_coef[tid];
    else if (tid < 100)  cw[tid - 50]  = g_coef[tid];
    else if (tid < 104)  sc[tid - 100] = g_coef[tid];
    __syncthreads();

    const int s = blockIdx.x * 128 + tid;
    const float e = eve[s];
    float vals[5];

    {   // scaling channel: y = e - 1; coefficients on T_1,T_3,...
        float y  = e - 1.0f;
        float te = 1.0f, to = y;
        float acc = cs[0] * (0.5f * (1.0f - to));
#pragma unroll
        for (int c = 1; c < NCOE; c++) {
            te = 2.0f * y * to - te;          // T_{2c}
            to = 2.0f * y * te - to;          // T_{2c+1}
            acc += cs[c] * (0.5f * (1.0f - to));
        }
        vals[0] = acc;
    }

#pragma unroll
    for (int j = 0; j < NSCALES; j++) {       // wavelet channels: T_0,T_2,...
        float f = e * sc[j];
        if (f > 2.0f) f = 0.0f;
        float y  = f - 1.0f;
        float te = 1.0f, to = y;
        float acc = 0.0f;                      // cw[0] * 0.5*(1-T_0) = 0
#pragma unroll
        for (int c = 1; c < NCOE; c++) {
            te = 2.0f * y * to - te;          // T_{2c}
            acc += cw[c] * (0.5f * (1.0f - te));
            to = 2.0f * y * te - to;          // T_{2c+1}
        }
        vals[1 + j] = acc;
    }

    float n2 = 0.0f;
#pragma unroll
    for (int i = 0; i < 5; i++) n2 += vals[i] * vals[i];
    float inv = 1.0f / (sqrtf(n2) + 1e-8f);
#pragma unroll
    for (int i = 0; i < 5; i++) out[s * 5 + i] = vals[i] * inv;
}

// ============================================================================
// launch
// ============================================================================
extern "C" void kernel_launch(void* const* d_in, const int* in_sizes, int n_in,
                              void* d_out, int out_size) {
    const float* eve      = (const float*)d_in[0];
    const int*   lenp     = (const int*)  d_in[1];
    const int*   snp      = (const int*)  d_in[2];
    const float* eig_w_W  = (const float*)d_in[3];
    const float* eig_w_b  = (const float*)d_in[4];
    const float* mha_ln_g = (const float*)d_in[5];
    const float* mha_ln_b = (const float*)d_in[6];
    const float* in_W     = (const float*)d_in[7];
    const float* in_b     = (const float*)d_in[8];
    const float* out_W    = (const float*)d_in[9];
    const float* out_b    = (const float*)d_in[10];
    const float* ffn_ln_g = (const float*)d_in[11];
    const float* ffn_ln_b = (const float*)d_in[12];
    const float* ffn1_W   = (const float*)d_in[13];
    const float* ffn1_b   = (const float*)d_in[14];
    const float* ffn2_W   = (const float*)d_in[15];
    const float* ffn2_b   = (const float*)d_in[16];
    const float* dsc_W    = (const float*)d_in[17];
    const float* dsc_b    = (const float*)d_in[18];
    const float* dwv_W    = (const float*)d_in[19];
    const float* dwv_b    = (const float*)d_in[20];
    const float* dss_W    = (const float*)d_in[21];
    const float* dss_b    = (const float*)d_in[22];
    float* out = (float*)d_out;

    float *p_eig, *p_qkv, *p_h1;
    cudaGetSymbolAddress((void**)&p_eig,  g_eig);
    cudaGetSymbolAddress((void**)&p_qkv,  g_qkv);
    cudaGetSymbolAddress((void**)&p_h1,   g_h1);

    // 0) weight images + zero xsum + static g_kv content (ones rows, pads)
    k_wprep<<<dim3(16, 6), 256>>>(in_W, out_W, ffn1_W, ffn2_W);
    // 1) eig = sine_encoding(eve) @ W + b
    k_sine_enc<<<S / 16, 256>>>(eve, eig_w_W, eig_w_b);
    // 2) qkv: Q -> float g_qkv; K/V -> fp16 g_kv images directly (KVOUT)
    k_gemm_mma<0, 0, 1, 1, 0, 0, 1><<<dim3(128, 3), 256>>>(p_eig, 0, in_b, nullptr, p_qkv, 384, mha_ln_g, mha_ln_b, nullptr);
    // 3) attention split-K partials (combine fused into step 4)
    k_attn_mma<<<dim3(S / QT, NHEADS, NKC), 256>>>(p_qkv, snp);
    // 4) eig = eig + combine(partials) @ out_W + out_b   (COMB staging)
    k_gemm_mma<0, 1, 0, 0, 1, 0, 0><<<dim3(128), 256>>>(nullptr, 3, out_b, p_eig, p_eig, 128, nullptr, nullptr, nullptr);
    // 5) h1 = gelu(LN(eig) @ ffn1_W + b)
    k_gemm_mma<1, 0, 1, 0, 0, 0, 0><<<dim3(128), 256>>>(p_eig, 4, ffn1_b, nullptr, p_h1, 128, ffn_ln_g, ffn_ln_b, nullptr);
    // 6) eigf column-sums = sum_rows<sn (eig + h1 @ ffn2_W + b)  (no store)
    k_gemm_mma<0, 1, 0, 0, 0, 1, 0><<<dim3(128), 256>>>(p_h1, 5, ffn2_b, p_eig, nullptr, 128, nullptr, nullptr, snp);
    // 7) pooled coefficients
    k_pool<<<1, 128>>>(dsc_W, dsc_b, dwv_W, dwv_b, dss_W, dss_b, lenp, snp);
    // 8) Chebyshev synthesis + normalize
    k_final<<<S / 128, 128>>>(eve, out);
}

// round 14
// speedup vs baseline: 2.9959x; 1.0939x over previous
#include <cuda_runtime.h>
#include <cuda_fp16.h>
#include <math.h>
#include <stdint.h>

// ---------------- problem constants ----------------
#define S 4096
#define HID 128
#define NHEADS 4
#define HD 32
#define NCOE 50
#define NSCALES 4
#define NKC 2              // split-K chunks for attention
#define CHUNK (S / NKC)    // 2048 keys per chunk
#define QT 128             // queries per block (8 warps x 16)
#define KT 64              // key tile
#define NT_CH (CHUNK / KT) // 32 tiles per chunk

// KV tile image geometry (halves). Padded rows for conflict-free LDS/LDSM.
#define KROW 40                      // per-key: 32 hi + 8 pad (pad never read)
#define KIMG (KT * KROW)             // 2560 halves
#define VROW 72                      // per-dim: 64 keys + 8 pad
#define VIMG (40 * VROW)             // rows 0..31 = V, 32 = ones, 33..39 = zero
#define TILE_H (KIMG + VIMG)         // 5440 halves = 10880 B
#define TILE_U4 (TILE_H / 8)         // 680 uint4
#define NIMG (NHEADS * (S / KT))     // 256 images
// ones row occupies uint4 slots [608, 616) within each image
#define ONES_LO ((KIMG + 32 * VROW) / 8)
#define ONES_HI (ONES_LO + KT / 8)

// log2(e)/sqrt(32): scores come out of QK in log2 domain
#define QSCALE 0.2550458572864341f

// ---------------- scratch (__device__ globals; no allocs allowed) ----------------
__device__ float  g_eig [S * HID];
__device__ float  g_qkv [S * 3 * HID];   // only Q region (cols 0..127) used now
__device__ float  g_h1  [S * HID];
__device__ __align__(16) __half g_kv[NIMG * TILE_H];  // pre-swizzled K/V tiles
__device__ __align__(16) uint4  g_wf[6 * 4096];   // 6 weight images, fragment-ordered
__device__ float  g_pl  [NHEADS * NKC * S];        // partial sum (fixed-ref softmax)
__device__ float  g_po  [NHEADS * NKC * S * HD];   // partial (unnormalized) out
__device__ double g_xsum[HID];
__device__ float  g_coef[128];   // [0:50) scaling, [50:100) wavelet, [100:104) scales

// ---------------- mma / async helpers ----------------
__device__ __forceinline__ void mma16816(float& c0, float& c1, float& c2, float& c3,
                                         uint32_t a0, uint32_t a1, uint32_t a2, uint32_t a3,
                                         uint32_t b0, uint32_t b1) {
    asm volatile("mma.sync.aligned.m16n8k16.row.col.f32.f16.f16.f32 "
                 "{%0,%1,%2,%3}, {%4,%5,%6,%7}, {%8,%9}, {%0,%1,%2,%3};\n"
                 : "+f"(c0), "+f"(c1), "+f"(c2), "+f"(c3)
                 : "r"(a0), "r"(a1), "r"(a2), "r"(a3), "r"(b0), "r"(b1));
}

__device__ __forceinline__ void ldm_x4(uint32_t& d0, uint32_t& d1, uint32_t& d2, uint32_t& d3,
                                       uint32_t addr) {
    asm volatile("ldmatrix.sync.aligned.m8n8.x4.shared.b16 {%0,%1,%2,%3}, [%4];\n"
                 : "=r"(d0), "=r"(d1), "=r"(d2), "=r"(d3) : "r"(addr));
}

__device__ __forceinline__ void cp16(uint32_t dst, const void* src) {
    asm volatile("cp.async.cg.shared.global [%0], [%1], 16;\n" :: "r"(dst), "l"(src));
}
__device__ __forceinline__ void cp_commit() {
    asm volatile("cp.async.commit_group;\n");
}
__device__ __forceinline__ void cp_wait_all() {
    asm volatile("cp.async.wait_group 0;\n");
}

__device__ __forceinline__ uint32_t packh2(__half a, __half b) {
    __half2 t = __halves2half2(a, b);     // a -> low half
    return *reinterpret_cast<uint32_t*>(&t);
}

// split x into hi (fp16) and lo (fp16 of remainder)
__device__ __forceinline__ void hsplit(float x, __half& h, __half& l) {
    h = __float2half_rn(x);
    l = __float2half_rn(x - __half2float(h));
}

__device__ __forceinline__ uint32_t pack2f(float x, float y) {
    __half2 t = __floats2half2_rn(x, y);  // x -> low
    return *reinterpret_cast<uint32_t*>(&t);
}

// 2^a, 2^b as packed fp16x2, clamped at 14.0 (2^14 < fp16 max). -inf -> 0.
__device__ __forceinline__ uint32_t exp2h2c(float a, float b) {
    uint32_t p = pack2f(a, b);
    uint32_t c, r;
    asm("min.f16x2 %0, %1, %2;" : "=r"(c) : "r"(p), "r"(0x4B004B00u));  // 14.0|14.0
    asm("ex2.approx.f16x2 %0, %1;" : "=r"(r) : "r"(c));
    return r;
}

// ============================================================================
// W-prep: fragment-ordered fp16 hi/lo images for all 6 [128,128] weights.
// Also zeroes g_xsum and initializes g_kv static content (zeros + ones rows).
// grid = (16, 6), 256 threads.
// ============================================================================
__global__ void __launch_bounds__(256) k_wprep(const float* __restrict__ inW,
                                               const float* __restrict__ outW,
                                               const float* __restrict__ f1W,
                                               const float* __restrict__ f2W) {
    const int tid  = threadIdx.x;
    if (blockIdx.x == 0 && blockIdx.y == 0 && tid < HID) g_xsum[tid] = 0.0;

    // ---- initialize g_kv static image content (ones rows; zero pad rows) ----
    {
        const int gthread = (blockIdx.y * 16 + blockIdx.x) * 256 + tid;   // 0..24575
        const uint4 zero4 = make_uint4(0, 0, 0, 0);
        const uint4 ones4 = make_uint4(0x3C003C00u, 0x3C003C00u, 0x3C003C00u, 0x3C003C00u);
        uint4* kvp = reinterpret_cast<uint4*>(g_kv);
        for (int i = gthread; i < NIMG * TILE_U4; i += 96 * 256) {
            int s = i % TILE_U4;
            if (s >= ONES_LO) kvp[i] = (s < ONES_HI) ? ones4 : zero4;
            else if (s >= KIMG / 8 + 32 * (VROW / 8)) kvp[i] = zero4;
        }
    }

    const int lane = tid & 31;
    const int g    = lane >> 2;
    const int t4   = lane & 3;
    const int wid  = blockIdx.x * 8 + (tid >> 5);   // fragment id 0..127
    const int nt   = wid >> 3;
    const int ks   = wid & 7;

    const float* W; int ldw, c0;
    switch (blockIdx.y) {
        case 0:  W = inW;  ldw = 384; c0 = 0;   break;
        case 1:  W = inW;  ldw = 384; c0 = 128; break;
        case 2:  W = inW;  ldw = 384; c0 = 256; break;
        case 3:  W = outW; ldw = 128; c0 = 0;   break;
        case 4:  W = f1W;  ldw = 128; c0 = 0;   break;
        default: W = f2W;  ldw = 128; c0 = 0;   break;
    }

    const int n  = nt * 8 + g;
    const int k0 = ks * 16 + 2 * t4;
    float w00 = W[(k0    ) * ldw + c0 + n];
    float w01 = W[(k0 + 1) * ldw + c0 + n];
    float w80 = W[(k0 + 8) * ldw + c0 + n];
    float w81 = W[(k0 + 9) * ldw + c0 + n];
    __half h00, l00, h01, l01, h80, l80, h81, l81;
    hsplit(w00, h00, l00);  hsplit(w01, h01, l01);
    hsplit(w80, h80, l80);  hsplit(w81, h81, l81);
    uint4 f;
    f.x = packh2(h00, h01);
    f.y = packh2(h80, h81);
    f.z = packh2(l00, l01);
    f.w = packh2(l80, l81);
    g_wf[blockIdx.y * 4096 + wid * 32 + lane] = f;
}

// ============================================================================
// MMA GEMM: C[:, c0:c0+128] = act( X @ Wimg + bias ) (+ R)
// X = A (optionally LayerNormed) or the split-K attention combine (COMB).
// 2-term: Ah*Wh + Ah*Wl (A staged hi-only; W images carry hi+lo).
// KVOUT: blockIdx.y==1/2 write results as fp16 into the g_kv attention images.
// SUMOUT: skip store; accumulate masked column sums into g_xsum.
// grid = (128, MULTI?3:1), 256 threads (8 warps). 32 rows per block.
// ============================================================================
template <int ACT, int RESID, int LNORM, int MULTI, int COMB, int SUMOUT, int KVOUT>
__global__ void __launch_bounds__(256) k_gemm_mma(const float* __restrict__ A,
                                                  int img0,
                                                  const float* __restrict__ bias,
                                                  const float* __restrict__ R,
                                                  float* __restrict__ C,
                                                  int outStride,
                                                  const float* __restrict__ lng,
                                                  const float* __restrict__ lnb,
                                                  const int* __restrict__ snp) {
    __shared__ __align__(16) __half Ahi[32 * 136];
    __shared__ float colsum[128];
    const int tid = threadIdx.x;
    const int m0  = blockIdx.x * 32;
    const int c0  = MULTI ? blockIdx.y * 128 : 0;
    const int img = img0 + (MULTI ? blockIdx.y : 0);

    // ---- stage X tile (plain / LN / attention-combine), fp16 hi ----
    {
        const int r = tid >> 3, l8 = tid & 7;
        float x[16];
        if (COMB) {
            // split-K combine (fixed-ref softmax): head = l8>>1, dims (l8&1)*16..
            const int row    = m0 + r;
            const int head   = l8 >> 1;
            const int hd_off = (l8 & 1) * 16;
#pragma unroll
            for (int j = 0; j < 16; j++) x[j] = 0.0f;
            float L = 0.0f;
#pragma unroll
            for (int kc = 0; kc < NKC; kc++) {
                const int p = (head * NKC + kc) * S + row;
                L += g_pl[p];
                const float4* po = reinterpret_cast<const float4*>(&g_po[(size_t)p * HD + hd_off]);
#pragma unroll
                for (int jj = 0; jj < 4; jj++) {
                    float4 v = po[jj];
                    x[jj * 4 + 0] += v.x;
                    x[jj * 4 + 1] += v.y;
                    x[jj * 4 + 2] += v.z;
                    x[jj * 4 + 3] += v.w;
                }
            }
            float inv = (L > 0.0f) ? 1.0f / L : 0.0f;
#pragma unroll
            for (int j = 0; j < 16; j++) x[j] *= inv;
        } else {
            const float4* ap = reinterpret_cast<const float4*>(A + (m0 + r) * HID + l8 * 16);
#pragma unroll
            for (int j = 0; j < 4; j++) {
                float4 v = ap[j];
                x[j * 4 + 0] = v.x; x[j * 4 + 1] = v.y;
                x[j * 4 + 2] = v.z; x[j * 4 + 3] = v.w;
            }
        }
        if (LNORM) {
            float s = 0.0f, s2 = 0.0f;
#pragma unroll
            for (int j = 0; j < 16; j++) { s += x[j]; s2 += x[j] * x[j]; }
#pragma unroll
            for (int o = 4; o; o >>= 1) {
                s  += __shfl_xor_sync(0xffffffffu, s,  o);
                s2 += __shfl_xor_sync(0xffffffffu, s2, o);
            }
            float mean = s * (1.0f / HID);
            float rstd = rsqrtf(s2 * (1.0f / HID) - mean * mean + 1e-5f);
#pragma unroll
            for (int j = 0; j < 16; j++) {
                int col = l8 * 16 + j;
                x[j] = (x[j] - mean) * rstd * lng[col] + lnb[col];
            }
        }
        uint32_t phi[8];
#pragma unroll
        for (int j = 0; j < 8; j++)
            phi[j] = pack2f(x[2 * j], x[2 * j + 1]);
        uint4* dhi = reinterpret_cast<uint4*>(&Ahi[r * 136 + l8 * 16]);
        dhi[0] = make_uint4(phi[0], phi[1], phi[2], phi[3]);
        dhi[1] = make_uint4(phi[4], phi[5], phi[6], phi[7]);
    }
    if (SUMOUT && tid < 128) colsum[tid] = 0.0f;
    __syncthreads();

    // ---- main MMA loop (2-term) ----
    const int warp = tid >> 5, lane = tid & 31;
    const int g = lane >> 2, t4 = lane & 3;
    const int mt = warp & 1, ch = warp >> 1;
    const uint4* img_p = &g_wf[(size_t)img * 4096];

    float acc[4][4];
#pragma unroll
    for (int nt = 0; nt < 4; nt++)
#pragma unroll
        for (int i = 0; i < 4; i++) acc[nt][i] = 0.0f;

    const __half* ahb = &Ahi[(mt * 16 + g) * 136];

#pragma unroll
    for (int ks = 0; ks < 8; ks++) {
        const int co = ks * 16 + 2 * t4;
        uint32_t ah0 = *reinterpret_cast<const uint32_t*>(&ahb[co]);
        uint32_t ah1 = *reinterpret_cast<const uint32_t*>(&ahb[8 * 136 + co]);
        uint32_t ah2 = *reinterpret_cast<const uint32_t*>(&ahb[co + 8]);
        uint32_t ah3 = *reinterpret_cast<const uint32_t*>(&ahb[8 * 136 + co + 8]);
#pragma unroll
        for (int nt = 0; nt < 4; nt++) {
            uint4 f = img_p[((4 * ch + nt) * 8 + ks) * 32 + lane];
            mma16816(acc[nt][0], acc[nt][1], acc[nt][2], acc[nt][3],
                     ah0, ah1, ah2, ah3, f.x, f.y);
            mma16816(acc[nt][0], acc[nt][1], acc[nt][2], acc[nt][3],
                     ah0, ah1, ah2, ah3, f.z, f.w);
        }
    }

    // ---- epilogue ----
    const int sn = SUMOUT ? *snp : 0;
#pragma unroll
    for (int nt = 0; nt < 4; nt++) {
        const int ncol = c0 + (4 * ch + nt) * 8 + 2 * t4;
        const int row0 = m0 + mt * 16 + g, row1 = row0 + 8;
        float b0 = bias[ncol], b1 = bias[ncol + 1];
        float v00 = acc[nt][0] + b0, v01 = acc[nt][1] + b1;
        float v10 = acc[nt][2] + b0, v11 = acc[nt][3] + b1;
        if (ACT == 1) {
            const float k = 0.70710678118654752f;
            v00 = 0.5f * v00 * (1.0f + erff(v00 * k));
            v01 = 0.5f * v01 * (1.0f + erff(v01 * k));
            v10 = 0.5f * v10 * (1.0f + erff(v10 * k));
            v11 = 0.5f * v11 * (1.0f + erff(v11 * k));
        }
        if (RESID) {
            v00 += R[row0 * HID + ncol];  v01 += R[row0 * HID + ncol + 1];
            v10 += R[row1 * HID + ncol];  v11 += R[row1 * HID + ncol + 1];
        }
        if (SUMOUT) {
            float a0 = (row0 < sn ? v00 : 0.0f) + (row1 < sn ? v10 : 0.0f);
            float a1 = (row0 < sn ? v01 : 0.0f) + (row1 < sn ? v11 : 0.0f);
            atomicAdd(&colsum[ncol], a0);
            atomicAdd(&colsum[ncol + 1], a1);
        } else if (KVOUT && blockIdx.y > 0) {
            // K (y==1) / V (y==2) written as fp16 into the attention image
            const int lc   = ncol - c0;         // local col 0..127
            const int head = lc >> 5, d = lc & 31;
            const size_t base = (size_t)(head * (S / KT) + (row0 >> 6)) * TILE_H;
            const int key0 = row0 & 63, key1 = row1 & 63;
            if (blockIdx.y == 1) {
                *reinterpret_cast<__half2*>(&g_kv[base + key0 * KROW + d]) =
                    __floats2half2_rn(v00, v01);
                *reinterpret_cast<__half2*>(&g_kv[base + key1 * KROW + d]) =
                    __floats2half2_rn(v10, v11);
            } else {
                g_kv[base + KIMG + d * VROW + key0]       = __float2half_rn(v00);
                g_kv[base + KIMG + (d + 1) * VROW + key0] = __float2half_rn(v01);
                g_kv[base + KIMG + d * VROW + key1]       = __float2half_rn(v10);
                g_kv[base + KIMG + (d + 1) * VROW + key1] = __float2half_rn(v11);
            }
        } else {
            C[row0 * outStride + ncol]     = v00;
            C[row0 * outStride + ncol + 1] = v01;
            C[row1 * outStride + ncol]     = v10;
            C[row1 * outStride + ncol + 1] = v11;
        }
    }
    if (SUMOUT) {
        __syncthreads();
        if (tid < 128) atomicAdd(&g_xsum[tid], (double)colsum[tid]);
    }
}

// ============================================================================
// K1: sine encoding + GEMM  ->  g_eig = eeig[S,129] @ W[129,128] + b
// 16 rows per block, 256 threads (each thread: 8 rows of one column).
// ============================================================================
__global__ void __launch_bounds__(256) k_sine_enc(const float* __restrict__ eve,
                                                  const float* __restrict__ W,
                                                  const float* __restrict__ b) {
    __shared__ float ee[16][132];   // 129 used
    const int m0  = blockIdx.x * 16;
    const int tid = threadIdx.x;
    const float kLog = -9.210340371976184f / 128.0f;   // -ln(1e4)/128

    for (int idx = tid; idx < 16 * 64; idx += 256) {
        int r = idx >> 6, i = idx & 63;
        float e  = eve[m0 + r];
        float pe = e * 100.0f * __expf((2.0f * i) * kLog);
        float sv, cv;
        sincosf(pe, &sv, &cv);
        ee[r][1 + i]  = sv;
        ee[r][65 + i] = cv;
    }
    if (tid < 16) ee[tid][0] = eve[m0 + tid];
    __syncthreads();

    const int col  = tid & 127;
    const int half = tid >> 7;     // 0: rows 0-7, 1: rows 8-15
    float acc[8];
#pragma unroll
    for (int r = 0; r < 8; r++) acc[r] = 0.0f;

    for (int k = 0; k < 129; k++) {
        float wv = W[k * HID + col];
#pragma unroll
        for (int r = 0; r < 8; r++) acc[r] = fmaf(ee[half * 8 + r][k], wv, acc[r]);
    }
    float bb = b[col];
#pragma unroll
    for (int r = 0; r < 8; r++)
        g_eig[(m0 + half * 8 + r) * HID + col] = acc[r] + bb;
}

// ============================================================================
// K4a: MMA flash attention partial. Fixed-reference softmax (M == 0):
// P = exp2(score) directly (clamped at 2^14); reference cancels in O/l.
// Fragment loads via ldmatrix.x4. QK 1-term, PV 1-term fp16; l via ones-row.
// grid = (S/QT, NHEADS, NKC), block = 256 (8 warps x 16 queries).
// ============================================================================
__global__ void __launch_bounds__(256) k_attn_mma(const float* __restrict__ qkv,
                                                  const int* __restrict__ snp) {
    __shared__ __align__(16) __half tile[2][TILE_H];

    const int tid  = threadIdx.x;
    const int warp = tid >> 5;
    const int lane = tid & 31;
    const int g    = lane >> 2;    // group (row within fragment)
    const int t4   = lane & 3;     // thread-in-group
    const int h    = blockIdx.y;
    const int kc   = blockIdx.z;
    const int sn   = *snp;

    const int qbase = blockIdx.x * QT + warp * 16;
    const int r0 = qbase + g;        // query rows owned by this thread
    const int r1 = r0 + 8;

    const uint32_t sm0 = (uint32_t)__cvta_generic_to_shared(&tile[0][0]);
    const uint32_t sm1 = (uint32_t)__cvta_generic_to_shared(&tile[1][0]);

    // lane-invariant ldmatrix byte offsets (within a tile buffer)
    const uint32_t qk_lane = (uint32_t)(((lane & 7) * KROW + (lane >> 3) * 8) * 2);
    const uint32_t pv_lane = (uint32_t)((KIMG + (lane & 7) * VROW + (lane >> 3) * 8) * 2);

    // ---- load Q fragments (2 k-steps), fp16 hi only; log2e folded in ----
    uint32_t Q[2][4];
#pragma unroll
    for (int ks = 0; ks < 2; ks++) {
#pragma unroll
        for (int hh = 0; hh < 2; hh++) {     // k-half (+0 / +8)
#pragma unroll
            for (int rr = 0; rr < 2; rr++) { // row g / g+8
                int row = rr ? r1 : r0;
                int d0  = ks * 16 + hh * 8 + 2 * t4;
                float x0 = qkv[row * 384 + h * HD + d0]     * QSCALE;
                float x1 = qkv[row * 384 + h * HD + d0 + 1] * QSCALE;
                Q[ks][hh * 2 + rr] = pack2f(x0, x1);
            }
        }
    }

    float O[5][4];                    // [d-tile][frag]; nt=4 carries l (ones row)
#pragma unroll
    for (int nt = 0; nt < 5; nt++)
#pragma unroll
        for (int i = 0; i < 4; i++) O[nt][i] = 0.0f;

    const int tile0 = (kc * CHUNK) >> 6;    // first tile index in this chunk

    // prefetch tile 0 into buffer 0
    {
        const uint4* src = reinterpret_cast<const uint4*>(
            g_kv + (size_t)(h * (S / KT) + tile0) * TILE_H);
        for (int i = tid; i < TILE_U4; i += 256)
            cp16(sm0 + i * 16, src + i);
        cp_commit();
    }

    for (int it = 0; it < NT_CH; it++) {
        cp_wait_all();
        __syncthreads();

        // prefetch next tile into the other buffer (overlaps compute below)
        if (it + 1 < NT_CH) {
            const uint4* src = reinterpret_cast<const uint4*>(
                g_kv + (size_t)(h * (S / KT) + tile0 + it + 1) * TILE_H);
            uint32_t dstb = ((it + 1) & 1) ? sm1 : sm0;
            for (int i = tid; i < TILE_U4; i += 256)
                cp16(dstb + i * 16, src + i);
            cp_commit();
        }

        const uint32_t smb = (it & 1) ? sm1 : sm0;
        const int kb = kc * CHUNK + it * KT;

        // ---- QK^T: 8 n-tiles of 8 keys; ldmatrix.x4 per tile (2 k-steps) ----
        float Sf[8][4];
#pragma unroll
        for (int nt = 0; nt < 8; nt++) {
#pragma unroll
            for (int i = 0; i < 4; i++) Sf[nt][i] = 0.0f;
            uint32_t b0, b1, b2, b3;
            ldm_x4(b0, b1, b2, b3, smb + qk_lane + nt * (8 * KROW * 2));
            mma16816(Sf[nt][0], Sf[nt][1], Sf[nt][2], Sf[nt][3],
                     Q[0][0], Q[0][1], Q[0][2], Q[0][3], b0, b1);
            mma16816(Sf[nt][0], Sf[nt][1], Sf[nt][2], Sf[nt][3],
                     Q[1][0], Q[1][1], Q[1][2], Q[1][3], b2, b3);
        }

        // ---- mask (only the boundary tile pays) ----
        if (kb + KT > sn) {
#pragma unroll
            for (int nt = 0; nt < 8; nt++) {
                int k0 = kb + nt * 8 + 2 * t4;
                if (k0     >= sn) { Sf[nt][0] = -INFINITY; Sf[nt][2] = -INFINITY; }
                if (k0 + 1 >= sn) { Sf[nt][1] = -INFINITY; Sf[nt][3] = -INFINITY; }
            }
        }

        // ---- P = exp2(score), fixed reference (no max, no rescale) ----
        uint32_t Ph[4][4];
#pragma unroll
        for (int j = 0; j < 4; j++) {       // key-step j covers tiles 2j, 2j+1
#pragma unroll
            for (int tt = 0; tt < 2; tt++) {
                int nt = 2 * j + tt;
                Ph[j][tt * 2]     = exp2h2c(Sf[nt][0], Sf[nt][1]);
                Ph[j][tt * 2 + 1] = exp2h2c(Sf[nt][2], Sf[nt][3]);
            }
        }

        // ---- PV: 5 d-tiles (incl. ones row) x 4 key-steps via ldmatrix ----
#pragma unroll
        for (int nt = 0; nt < 5; nt++) {
            const uint32_t abase = smb + pv_lane + nt * (8 * VROW * 2);
#pragma unroll
            for (int p = 0; p < 2; p++) {   // key-step pair
                uint32_t b0, b1, b2, b3;
                ldm_x4(b0, b1, b2, b3, abase + p * 64);
                mma16816(O[nt][0], O[nt][1], O[nt][2], O[nt][3],
                         Ph[2 * p][0], Ph[2 * p][1], Ph[2 * p][2], Ph[2 * p][3], b0, b1);
                mma16816(O[nt][0], O[nt][1], O[nt][2], O[nt][3],
                         Ph[2 * p + 1][0], Ph[2 * p + 1][1], Ph[2 * p + 1][2], Ph[2 * p + 1][3], b2, b3);
            }
        }
        __syncthreads();
    }

    // ---- write partials (unnormalized); l lives in O[4] at col 32 (t4==0) ----
    const int p0 = (h * NKC + kc) * S + r0;
    const int p1 = (h * NKC + kc) * S + r1;
    if (t4 == 0) {
        g_pl[p0] = O[4][0];
        g_pl[p1] = O[4][2];
    }
#pragma unroll
    for (int nt = 0; nt < 4; nt++) {
        int d = nt * 8 + 2 * t4;
        g_po[(size_t)p0 * HD + d]     = O[nt][0];
        g_po[(size_t)p0 * HD + d + 1] = O[nt][1];
        g_po[(size_t)p1 * HD + d]     = O[nt][2];
        g_po[(size_t)p1 * HD + d + 1] = O[nt][3];
    }
}

// ============================================================================
// pooled coefficients (single block)
// ============================================================================
__global__ void __launch_bounds__(128) k_pool(const float* __restrict__ dscW, const float* __restrict__ dscb,
                                              const float* __restrict__ dwvW, const float* __restrict__ dwvb,
                                              const float* __restrict__ dssW, const float* __restrict__ dssb,
                                              const int* __restrict__ lenp, const int* __restrict__ snp) {
    const int tid = threadIdx.x;
    __shared__ float sig[104];
    __shared__ float ssum[2];
    const float lenf = (float)(*lenp);
    const float snf  = (float)(*snp);

    if (tid < 104) {
        const float* W; const float* bb; int c; int NCc;
        if (tid < 50)       { W = dscW; bb = dscb; c = tid;       NCc = NCOE; }
        else if (tid < 100) { W = dwvW; bb = dwvb; c = tid - 50;  NCc = NCOE; }
        else                { W = dssW; bb = dssb; c = tid - 100; NCc = NSCALES; }
        double acc = 0.0;
        for (int k = 0; k < HID; k++) acc += g_xsum[k] * (double)W[k * NCc + c];
        float pooled = (float)((acc + (double)(snf * bb[c])) / (double)(lenf + 1e-8f));
        sig[tid] = 1.0f / (1.0f + expf(-pooled));
    }
    __syncthreads();
    if (tid == 0) { float t = 0.f; for (int i = 0;  i < 50;  i++) t += sig[i]; ssum[0] = t; }
    if (tid == 1) { float t = 0.f; for (int i = 50; i < 100; i++) t += sig[i]; ssum[1] = t; }
    __syncthreads();
    if (tid < 50)       g_coef[tid] = sig[tid] / (ssum[0] + 1e-8f);
    else if (tid < 100) g_coef[tid] = sig[tid] / (ssum[1] + 1e-8f);
    else if (tid < 104) g_coef[tid] = sig[tid] * 5.0f;   // THRE
}

// ============================================================================
// Chebyshev synthesis + L2 normalize  ->  out[S, 5]
// ============================================================================
__global__ void __launch_bounds__(128) k_final(const float* __restrict__ eve,
                                               float* __restrict__ out) {
    __shared__ float cs[NCOE], cw[NCOE], sc[NSCALES];
    const int tid = threadIdx.x;
    if (tid < 50)        cs[tid]       = g_coef[tid];
    else if (tid < 100)  cw[tid - 50]  = g_coef[tid];
    else if (tid < 104)  sc[tid - 100] = g_coef[tid];
    __syncthreads();

    const int s = blockIdx.x * 128 + tid;
    const float e = eve[s];
    float vals[5];

    {   // scaling channel: y = e - 1; coefficients on T_1,T_3,...
        float y  = e - 1.0f;
        float te = 1.0f, to = y;
        float acc = cs[0] * (0.5f * (1.0f - to));
#pragma unroll
        for (int c = 1; c < NCOE; c++) {
            te = 2.0f * y * to - te;          // T_{2c}
            to = 2.0f * y * te - to;          // T_{2c+1}
            acc += cs[c] * (0.5f * (1.0f - to));
        }
        vals[0] = acc;
    }

#pragma unroll
    for (int j = 0; j < NSCALES; j++) {       // wavelet channels: T_0,T_2,...
        float f = e * sc[j];
        if (f > 2.0f) f = 0.0f;
        float y  = f - 1.0f;
        float te = 1.0f, to = y;
        float acc = 0.0f;                      // cw[0] * 0.5*(1-T_0) = 0
#pragma unroll
        for (int c = 1; c < NCOE; c++) {
            te = 2.0f * y * to - te;          // T_{2c}
            acc += cw[c] * (0.5f * (1.0f - te));
            to = 2.0f * y * te - to;          // T_{2c+1}
        }
        vals[1 + j] = acc;
    }

    float n2 = 0.0f;
#pragma unroll
    for (int i = 0; i < 5; i++) n2 += vals[i] * vals[i];
    float inv = 1.0f / (sqrtf(n2) + 1e-8f);
#pragma unroll
    for (int i = 0; i < 5; i++) out[s * 5 + i] = vals[i] * inv;
}

// ============================================================================
// launch
// ============================================================================
extern "C" void kernel_launch(void* const* d_in, const int* in_sizes, int n_in,
                              void* d_out, int out_size) {
    const float* eve      = (const float*)d_in[0];
    const int*   lenp     = (const int*)  d_in[1];
    const int*   snp      = (const int*)  d_in[2];
    const float* eig_w_W  = (const float*)d_in[3];
    const float* eig_w_b  = (const float*)d_in[4];
    const float* mha_ln_g = (const float*)d_in[5];
    const float* mha_ln_b = (const float*)d_in[6];
    const float* in_W     = (const float*)d_in[7];
    const float* in_b     = (const float*)d_in[8];
    const float* out_W    = (const float*)d_in[9];
    const float* out_b    = (const float*)d_in[10];
    const float* ffn_ln_g = (const float*)d_in[11];
    const float* ffn_ln_b = (const float*)d_in[12];
    const float* ffn1_W   = (const float*)d_in[13];
    const float* ffn1_b   = (const float*)d_in[14];
    const float* ffn2_W   = (const float*)d_in[15];
    const float* ffn2_b   = (const float*)d_in[16];
    const float* dsc_W    = (const float*)d_in[17];
    const float* dsc_b    = (const float*)d_in[18];
    const float* dwv_W    = (const float*)d_in[19];
    const float* dwv_b    = (const float*)d_in[20];
    const float* dss_W    = (const float*)d_in[21];
    const float* dss_b    = (const float*)d_in[22];
    float* out = (float*)d_out;

    float *p_eig, *p_qkv, *p_h1;
    cudaGetSymbolAddress((void**)&p_eig,  g_eig);
    cudaGetSymbolAddress((void**)&p_qkv,  g_qkv);
    cudaGetSymbolAddress((void**)&p_h1,   g_h1);

    // 0) weight images + zero xsum + static g_kv content (ones rows, pads)
    k_wprep<<<dim3(16, 6), 256>>>(in_W, out_W, ffn1_W, ffn2_W);
    // 1) eig = sine_encoding(eve) @ W + b
    k_sine_enc<<<S / 16, 256>>>(eve, eig_w_W, eig_w_b);
    // 2) qkv: Q -> float g_qkv; K/V -> fp16 g_kv images directly (KVOUT)
    k_gemm_mma<0, 0, 1, 1, 0, 0, 1><<<dim3(128, 3), 256>>>(p_eig, 0, in_b, nullptr, p_qkv, 384, mha_ln_g, mha_ln_b, nullptr);
    // 3) attention split-K partials (combine fused into step 4)
    k_attn_mma<<<dim3(S / QT, NHEADS, NKC), 256>>>(p_qkv, snp);
    // 4) eig = eig + combine(partials) @ out_W + out_b   (COMB staging)
    k_gemm_mma<0, 1, 0, 0, 1, 0, 0><<<dim3(128), 256>>>(nullptr, 3, out_b, p_eig, p_eig, 128, nullptr, nullptr, nullptr);
    // 5) h1 = gelu(LN(eig) @ ffn1_W + b)
    k_gemm_mma<1, 0, 1, 0, 0, 0, 0><<<dim3(128), 256>>>(p_eig, 4, ffn1_b, nullptr, p_h1, 128, ffn_ln_g, ffn_ln_b, nullptr);
    // 6) eigf column-sums = sum_rows<sn (eig + h1 @ ffn2_W + b)  (no store)
    k_gemm_mma<0, 1, 0, 0, 0, 1, 0><<<dim3(128), 256>>>(p_h1, 5, ffn2_b, p_eig, nullptr, 128, nullptr, nullptr, snp);
    // 7) pooled coefficients
    k_pool<<<1, 128>>>(dsc_W, dsc_b, dwv_W, dwv_b, dss_W, dss_b, lenp, snp);
    // 8) Chebyshev synthesis + normalize
    k_final<<<S / 128, 128>>>(eve, out);
}